// round 4
// baseline (speedup 1.0000x reference)
#include <cuda_runtime.h>
#include <cuda_bf16.h>
#include <math.h>

#define Bv 4
#define Lv 1024
#define Dv 1024
#define Hv 16
#define HDv 64
#define Fv 2816
#define Av 64
#define Pv 30
#define KTOT (Pv + Lv)          /* 1054 keys incl. prefix */
#define NKT 17                  /* ceil(1054/64) key tiles */

// ---------------- scratch (static device globals; no allocations) ----------
__device__ float g_xn[Bv*Lv*Dv];
__device__ float g_q [Bv*Lv*Dv];
__device__ float g_k [Bv*Lv*Dv];
__device__ float g_v [Bv*Lv*Dv];
__device__ float g_att[Bv*Lv*Dv];
__device__ float g_x [Bv*Lv*Dv];
__device__ float g_y [Bv*Lv*Dv];
__device__ float g_h0[Bv*Lv*Fv];
__device__ float g_h1[Bv*Lv*Fv];
__device__ float g_az[Bv*Lv*Av];

__device__ __forceinline__ float gelu_f(float x) {
    float x3 = x * x * x;
    return 0.5f * x * (1.0f + tanhf(0.7978845608028654f * (x + 0.044715f * x3)));
}

// pack two floats into hi/lo bf16x2 words (bf16x3 split scheme)
__device__ __forceinline__ void split2(float f0, float f1, unsigned &hi, unsigned &lo) {
    __nv_bfloat162 h = __floats2bfloat162_rn(f0, f1);
    float r0 = f0 - __bfloat162float(h.x);
    float r1 = f1 - __bfloat162float(h.y);
    __nv_bfloat162 l = __floats2bfloat162_rn(r0, r1);
    hi = *reinterpret_cast<unsigned*>(&h);
    lo = *reinterpret_cast<unsigned*>(&l);
}

__device__ __forceinline__ void mma16816(float* c, const unsigned* a, const unsigned* b) {
    asm volatile(
        "mma.sync.aligned.m16n8k16.row.col.f32.bf16.bf16.f32 "
        "{%0,%1,%2,%3}, {%4,%5,%6,%7}, {%8,%9}, {%0,%1,%2,%3};\n"
        : "+f"(c[0]), "+f"(c[1]), "+f"(c[2]), "+f"(c[3])
        : "r"(a[0]), "r"(a[1]), "r"(a[2]), "r"(a[3]), "r"(b[0]), "r"(b[1]));
}

// ---------------- RMSNorm ---------------------------------------------------
__global__ __launch_bounds__(256) void rmsnorm_kernel(
    const float* __restrict__ x, const float* __restrict__ w, float* __restrict__ o)
{
    int row = blockIdx.x;
    const float* xr = x + (size_t)row * Dv;
    float* orow = o + (size_t)row * Dv;
    int tid = threadIdx.x;
    int d0 = tid * 4;
    float4 v = *(const float4*)&xr[d0];
    float s = v.x*v.x + v.y*v.y + v.z*v.z + v.w*v.w;
    #pragma unroll
    for (int off = 16; off; off >>= 1) s += __shfl_xor_sync(0xffffffffu, s, off);
    __shared__ float red[8];
    __shared__ float inv_s;
    if ((tid & 31) == 0) red[tid >> 5] = s;
    __syncthreads();
    if (tid == 0) {
        float t = 0.f;
        #pragma unroll
        for (int i = 0; i < 8; i++) t += red[i];
        inv_s = rsqrtf(t * (1.0f / Dv) + 1e-6f);
    }
    __syncthreads();
    float inv = inv_s;
    float4 wv = *(const float4*)&w[d0];
    float4 r;
    r.x = v.x*inv*wv.x; r.y = v.y*inv*wv.y; r.z = v.z*inv*wv.z; r.w = v.w*inv*wv.w;
    *(float4*)&orow[d0] = r;
}

// ---------------- bf16x3 tensor-core GEMM 128x128x32, double-buffered -------
// dynamic smem: 2 buffers x 4 arrays x [128][40] bf16 = 81920 bytes
#define TG_SEG  (128 * 40)
#define TG_BUF  (4 * TG_SEG)
#define TG_SMEM (2 * TG_BUF * (int)sizeof(__nv_bfloat16))

__global__ __launch_bounds__(256, 2) void tgemm_kernel(
    const float* __restrict__ A, const float* __restrict__ B, float* __restrict__ C,
    int M, int N, int K, float alpha,
    const float* __restrict__ res, const float* __restrict__ gate)
{
    extern __shared__ __align__(16) __nv_bfloat16 tgsm[];

    int tid  = threadIdx.x;
    int m0   = blockIdx.y * 128;
    int n0   = blockIdx.x * 128;
    int wid  = tid >> 5, lane = tid & 31;
    int g    = lane >> 2, tig = lane & 3;
    int wm   = (wid & 1) * 64;
    int wn   = (wid >> 1) * 32;

    float acc[4][4][4];
    #pragma unroll
    for (int i = 0; i < 4; i++)
        #pragma unroll
        for (int j = 0; j < 4; j++)
            #pragma unroll
            for (int r = 0; r < 4; r++) acc[i][j][r] = 0.f;

    // loader coords
    int arow[4], acol[4];
    #pragma unroll
    for (int i = 0; i < 4; i++) {
        int v = tid + i * 256;
        arow[i] = v >> 3;
        acol[i] = (v & 7) * 4;
    }
    int bn  = tid & 127;
    int bkg = tid >> 7;

    float4 areg[4];
    float  breg[16];

    // ---- prologue: load + store tile 0 ----
    #pragma unroll
    for (int i = 0; i < 4; i++)
        areg[i] = *(const float4*)&A[(size_t)(m0 + arow[i]) * K + acol[i]];
    {
        const float* bp = &B[(size_t)(bkg * 16) * N + n0 + bn];
        #pragma unroll
        for (int j = 0; j < 16; j++) breg[j] = bp[(size_t)j * N];
    }
    {
        __nv_bfloat16* Ahi = tgsm;
        __nv_bfloat16* Alo = Ahi + TG_SEG;
        __nv_bfloat16* Bhi = Alo + TG_SEG;
        __nv_bfloat16* Blo = Bhi + TG_SEG;
        #pragma unroll
        for (int i = 0; i < 4; i++) {
            unsigned h0, l0, h1, l1;
            split2(areg[i].x, areg[i].y, h0, l0);
            split2(areg[i].z, areg[i].w, h1, l1);
            *(uint2*)&Ahi[arow[i] * 40 + acol[i]] = make_uint2(h0, h1);
            *(uint2*)&Alo[arow[i] * 40 + acol[i]] = make_uint2(l0, l1);
        }
        unsigned hp[8], lp[8];
        #pragma unroll
        for (int j = 0; j < 8; j++) split2(breg[2*j], breg[2*j+1], hp[j], lp[j]);
        *(uint4*)&Bhi[bn * 40 + bkg * 16]     = make_uint4(hp[0], hp[1], hp[2], hp[3]);
        *(uint4*)&Bhi[bn * 40 + bkg * 16 + 8] = make_uint4(hp[4], hp[5], hp[6], hp[7]);
        *(uint4*)&Blo[bn * 40 + bkg * 16]     = make_uint4(lp[0], lp[1], lp[2], lp[3]);
        *(uint4*)&Blo[bn * 40 + bkg * 16 + 8] = make_uint4(lp[4], lp[5], lp[6], lp[7]);
    }
    __syncthreads();

    int nk = K >> 5;
    for (int t = 0; t < nk; t++) {
        // ---- prefetch tile t+1 into registers (latency hidden under MMAs) ----
        if (t + 1 < nk) {
            int k0 = (t + 1) << 5;
            #pragma unroll
            for (int i = 0; i < 4; i++)
                areg[i] = *(const float4*)&A[(size_t)(m0 + arow[i]) * K + k0 + acol[i]];
            const float* bp = &B[(size_t)(k0 + bkg * 16) * N + n0 + bn];
            #pragma unroll
            for (int j = 0; j < 16; j++) breg[j] = bp[(size_t)j * N];
        }

        // ---- compute on buffer t&1 ----
        {
            const __nv_bfloat16* Ahi = tgsm + (t & 1) * TG_BUF;
            const __nv_bfloat16* Alo = Ahi + TG_SEG;
            const __nv_bfloat16* Bhi = Alo + TG_SEG;
            const __nv_bfloat16* Blo = Bhi + TG_SEG;
            #pragma unroll
            for (int ks = 0; ks < 2; ks++) {
                int kb = ks * 16;
                unsigned bh[4][2], bl[4][2];
                #pragma unroll
                for (int nt = 0; nt < 4; nt++) {
                    int n = wn + nt * 8 + g;
                    bh[nt][0] = *(const unsigned*)&Bhi[n * 40 + kb + 2 * tig];
                    bh[nt][1] = *(const unsigned*)&Bhi[n * 40 + kb + 2 * tig + 8];
                    bl[nt][0] = *(const unsigned*)&Blo[n * 40 + kb + 2 * tig];
                    bl[nt][1] = *(const unsigned*)&Blo[n * 40 + kb + 2 * tig + 8];
                }
                #pragma unroll
                for (int mt = 0; mt < 4; mt++) {
                    int r = wm + mt * 16 + g;
                    unsigned ah[4], al[4];
                    ah[0] = *(const unsigned*)&Ahi[r * 40 + kb + 2 * tig];
                    ah[1] = *(const unsigned*)&Ahi[(r + 8) * 40 + kb + 2 * tig];
                    ah[2] = *(const unsigned*)&Ahi[r * 40 + kb + 2 * tig + 8];
                    ah[3] = *(const unsigned*)&Ahi[(r + 8) * 40 + kb + 2 * tig + 8];
                    al[0] = *(const unsigned*)&Alo[r * 40 + kb + 2 * tig];
                    al[1] = *(const unsigned*)&Alo[(r + 8) * 40 + kb + 2 * tig];
                    al[2] = *(const unsigned*)&Alo[r * 40 + kb + 2 * tig + 8];
                    al[3] = *(const unsigned*)&Alo[(r + 8) * 40 + kb + 2 * tig + 8];
                    #pragma unroll
                    for (int nt = 0; nt < 4; nt++) {
                        mma16816(acc[mt][nt], ah, bh[nt]);
                        mma16816(acc[mt][nt], ah, bl[nt]);
                        mma16816(acc[mt][nt], al, bh[nt]);
                    }
                }
            }
        }

        // ---- split + store tile t+1 into the other buffer ----
        if (t + 1 < nk) {
            __nv_bfloat16* Ahi = tgsm + ((t + 1) & 1) * TG_BUF;
            __nv_bfloat16* Alo = Ahi + TG_SEG;
            __nv_bfloat16* Bhi = Alo + TG_SEG;
            __nv_bfloat16* Blo = Bhi + TG_SEG;
            #pragma unroll
            for (int i = 0; i < 4; i++) {
                unsigned h0, l0, h1, l1;
                split2(areg[i].x, areg[i].y, h0, l0);
                split2(areg[i].z, areg[i].w, h1, l1);
                *(uint2*)&Ahi[arow[i] * 40 + acol[i]] = make_uint2(h0, h1);
                *(uint2*)&Alo[arow[i] * 40 + acol[i]] = make_uint2(l0, l1);
            }
            unsigned hp[8], lp[8];
            #pragma unroll
            for (int j = 0; j < 8; j++) split2(breg[2*j], breg[2*j+1], hp[j], lp[j]);
            *(uint4*)&Bhi[bn * 40 + bkg * 16]     = make_uint4(hp[0], hp[1], hp[2], hp[3]);
            *(uint4*)&Bhi[bn * 40 + bkg * 16 + 8] = make_uint4(hp[4], hp[5], hp[6], hp[7]);
            *(uint4*)&Blo[bn * 40 + bkg * 16]     = make_uint4(lp[0], lp[1], lp[2], lp[3]);
            *(uint4*)&Blo[bn * 40 + bkg * 16 + 8] = make_uint4(lp[4], lp[5], lp[6], lp[7]);
        }
        __syncthreads();
    }

    // ---- epilogue ----
    #pragma unroll
    for (int mt = 0; mt < 4; mt++) {
        #pragma unroll
        for (int half = 0; half < 2; half++) {
            int m = m0 + wm + mt * 16 + g + half * 8;
            #pragma unroll
            for (int nt = 0; nt < 4; nt++) {
                int n = n0 + wn + nt * 8 + 2 * tig;
                size_t idx = (size_t)m * N + n;
                float v0 = acc[mt][nt][half * 2 + 0] * alpha;
                float v1 = acc[mt][nt][half * 2 + 1] * alpha;
                if (res) {
                    float2 rv = *(const float2*)&res[idx];
                    v0 += rv.x; v1 += rv.y;
                }
                if (gate) {
                    float2 gv = *(const float2*)&gate[idx];
                    v0 *= gelu_f(gv.x); v1 *= gelu_f(gv.y);
                }
                float2 o; o.x = v0; o.y = v1;
                *(float2*)&C[idx] = o;
            }
        }
    }
}

// ---------------- Flash attention (online softmax, prefix KV) ---------------
#define FATTN_SMEM ((32*64 + 32*68 + 64*68 + 64*68 + 4*32) * 4)

__global__ __launch_bounds__(256, 3) void fattn_kernel(
    const float* __restrict__ qb, const float* __restrict__ kb, const float* __restrict__ vb,
    const float* __restrict__ pkb, const float* __restrict__ pvb,
    const float* __restrict__ relpos, float* __restrict__ ob,
    int sel, int causal)
{
    extern __shared__ float sm[];
    float* Qs     = sm;                    // [32][64]
    float* S      = Qs + 32 * 64;          // [32][68]
    float* Ks     = S + 32 * 68;           // [64][68]
    float* Vs     = Ks + 64 * 68;          // [64][68]
    float* relrow = Vs + 64 * 68;          // [32]
    float* rowm   = relrow + 32;           // [32]
    float* rowl   = rowm + 32;             // [32]
    float* corr   = rowl + 32;             // [32]

    int tid = threadIdx.x;
    int bh = blockIdx.y;
    int b = bh >> 4, h = bh & 15;
    int q0 = blockIdx.x * 32;

    {
        int r  = tid >> 3;
        int c0 = (tid & 7) * 8;
        const float* src = qb + ((size_t)(b * Lv + q0 + r) * Hv + h) * HDv + c0;
        *(float4*)&Qs[r * 64 + c0]     = *(const float4*)src;
        *(float4*)&Qs[r * 64 + c0 + 4] = *(const float4*)(src + 4);
    }
    if (tid < 32) {
        if (causal) relrow[tid] = relpos[h * 32 + tid];
        rowm[tid] = -1e30f;
        rowl[tid] = 0.f;
    }
    __syncthreads();

    int qrb = tid >> 6;
    int kk  = tid & 63;

    float oacc[8];
    #pragma unroll
    for (int i = 0; i < 8; i++) oacc[i] = 0.f;

    int ntile = causal ? (Pv + q0 + 32 + 63) >> 6 : NKT;

    for (int t = 0; t < ntile; t++) {
        {
            int r = tid >> 2;
            int g = t * 64 + r;
            bool valid = g < KTOT;
            const float *ks, *vs;
            if (g < Pv) {
                size_t off = (((size_t)(b * 2 + sel) * Pv + g) * Hv + h) * HDv;
                ks = pkb + off; vs = pvb + off;
            } else {
                size_t off = ((size_t)(b * Lv + (g - Pv)) * Hv + h) * HDv;
                ks = kb + off; vs = vb + off;
            }
            int c = (tid & 3) * 4;
            #pragma unroll
            for (int p = 0; p < 4; p++) {
                int cc = c + p * 16;
                float4 kv = valid ? *(const float4*)(ks + cc) : make_float4(0.f,0.f,0.f,0.f);
                float4 vv = valid ? *(const float4*)(vs + cc) : make_float4(0.f,0.f,0.f,0.f);
                *(float4*)&Ks[r * 68 + cc] = kv;
                *(float4*)&Vs[r * 68 + cc] = vv;
            }
        }
        __syncthreads();

        float sc[8];
        #pragma unroll
        for (int i = 0; i < 8; i++) sc[i] = 0.f;
        #pragma unroll
        for (int db = 0; db < 64; db += 16) {
            float kr[16];
            #pragma unroll
            for (int u = 0; u < 16; u += 4) {
                float4 v = *(const float4*)&Ks[kk * 68 + db + u];
                kr[u] = v.x; kr[u+1] = v.y; kr[u+2] = v.z; kr[u+3] = v.w;
            }
            #pragma unroll
            for (int i = 0; i < 8; i++) {
                const float* qp = &Qs[(qrb + i * 4) * 64 + db];
                #pragma unroll
                for (int u = 0; u < 16; u += 4) {
                    float4 v = *(const float4*)(qp + u);
                    sc[i] += v.x * kr[u] + v.y * kr[u+1] + v.z * kr[u+2] + v.w * kr[u+3];
                }
            }
        }
        {
            int g = t * 64 + kk;
            #pragma unroll
            for (int i = 0; i < 8; i++) {
                int q = qrb + i * 4;
                float val = sc[i];
                if (g >= KTOT) {
                    val = -1e10f;
                } else if (causal && g >= Pv) {
                    int kp = g - Pv;
                    int qp = q0 + q;
                    if (kp > qp) val = -1e10f;
                    else {
                        int rel = qp - kp;
                        int bkt;
                        if (rel < 16) bkt = rel;
                        else {
                            bkt = 16 + (int)(logf((float)rel * 0.0625f) *
                                             (16.0f / 2.0794415416798357f));
                            if (bkt > 31) bkt = 31;
                        }
                        val += relrow[bkt];
                    }
                }
                S[q * 68 + kk] = val;
            }
        }
        __syncthreads();

        {
            int wid = tid >> 5, lane = tid & 31;
            #pragma unroll
            for (int qi = 0; qi < 4; qi++) {
                int q = wid * 4 + qi;
                float* row = &S[q * 68];
                float v0 = row[lane], v1 = row[lane + 32];
                float tm = fmaxf(v0, v1);
                #pragma unroll
                for (int o = 16; o; o >>= 1) tm = fmaxf(tm, __shfl_xor_sync(0xffffffffu, tm, o));
                float mold = rowm[q];
                float mnew = fmaxf(mold, tm);
                float e0 = __expf(v0 - mnew), e1 = __expf(v1 - mnew);
                row[lane] = e0; row[lane + 32] = e1;
                float s = e0 + e1;
                #pragma unroll
                for (int o = 16; o; o >>= 1) s += __shfl_xor_sync(0xffffffffu, s, o);
                if (lane == 0) {
                    float c = __expf(mold - mnew);
                    rowm[q] = mnew;
                    rowl[q] = rowl[q] * c + s;
                    corr[q] = c;
                }
            }
        }
        __syncthreads();

        int d = kk;
        #pragma unroll
        for (int i = 0; i < 8; i++) oacc[i] *= corr[qrb + i * 4];
        #pragma unroll 4
        for (int k2 = 0; k2 < 64; k2++) {
            float vv = Vs[k2 * 68 + d];
            #pragma unroll
            for (int i = 0; i < 8; i++)
                oacc[i] += S[(qrb + i * 4) * 68 + k2] * vv;
        }
        __syncthreads();
    }

    #pragma unroll
    for (int i = 0; i < 8; i++) {
        int q = qrb + i * 4;
        float inv = 1.0f / rowl[q];
        ob[((size_t)(b * Lv + q0 + q) * Hv + h) * HDv + kk] = oacc[i] * inv;
    }
}

// ---------------- per-example adapter ---------------------------------------
__global__ __launch_bounds__(64) void adapter_down(
    const float* __restrict__ lz, const float* __restrict__ wd,
    const float* __restrict__ bd, float* __restrict__ az)
{
    int b = blockIdx.y, l = blockIdx.x, a = threadIdx.x;
    const float* xr = lz + (size_t)(b * Lv + l) * Dv;
    const float* wb = wd + (size_t)b * Dv * Av;
    float s = 0.f;
    #pragma unroll 4
    for (int dd = 0; dd < Dv; dd++) s += xr[dd] * wb[dd * Av + a];
    s += bd[b * Av + a];
    az[(size_t)(b * Lv + l) * Av + a] = gelu_f(s);
}

__global__ __launch_bounds__(256) void adapter_up(
    const float* __restrict__ az, const float* __restrict__ wu,
    const float* __restrict__ bu, float* __restrict__ out)
{
    int b = blockIdx.y, l = blockIdx.x;
    __shared__ float ash[Av];
    int tid = threadIdx.x;
    if (tid < Av) ash[tid] = az[(size_t)(b * Lv + l) * Av + tid];
    __syncthreads();
    const float* wb = wu + (size_t)b * Av * Dv;
    size_t o = (size_t)(b * Lv + l) * Dv;
    for (int dd = tid; dd < Dv; dd += 256) {
        float s = bu[b * Dv + dd];
        #pragma unroll 8
        for (int a = 0; a < Av; a++) s += ash[a] * wb[a * Dv + dd];
        out[o + dd] += s;
    }
}

// ---------------- driver -----------------------------------------------------
extern "C" void kernel_launch(void* const* d_in, const int* in_sizes, int n_in,
                              void* d_out, int out_size)
{
    const float* inputs  = (const float*)d_in[0];
    const float* encoded = (const float*)d_in[1];
    const float* awd     = (const float*)d_in[2];
    const float* awu     = (const float*)d_in[3];
    const float* abd     = (const float*)d_in[4];
    const float* abu     = (const float*)d_in[5];
    const float* pk      = (const float*)d_in[6];
    const float* pvv     = (const float*)d_in[7];
    const float* ln1     = (const float*)d_in[8];
    const float* ln2     = (const float*)d_in[9];
    const float* ln3     = (const float*)d_in[10];
    const float* sa_wq   = (const float*)d_in[11];
    const float* sa_wk   = (const float*)d_in[12];
    const float* sa_wv   = (const float*)d_in[13];
    const float* sa_wo   = (const float*)d_in[14];
    const float* ca_wq   = (const float*)d_in[15];
    const float* ca_wk   = (const float*)d_in[16];
    const float* ca_wv   = (const float*)d_in[17];
    const float* ca_wo   = (const float*)d_in[18];
    const float* relpos  = (const float*)d_in[19];
    const float* wi0     = (const float*)d_in[20];
    const float* wi1     = (const float*)d_in[21];
    const float* wo_mlp  = (const float*)d_in[22];
    float* out = (float*)d_out;

    float *xn, *q, *k, *v, *att, *x, *y, *h0, *h1, *az;
    cudaGetSymbolAddress((void**)&xn,  g_xn);
    cudaGetSymbolAddress((void**)&q,   g_q);
    cudaGetSymbolAddress((void**)&k,   g_k);
    cudaGetSymbolAddress((void**)&v,   g_v);
    cudaGetSymbolAddress((void**)&att, g_att);
    cudaGetSymbolAddress((void**)&x,   g_x);
    cudaGetSymbolAddress((void**)&y,   g_y);
    cudaGetSymbolAddress((void**)&h0,  g_h0);
    cudaGetSymbolAddress((void**)&h1,  g_h1);
    cudaGetSymbolAddress((void**)&az,  g_az);

    cudaFuncSetAttribute(fattn_kernel, cudaFuncAttributeMaxDynamicSharedMemorySize, FATTN_SMEM);
    cudaFuncSetAttribute(tgemm_kernel, cudaFuncAttributeMaxDynamicSharedMemorySize, TG_SMEM);

    const int M = Bv * Lv;              // 4096
    dim3 g8(8, 32), g22(22, 32);
    dim3 ga(32, Bv * Hv);
    const float qs = 0.125f;            // HD^-0.5

    // self-attention block
    rmsnorm_kernel<<<M, 256>>>(inputs, ln1, xn);
    tgemm_kernel<<<g8, 256, TG_SMEM>>>(xn, sa_wq, q, M, 1024, 1024, qs,  nullptr, nullptr);
    tgemm_kernel<<<g8, 256, TG_SMEM>>>(xn, sa_wk, k, M, 1024, 1024, 1.f, nullptr, nullptr);
    tgemm_kernel<<<g8, 256, TG_SMEM>>>(xn, sa_wv, v, M, 1024, 1024, 1.f, nullptr, nullptr);
    fattn_kernel<<<ga, 256, FATTN_SMEM>>>(q, k, v, pk, pvv, relpos, att, 0, 1);
    tgemm_kernel<<<g8, 256, TG_SMEM>>>(att, sa_wo, x, M, 1024, 1024, 1.f, inputs, nullptr);

    // cross-attention block
    rmsnorm_kernel<<<M, 256>>>(x, ln2, xn);
    tgemm_kernel<<<g8, 256, TG_SMEM>>>(xn,      ca_wq, q, M, 1024, 1024, qs,  nullptr, nullptr);
    tgemm_kernel<<<g8, 256, TG_SMEM>>>(encoded, ca_wk, k, M, 1024, 1024, 1.f, nullptr, nullptr);
    tgemm_kernel<<<g8, 256, TG_SMEM>>>(encoded, ca_wv, v, M, 1024, 1024, 1.f, nullptr, nullptr);
    fattn_kernel<<<ga, 256, FATTN_SMEM>>>(q, k, v, pk, pvv, relpos, att, 1, 0);
    tgemm_kernel<<<g8, 256, TG_SMEM>>>(att, ca_wo, y, M, 1024, 1024, 1.f, x, nullptr);

    // MLP + adapter
    rmsnorm_kernel<<<M, 256>>>(y, ln3, xn);     // xn = lz
    tgemm_kernel<<<g22, 256, TG_SMEM>>>(xn, wi0, h0, M, Fv, 1024, 1.f, nullptr, nullptr);
    tgemm_kernel<<<g22, 256, TG_SMEM>>>(xn, wi1, h1, M, Fv, 1024, 1.f, nullptr, h0);
    tgemm_kernel<<<g8, 256, TG_SMEM>>>(h1, wo_mlp, out, M, 1024, Fv, 1.f, y, nullptr);
    adapter_down<<<dim3(Lv, Bv), 64>>>(xn, awd, abd, az);
    adapter_up<<<dim3(Lv, Bv), 256>>>(az, awu, abu, out);
}

// round 5
// speedup vs baseline: 1.1865x; 1.1865x over previous
#include <cuda_runtime.h>
#include <cuda_bf16.h>
#include <math.h>

#define Bv 4
#define Lv 1024
#define Dv 1024
#define Hv 16
#define HDv 64
#define Fv 2816
#define Av 64
#define Pv 30
#define KTOT (Pv + Lv)
#define NKT 17

#define NSQ (1024*1024)
#define NWI (1024*2816)
// weight offsets in split weight pool
#define O_SAWQ ((size_t)0)
#define O_SAWK ((size_t)1*NSQ)
#define O_SAWV ((size_t)2*NSQ)
#define O_SAWO ((size_t)3*NSQ)
#define O_CAWQ ((size_t)4*NSQ)
#define O_CAWK ((size_t)5*NSQ)
#define O_CAWV ((size_t)6*NSQ)
#define O_CAWO ((size_t)7*NSQ)
#define O_WI0  ((size_t)8*NSQ)
#define O_WI1  (O_WI0 + NWI)
#define O_WO   (O_WI1 + NWI)
#define W_TOT  (O_WO + NWI)

// ---------------- scratch ----------------------------------------------------
__device__ float g_xn[Bv*Lv*Dv];          // f32 lz (adapter)
__device__ __nv_bfloat16 g_xnh[Bv*Lv*Dv], g_xnl[Bv*Lv*Dv];
__device__ __nv_bfloat16 g_ench[Bv*Lv*Dv], g_encl[Bv*Lv*Dv];
__device__ __nv_bfloat16 g_atth[Bv*Lv*Dv], g_attl[Bv*Lv*Dv];
__device__ float g_q [Bv*Lv*Dv];
__device__ float g_k [Bv*Lv*Dv];
__device__ float g_v [Bv*Lv*Dv];
__device__ float g_x [Bv*Lv*Dv];
__device__ float g_y [Bv*Lv*Dv];
__device__ float g_h0[Bv*Lv*Fv];
__device__ __nv_bfloat16 g_h1h[Bv*Lv*Fv], g_h1l[Bv*Lv*Fv];
__device__ float g_az[Bv*Lv*Av];
__device__ __nv_bfloat16 g_wth[W_TOT], g_wtl[W_TOT];

__device__ __forceinline__ float gelu_f(float x) {
    float x3 = x * x * x;
    return 0.5f * x * (1.0f + tanhf(0.7978845608028654f * (x + 0.044715f * x3)));
}

__device__ __forceinline__ void split1(float f, __nv_bfloat16& h, __nv_bfloat16& l) {
    h = __float2bfloat16(f);
    l = __float2bfloat16(f - __bfloat162float(h));
}

__device__ __forceinline__ void mma16816(float* c, const unsigned* a, const unsigned* b) {
    asm volatile(
        "mma.sync.aligned.m16n8k16.row.col.f32.bf16.bf16.f32 "
        "{%0,%1,%2,%3}, {%4,%5,%6,%7}, {%8,%9}, {%0,%1,%2,%3};\n"
        : "+f"(c[0]), "+f"(c[1]), "+f"(c[2]), "+f"(c[3])
        : "r"(a[0]), "r"(a[1]), "r"(a[2]), "r"(a[3]), "r"(b[0]), "r"(b[1]));
}

#define LDSM4(r0,r1,r2,r3,a) \
    asm volatile("ldmatrix.sync.aligned.m8n8.x4.shared.b16 {%0,%1,%2,%3}, [%4];" \
        : "=r"(r0),"=r"(r1),"=r"(r2),"=r"(r3) : "r"(a))

#define CPA16(dst, src) \
    asm volatile("cp.async.cg.shared.global [%0], [%1], 16;" :: "r"(dst), "l"(src))

// ---------------- split / transpose-split conversions ------------------------
__global__ __launch_bounds__(256) void split_kernel(
    const float* __restrict__ in, __nv_bfloat16* __restrict__ hi,
    __nv_bfloat16* __restrict__ lo, int n4)
{
    int i = blockIdx.x * 256 + threadIdx.x;
    if (i >= n4) return;
    float4 v = *(const float4*)&in[(size_t)i * 4];
    __nv_bfloat16 h[4], l[4];
    split1(v.x, h[0], l[0]); split1(v.y, h[1], l[1]);
    split1(v.z, h[2], l[2]); split1(v.w, h[3], l[3]);
    *(uint2*)&hi[(size_t)i * 4] = *(uint2*)h;
    *(uint2*)&lo[(size_t)i * 4] = *(uint2*)l;
}

// W [K][N] f32 -> Wt [N][K] bf16 hi/lo
__global__ __launch_bounds__(256) void tsplit_kernel(
    const float* __restrict__ W, __nv_bfloat16* __restrict__ th,
    __nv_bfloat16* __restrict__ tl, int K, int N)
{
    __shared__ float tile[32][33];
    int n0 = blockIdx.x * 32, k0 = blockIdx.y * 32;
    int tx = threadIdx.x & 31, ty = threadIdx.x >> 5;
    #pragma unroll
    for (int j = 0; j < 4; j++)
        tile[ty + 8*j][tx] = W[(size_t)(k0 + ty + 8*j) * N + n0 + tx];
    __syncthreads();
    #pragma unroll
    for (int j = 0; j < 4; j++) {
        float v = tile[tx][ty + 8*j];
        __nv_bfloat16 h, l;
        split1(v, h, l);
        size_t idx = (size_t)(n0 + ty + 8*j) * K + k0 + tx;
        th[idx] = h; tl[idx] = l;
    }
}

// ---------------- RMSNorm (emits split + optional f32) -----------------------
__global__ __launch_bounds__(256) void rmsnorm_kernel(
    const float* __restrict__ x, const float* __restrict__ w,
    float* __restrict__ of32, __nv_bfloat16* __restrict__ ohi,
    __nv_bfloat16* __restrict__ olo)
{
    int row = blockIdx.x;
    const float* xr = x + (size_t)row * Dv;
    int tid = threadIdx.x;
    int d0 = tid * 4;
    float4 v = *(const float4*)&xr[d0];
    float s = v.x*v.x + v.y*v.y + v.z*v.z + v.w*v.w;
    #pragma unroll
    for (int off = 16; off; off >>= 1) s += __shfl_xor_sync(0xffffffffu, s, off);
    __shared__ float red[8];
    __shared__ float inv_s;
    if ((tid & 31) == 0) red[tid >> 5] = s;
    __syncthreads();
    if (tid == 0) {
        float t = 0.f;
        #pragma unroll
        for (int i = 0; i < 8; i++) t += red[i];
        inv_s = rsqrtf(t * (1.0f / Dv) + 1e-6f);
    }
    __syncthreads();
    float inv = inv_s;
    float4 wv = *(const float4*)&w[d0];
    float r[4];
    r[0] = v.x*inv*wv.x; r[1] = v.y*inv*wv.y; r[2] = v.z*inv*wv.z; r[3] = v.w*inv*wv.w;
    size_t o = (size_t)row * Dv + d0;
    if (of32) { float4 rr; rr.x=r[0]; rr.y=r[1]; rr.z=r[2]; rr.w=r[3]; *(float4*)&of32[o] = rr; }
    __nv_bfloat16 h[4], l[4];
    #pragma unroll
    for (int i = 0; i < 4; i++) split1(r[i], h[i], l[i]);
    *(uint2*)&ohi[o] = *(uint2*)h;
    *(uint2*)&olo[o] = *(uint2*)l;
}

// ---------------- tensor-core GEMM on pre-split operands ---------------------
// A: [M][K] bf16 hi/lo row-major. B: [N][K] bf16 hi/lo (pre-transposed).
// out: f32 Cf (with res) OR split Chi/Clo (with gate).
#define TG_SEG 4096                 /* bf16 elems per array: 128 rows x 32 */
#define TG_BUF (4*TG_SEG)
#define TG_SMEM (2*TG_BUF*2)        /* 64 KB */

__device__ __forceinline__ unsigned sw_elem(int row, int c) {
    return (unsigned)(row * 32 + ((c ^ ((row >> 1) & 3)) << 3));
}

__global__ __launch_bounds__(256, 2) void tgemm_kernel(
    const __nv_bfloat16* __restrict__ Ahi, const __nv_bfloat16* __restrict__ Alo,
    const __nv_bfloat16* __restrict__ Bh,  const __nv_bfloat16* __restrict__ Bl,
    float* __restrict__ Cf, __nv_bfloat16* __restrict__ Chi, __nv_bfloat16* __restrict__ Clo,
    int M, int N, int K, float alpha,
    const float* __restrict__ res, const float* __restrict__ gate)
{
    extern __shared__ __align__(16) __nv_bfloat16 tgsm[];
    unsigned sbase = (unsigned)__cvta_generic_to_shared(tgsm);

    int tid  = threadIdx.x;
    int m0   = blockIdx.y * 128;
    int n0   = blockIdx.x * 128;
    int wid  = tid >> 5, lane = tid & 31;
    int g    = lane >> 2, tig = lane & 3;
    int l7   = lane & 7, sub = lane >> 3;
    int wm   = (wid & 1) * 64;
    int wn   = (wid >> 1) * 32;

    float acc[4][4][4];
    #pragma unroll
    for (int i = 0; i < 4; i++)
        #pragma unroll
        for (int j = 0; j < 4; j++)
            #pragma unroll
            for (int r = 0; r < 4; r++) acc[i][j][r] = 0.f;

#define TG_ISSUE(tt, bufb) do {                                                  \
    size_t k0i = (size_t)(tt) * 32;                                              \
    unsigned base = sbase + (unsigned)(bufb) * (TG_BUF * 2);                     \
    _Pragma("unroll")                                                            \
    for (int i_ = 0; i_ < 2; i_++) {                                             \
        int cc = tid + i_ * 256; int row = cc >> 2; int c4 = cc & 3;             \
        unsigned so = sw_elem(row, c4) * 2;                                      \
        size_t ga = (size_t)(m0 + row) * K + k0i + c4 * 8;                       \
        size_t gb = (size_t)(n0 + row) * K + k0i + c4 * 8;                       \
        CPA16(base + so,                 Ahi + ga);                              \
        CPA16(base + TG_SEG*2 + so,      Alo + ga);                              \
        CPA16(base + 2*TG_SEG*2 + so,    Bh + gb);                               \
        CPA16(base + 3*TG_SEG*2 + so,    Bl + gb);                               \
    }                                                                            \
    asm volatile("cp.async.commit_group;");                                      \
} while (0)

    TG_ISSUE(0, 0);
    int nk = K >> 5;
    for (int t = 0; t < nk; t++) {
        if (t + 1 < nk) {
            TG_ISSUE(t + 1, (t + 1) & 1);
            asm volatile("cp.async.wait_group 1;");
        } else {
            asm volatile("cp.async.wait_group 0;");
        }
        __syncthreads();

        unsigned bufo = sbase + (unsigned)(t & 1) * (TG_BUF * 2);
        #pragma unroll
        for (int ks = 0; ks < 2; ks++) {
            unsigned bh_[8], bl_[8];
            #pragma unroll
            for (int p = 0; p < 2; p++) {
                int nrow = wn + p * 16 + ((sub >> 1) << 3) + l7;
                int cB = ks * 2 + (sub & 1);
                unsigned ab = bufo + 2 * TG_SEG * 2 + sw_elem(nrow, cB) * 2;
                LDSM4(bh_[4*p+0], bh_[4*p+1], bh_[4*p+2], bh_[4*p+3], ab);
                unsigned abl = ab + TG_SEG * 2;
                LDSM4(bl_[4*p+0], bl_[4*p+1], bl_[4*p+2], bl_[4*p+3], abl);
            }
            #pragma unroll
            for (int mt = 0; mt < 4; mt++) {
                int arow = wm + mt * 16 + ((sub & 1) << 3) + l7;
                int cA = ks * 2 + (sub >> 1);
                unsigned aa = bufo + sw_elem(arow, cA) * 2;
                unsigned ah[4], al[4];
                LDSM4(ah[0], ah[1], ah[2], ah[3], aa);
                LDSM4(al[0], al[1], al[2], al[3], aa + TG_SEG * 2);
                #pragma unroll
                for (int nt = 0; nt < 4; nt++) {
                    mma16816(acc[mt][nt], ah, &bh_[nt * 2]);
                    mma16816(acc[mt][nt], ah, &bl_[nt * 2]);
                    mma16816(acc[mt][nt], al, &bh_[nt * 2]);
                }
            }
        }
        __syncthreads();
    }
#undef TG_ISSUE

    // ---- epilogue ----
    #pragma unroll
    for (int mt = 0; mt < 4; mt++) {
        #pragma unroll
        for (int half = 0; half < 2; half++) {
            int m = m0 + wm + mt * 16 + g + half * 8;
            #pragma unroll
            for (int nt = 0; nt < 4; nt++) {
                int n = n0 + wn + nt * 8 + 2 * tig;
                size_t idx = (size_t)m * N + n;
                float v0 = acc[mt][nt][half * 2 + 0] * alpha;
                float v1 = acc[mt][nt][half * 2 + 1] * alpha;
                if (res) {
                    float2 rv = *(const float2*)&res[idx];
                    v0 += rv.x; v1 += rv.y;
                }
                if (gate) {
                    float2 gv = *(const float2*)&gate[idx];
                    v0 *= gelu_f(gv.x); v1 *= gelu_f(gv.y);
                }
                if (Cf) {
                    float2 o; o.x = v0; o.y = v1;
                    *(float2*)&Cf[idx] = o;
                } else {
                    __nv_bfloat16 h0b, l0b, h1b, l1b;
                    split1(v0, h0b, l0b); split1(v1, h1b, l1b);
                    __nv_bfloat162 hh; hh.x = h0b; hh.y = h1b;
                    __nv_bfloat162 ll; ll.x = l0b; ll.y = l1b;
                    *(__nv_bfloat162*)&Chi[idx] = hh;
                    *(__nv_bfloat162*)&Clo[idx] = ll;
                }
            }
        }
    }
}

// ---------------- Flash attention (online softmax, prefix KV) ---------------
#define FATTN_SMEM ((32*64 + 32*68 + 64*68 + 64*68 + 4*32) * 4)

__global__ __launch_bounds__(256, 3) void fattn_kernel(
    const float* __restrict__ qb, const float* __restrict__ kb, const float* __restrict__ vb,
    const float* __restrict__ pkb, const float* __restrict__ pvb,
    const float* __restrict__ relpos,
    __nv_bfloat16* __restrict__ obh, __nv_bfloat16* __restrict__ obl,
    int sel, int causal)
{
    extern __shared__ float sm[];
    float* Qs     = sm;
    float* S      = Qs + 32 * 64;
    float* Ks     = S + 32 * 68;
    float* Vs     = Ks + 64 * 68;
    float* relrow = Vs + 64 * 68;
    float* rowm   = relrow + 32;
    float* rowl   = rowm + 32;
    float* corr   = rowl + 32;

    int tid = threadIdx.x;
    int bh = blockIdx.y;
    int b = bh >> 4, h = bh & 15;
    int q0 = blockIdx.x * 32;

    {
        int r  = tid >> 3;
        int c0 = (tid & 7) * 8;
        const float* src = qb + ((size_t)(b * Lv + q0 + r) * Hv + h) * HDv + c0;
        *(float4*)&Qs[r * 64 + c0]     = *(const float4*)src;
        *(float4*)&Qs[r * 64 + c0 + 4] = *(const float4*)(src + 4);
    }
    if (tid < 32) {
        if (causal) relrow[tid] = relpos[h * 32 + tid];
        rowm[tid] = -1e30f;
        rowl[tid] = 0.f;
    }
    __syncthreads();

    int qrb = tid >> 6;
    int kk  = tid & 63;

    float oacc[8];
    #pragma unroll
    for (int i = 0; i < 8; i++) oacc[i] = 0.f;

    int ntile = causal ? (Pv + q0 + 32 + 63) >> 6 : NKT;

    for (int t = 0; t < ntile; t++) {
        {
            int r = tid >> 2;
            int gg = t * 64 + r;
            bool valid = gg < KTOT;
            const float *ks, *vs;
            if (gg < Pv) {
                size_t off = (((size_t)(b * 2 + sel) * Pv + gg) * Hv + h) * HDv;
                ks = pkb + off; vs = pvb + off;
            } else {
                size_t off = ((size_t)(b * Lv + (gg - Pv)) * Hv + h) * HDv;
                ks = kb + off; vs = vb + off;
            }
            int c = (tid & 3) * 4;
            #pragma unroll
            for (int p = 0; p < 4; p++) {
                int cc = c + p * 16;
                float4 kv = valid ? *(const float4*)(ks + cc) : make_float4(0.f,0.f,0.f,0.f);
                float4 vv = valid ? *(const float4*)(vs + cc) : make_float4(0.f,0.f,0.f,0.f);
                *(float4*)&Ks[r * 68 + cc] = kv;
                *(float4*)&Vs[r * 68 + cc] = vv;
            }
        }
        __syncthreads();

        float sc[8];
        #pragma unroll
        for (int i = 0; i < 8; i++) sc[i] = 0.f;
        #pragma unroll
        for (int db = 0; db < 64; db += 16) {
            float kr[16];
            #pragma unroll
            for (int u = 0; u < 16; u += 4) {
                float4 v = *(const float4*)&Ks[kk * 68 + db + u];
                kr[u] = v.x; kr[u+1] = v.y; kr[u+2] = v.z; kr[u+3] = v.w;
            }
            #pragma unroll
            for (int i = 0; i < 8; i++) {
                const float* qp = &Qs[(qrb + i * 4) * 64 + db];
                #pragma unroll
                for (int u = 0; u < 16; u += 4) {
                    float4 v = *(const float4*)(qp + u);
                    sc[i] += v.x * kr[u] + v.y * kr[u+1] + v.z * kr[u+2] + v.w * kr[u+3];
                }
            }
        }
        {
            int gg = t * 64 + kk;
            #pragma unroll
            for (int i = 0; i < 8; i++) {
                int q = qrb + i * 4;
                float val = sc[i];
                if (gg >= KTOT) {
                    val = -1e10f;
                } else if (causal && gg >= Pv) {
                    int kp = gg - Pv;
                    int qp = q0 + q;
                    if (kp > qp) val = -1e10f;
                    else {
                        int rel = qp - kp;
                        int bkt;
                        if (rel < 16) bkt = rel;
                        else {
                            bkt = 16 + (int)(logf((float)rel * 0.0625f) *
                                             (16.0f / 2.0794415416798357f));
                            if (bkt > 31) bkt = 31;
                        }
                        val += relrow[bkt];
                    }
                }
                S[q * 68 + kk] = val;
            }
        }
        __syncthreads();

        {
            int wd = tid >> 5, lane = tid & 31;
            #pragma unroll
            for (int qi = 0; qi < 4; qi++) {
                int q = wd * 4 + qi;
                float* row = &S[q * 68];
                float v0 = row[lane], v1 = row[lane + 32];
                float tm = fmaxf(v0, v1);
                #pragma unroll
                for (int o = 16; o; o >>= 1) tm = fmaxf(tm, __shfl_xor_sync(0xffffffffu, tm, o));
                float mold = rowm[q];
                float mnew = fmaxf(mold, tm);
                float e0 = __expf(v0 - mnew), e1 = __expf(v1 - mnew);
                row[lane] = e0; row[lane + 32] = e1;
                float s = e0 + e1;
                #pragma unroll
                for (int o = 16; o; o >>= 1) s += __shfl_xor_sync(0xffffffffu, s, o);
                if (lane == 0) {
                    float c = __expf(mold - mnew);
                    rowm[q] = mnew;
                    rowl[q] = rowl[q] * c + s;
                    corr[q] = c;
                }
            }
        }
        __syncthreads();

        int d = kk;
        #pragma unroll
        for (int i = 0; i < 8; i++) oacc[i] *= corr[qrb + i * 4];
        #pragma unroll 4
        for (int k2 = 0; k2 < 64; k2++) {
            float vv = Vs[k2 * 68 + d];
            #pragma unroll
            for (int i = 0; i < 8; i++)
                oacc[i] += S[(qrb + i * 4) * 68 + k2] * vv;
        }
        __syncthreads();
    }

    #pragma unroll
    for (int i = 0; i < 8; i++) {
        int q = qrb + i * 4;
        float inv = 1.0f / rowl[q];
        float val = oacc[i] * inv;
        size_t idx = ((size_t)(b * Lv + q0 + q) * Hv + h) * HDv + kk;
        __nv_bfloat16 hh, ll;
        split1(val, hh, ll);
        obh[idx] = hh; obl[idx] = ll;
    }
}

// ---------------- per-example adapter ---------------------------------------
__global__ __launch_bounds__(64) void adapter_down(
    const float* __restrict__ lz, const float* __restrict__ wd,
    const float* __restrict__ bd, float* __restrict__ az)
{
    int b = blockIdx.y, l = blockIdx.x, a = threadIdx.x;
    const float* xr = lz + (size_t)(b * Lv + l) * Dv;
    const float* wb = wd + (size_t)b * Dv * Av;
    float s = 0.f;
    #pragma unroll 4
    for (int dd = 0; dd < Dv; dd++) s += xr[dd] * wb[dd * Av + a];
    s += bd[b * Av + a];
    az[(size_t)(b * Lv + l) * Av + a] = gelu_f(s);
}

__global__ __launch_bounds__(256) void adapter_up(
    const float* __restrict__ az, const float* __restrict__ wu,
    const float* __restrict__ bu, float* __restrict__ out)
{
    int b = blockIdx.y, l = blockIdx.x;
    __shared__ float ash[Av];
    int tid = threadIdx.x;
    if (tid < Av) ash[tid] = az[(size_t)(b * Lv + l) * Av + tid];
    __syncthreads();
    const float* wb = wu + (size_t)b * Av * Dv;
    size_t o = (size_t)(b * Lv + l) * Dv;
    for (int dd = tid; dd < Dv; dd += 256) {
        float s = bu[b * Dv + dd];
        #pragma unroll 8
        for (int a = 0; a < Av; a++) s += ash[a] * wb[a * Dv + dd];
        out[o + dd] += s;
    }
}

// ---------------- driver -----------------------------------------------------
extern "C" void kernel_launch(void* const* d_in, const int* in_sizes, int n_in,
                              void* d_out, int out_size)
{
    const float* inputs  = (const float*)d_in[0];
    const float* encoded = (const float*)d_in[1];
    const float* awd     = (const float*)d_in[2];
    const float* awu     = (const float*)d_in[3];
    const float* abd     = (const float*)d_in[4];
    const float* abu     = (const float*)d_in[5];
    const float* pk      = (const float*)d_in[6];
    const float* pvv     = (const float*)d_in[7];
    const float* ln1     = (const float*)d_in[8];
    const float* ln2     = (const float*)d_in[9];
    const float* ln3     = (const float*)d_in[10];
    const float* sa_wq   = (const float*)d_in[11];
    const float* sa_wk   = (const float*)d_in[12];
    const float* sa_wv   = (const float*)d_in[13];
    const float* sa_wo   = (const float*)d_in[14];
    const float* ca_wq   = (const float*)d_in[15];
    const float* ca_wk   = (const float*)d_in[16];
    const float* ca_wv   = (const float*)d_in[17];
    const float* ca_wo   = (const float*)d_in[18];
    const float* relpos  = (const float*)d_in[19];
    const float* wi0     = (const float*)d_in[20];
    const float* wi1     = (const float*)d_in[21];
    const float* wo_mlp  = (const float*)d_in[22];
    float* out = (float*)d_out;

    float *xn, *q, *k, *v, *x, *y, *h0, *az;
    __nv_bfloat16 *xnh, *xnl, *ench, *encl, *atth, *attl, *h1h, *h1l, *wth, *wtl;
    cudaGetSymbolAddress((void**)&xn,   g_xn);
    cudaGetSymbolAddress((void**)&xnh,  g_xnh);
    cudaGetSymbolAddress((void**)&xnl,  g_xnl);
    cudaGetSymbolAddress((void**)&ench, g_ench);
    cudaGetSymbolAddress((void**)&encl, g_encl);
    cudaGetSymbolAddress((void**)&atth, g_atth);
    cudaGetSymbolAddress((void**)&attl, g_attl);
    cudaGetSymbolAddress((void**)&q,    g_q);
    cudaGetSymbolAddress((void**)&k,    g_k);
    cudaGetSymbolAddress((void**)&v,    g_v);
    cudaGetSymbolAddress((void**)&x,    g_x);
    cudaGetSymbolAddress((void**)&y,    g_y);
    cudaGetSymbolAddress((void**)&h0,   g_h0);
    cudaGetSymbolAddress((void**)&h1h,  g_h1h);
    cudaGetSymbolAddress((void**)&h1l,  g_h1l);
    cudaGetSymbolAddress((void**)&az,   g_az);
    cudaGetSymbolAddress((void**)&wth,  g_wth);
    cudaGetSymbolAddress((void**)&wtl,  g_wtl);

    cudaFuncSetAttribute(fattn_kernel, cudaFuncAttributeMaxDynamicSharedMemorySize, FATTN_SMEM);
    cudaFuncSetAttribute(tgemm_kernel, cudaFuncAttributeMaxDynamicSharedMemorySize, TG_SMEM);

    const int M = Bv * Lv;
    dim3 g8(8, 32), g22(22, 32);
    dim3 ga(32, Bv * Hv);
    dim3 tsq(32, 32), tswi(88, 32), tswo(32, 88);
    const float qs = 0.125f;

    // ---- weight + encoded conversions (independent of intermediates) ----
    tsplit_kernel<<<tsq, 256>>>(sa_wq, wth + O_SAWQ, wtl + O_SAWQ, 1024, 1024);
    tsplit_kernel<<<tsq, 256>>>(sa_wk, wth + O_SAWK, wtl + O_SAWK, 1024, 1024);
    tsplit_kernel<<<tsq, 256>>>(sa_wv, wth + O_SAWV, wtl + O_SAWV, 1024, 1024);
    tsplit_kernel<<<tsq, 256>>>(sa_wo, wth + O_SAWO, wtl + O_SAWO, 1024, 1024);
    tsplit_kernel<<<tsq, 256>>>(ca_wq, wth + O_CAWQ, wtl + O_CAWQ, 1024, 1024);
    tsplit_kernel<<<tsq, 256>>>(ca_wk, wth + O_CAWK, wtl + O_CAWK, 1024, 1024);
    tsplit_kernel<<<tsq, 256>>>(ca_wv, wth + O_CAWV, wtl + O_CAWV, 1024, 1024);
    tsplit_kernel<<<tsq, 256>>>(ca_wo, wth + O_CAWO, wtl + O_CAWO, 1024, 1024);
    tsplit_kernel<<<tswi, 256>>>(wi0,    wth + O_WI0, wtl + O_WI0, 1024, 2816);
    tsplit_kernel<<<tswi, 256>>>(wi1,    wth + O_WI1, wtl + O_WI1, 1024, 2816);
    tsplit_kernel<<<tswo, 256>>>(wo_mlp, wth + O_WO,  wtl + O_WO,  2816, 1024);
    split_kernel<<<(M * Dv / 4 + 255) / 256, 256>>>(encoded, ench, encl, M * Dv / 4);

    // ---- self-attention block ----
    rmsnorm_kernel<<<M, 256>>>(inputs, ln1, nullptr, xnh, xnl);
    tgemm_kernel<<<g8, 256, TG_SMEM>>>(xnh, xnl, wth + O_SAWQ, wtl + O_SAWQ,
                                       q, nullptr, nullptr, M, 1024, 1024, qs, nullptr, nullptr);
    tgemm_kernel<<<g8, 256, TG_SMEM>>>(xnh, xnl, wth + O_SAWK, wtl + O_SAWK,
                                       k, nullptr, nullptr, M, 1024, 1024, 1.f, nullptr, nullptr);
    tgemm_kernel<<<g8, 256, TG_SMEM>>>(xnh, xnl, wth + O_SAWV, wtl + O_SAWV,
                                       v, nullptr, nullptr, M, 1024, 1024, 1.f, nullptr, nullptr);
    fattn_kernel<<<ga, 256, FATTN_SMEM>>>(q, k, v, pk, pvv, relpos, atth, attl, 0, 1);
    tgemm_kernel<<<g8, 256, TG_SMEM>>>(atth, attl, wth + O_SAWO, wtl + O_SAWO,
                                       x, nullptr, nullptr, M, 1024, 1024, 1.f, inputs, nullptr);

    // ---- cross-attention block ----
    rmsnorm_kernel<<<M, 256>>>(x, ln2, nullptr, xnh, xnl);
    tgemm_kernel<<<g8, 256, TG_SMEM>>>(xnh, xnl, wth + O_CAWQ, wtl + O_CAWQ,
                                       q, nullptr, nullptr, M, 1024, 1024, qs, nullptr, nullptr);
    tgemm_kernel<<<g8, 256, TG_SMEM>>>(ench, encl, wth + O_CAWK, wtl + O_CAWK,
                                       k, nullptr, nullptr, M, 1024, 1024, 1.f, nullptr, nullptr);
    tgemm_kernel<<<g8, 256, TG_SMEM>>>(ench, encl, wth + O_CAWV, wtl + O_CAWV,
                                       v, nullptr, nullptr, M, 1024, 1024, 1.f, nullptr, nullptr);
    fattn_kernel<<<ga, 256, FATTN_SMEM>>>(q, k, v, pk, pvv, relpos, atth, attl, 1, 0);
    tgemm_kernel<<<g8, 256, TG_SMEM>>>(atth, attl, wth + O_CAWO, wtl + O_CAWO,
                                       y, nullptr, nullptr, M, 1024, 1024, 1.f, x, nullptr);

    // ---- MLP + adapter ----
    rmsnorm_kernel<<<M, 256>>>(y, ln3, xn, xnh, xnl);
    tgemm_kernel<<<g22, 256, TG_SMEM>>>(xnh, xnl, wth + O_WI0, wtl + O_WI0,
                                        h0, nullptr, nullptr, M, Fv, 1024, 1.f, nullptr, nullptr);
    tgemm_kernel<<<g22, 256, TG_SMEM>>>(xnh, xnl, wth + O_WI1, wtl + O_WI1,
                                        nullptr, h1h, h1l, M, Fv, 1024, 1.f, nullptr, h0);
    tgemm_kernel<<<g8, 256, TG_SMEM>>>(h1h, h1l, wth + O_WO, wtl + O_WO,
                                       out, nullptr, nullptr, M, 1024, Fv, 1.f, y, nullptr);
    adapter_down<<<dim3(Lv, Bv), 64>>>(xn, awd, abd, az);
    adapter_up<<<dim3(Lv, Bv), 256>>>(az, awu, abu, out);
}

// round 6
// speedup vs baseline: 1.9475x; 1.6414x over previous
#include <cuda_runtime.h>
#include <cuda_bf16.h>
#include <math.h>

#define Bv 4
#define Lv 1024
#define Dv 1024
#define Hv 16
#define HDv 64
#define Fv 2816
#define Av 64
#define Pv 30
#define KTOT (Pv + Lv)
#define NKT 17
#define BQ 128

#define NSQ (1024*1024)
#define NWI (1024*2816)
#define O_SAWQ ((size_t)0)
#define O_SAWK ((size_t)1*NSQ)
#define O_SAWV ((size_t)2*NSQ)
#define O_SAWO ((size_t)3*NSQ)
#define O_CAWQ ((size_t)4*NSQ)
#define O_CAWK ((size_t)5*NSQ)
#define O_CAWV ((size_t)6*NSQ)
#define O_CAWO ((size_t)7*NSQ)
#define O_WI0  ((size_t)8*NSQ)
#define O_WI1  (O_WI0 + NWI)
#define O_WO   (O_WI1 + NWI)
#define W_TOT  (O_WO + NWI)
#define PFXN   (Bv*2*Pv*Hv*HDv)

// ---------------- scratch ----------------------------------------------------
__device__ float g_xn[Bv*Lv*Dv];
__device__ __nv_bfloat16 g_xnh[Bv*Lv*Dv], g_xnl[Bv*Lv*Dv];
__device__ __nv_bfloat16 g_ench[Bv*Lv*Dv], g_encl[Bv*Lv*Dv];
__device__ __nv_bfloat16 g_atth[Bv*Lv*Dv], g_attl[Bv*Lv*Dv];
__device__ __nv_bfloat16 g_qh[Bv*Lv*Dv], g_ql[Bv*Lv*Dv];
__device__ __nv_bfloat16 g_kh[Bv*Lv*Dv], g_kl[Bv*Lv*Dv];
__device__ __nv_bfloat16 g_vh[Bv*Lv*Dv], g_vl[Bv*Lv*Dv];
__device__ __nv_bfloat16 g_pkh[PFXN], g_pkl[PFXN], g_pvh[PFXN], g_pvl[PFXN];
__device__ float g_bias[Hv*1024];
__device__ float g_x [Bv*Lv*Dv];
__device__ float g_y [Bv*Lv*Dv];
__device__ float g_h0[Bv*Lv*Fv];
__device__ __nv_bfloat16 g_h1h[Bv*Lv*Fv], g_h1l[Bv*Lv*Fv];
__device__ float g_az[Bv*Lv*Av];
__device__ __nv_bfloat16 g_wth[W_TOT], g_wtl[W_TOT];

__device__ __forceinline__ float gelu_f(float x) {
    float x3 = x * x * x;
    return 0.5f * x * (1.0f + tanhf(0.7978845608028654f * (x + 0.044715f * x3)));
}

__device__ __forceinline__ void split1(float f, __nv_bfloat16& h, __nv_bfloat16& l) {
    h = __float2bfloat16(f);
    l = __float2bfloat16(f - __bfloat162float(h));
}

__device__ __forceinline__ void split2(float f0, float f1, unsigned &hi, unsigned &lo) {
    __nv_bfloat162 h = __floats2bfloat162_rn(f0, f1);
    float r0 = f0 - __bfloat162float(h.x);
    float r1 = f1 - __bfloat162float(h.y);
    __nv_bfloat162 l = __floats2bfloat162_rn(r0, r1);
    hi = *reinterpret_cast<unsigned*>(&h);
    lo = *reinterpret_cast<unsigned*>(&l);
}

__device__ __forceinline__ void mma16816(float* c, const unsigned* a, const unsigned* b) {
    asm volatile(
        "mma.sync.aligned.m16n8k16.row.col.f32.bf16.bf16.f32 "
        "{%0,%1,%2,%3}, {%4,%5,%6,%7}, {%8,%9}, {%0,%1,%2,%3};\n"
        : "+f"(c[0]), "+f"(c[1]), "+f"(c[2]), "+f"(c[3])
        : "r"(a[0]), "r"(a[1]), "r"(a[2]), "r"(a[3]), "r"(b[0]), "r"(b[1]));
}

#define LDSM4(r0,r1,r2,r3,a) \
    asm volatile("ldmatrix.sync.aligned.m8n8.x4.shared.b16 {%0,%1,%2,%3}, [%4];" \
        : "=r"(r0),"=r"(r1),"=r"(r2),"=r"(r3) : "r"(a))
#define LDSM4T(r0,r1,r2,r3,a) \
    asm volatile("ldmatrix.sync.aligned.m8n8.x4.trans.shared.b16 {%0,%1,%2,%3}, [%4];" \
        : "=r"(r0),"=r"(r1),"=r"(r2),"=r"(r3) : "r"(a))
#define CPA16(dst, src) \
    asm volatile("cp.async.cg.shared.global [%0], [%1], 16;" :: "r"(dst), "l"(src))
#define CPA16Z(dst, src) \
    asm volatile("cp.async.cg.shared.global [%0], [%1], 16, 0;" :: "r"(dst), "l"(src))

// ---------------- conversions -------------------------------------------------
__global__ __launch_bounds__(256) void split_kernel(
    const float* __restrict__ in, __nv_bfloat16* __restrict__ hi,
    __nv_bfloat16* __restrict__ lo, int n4)
{
    int i = blockIdx.x * 256 + threadIdx.x;
    if (i >= n4) return;
    float4 v = *(const float4*)&in[(size_t)i * 4];
    __nv_bfloat16 h[4], l[4];
    split1(v.x, h[0], l[0]); split1(v.y, h[1], l[1]);
    split1(v.z, h[2], l[2]); split1(v.w, h[3], l[3]);
    *(uint2*)&hi[(size_t)i * 4] = *(uint2*)h;
    *(uint2*)&lo[(size_t)i * 4] = *(uint2*)l;
}

__global__ __launch_bounds__(256) void tsplit_kernel(
    const float* __restrict__ W, __nv_bfloat16* __restrict__ th,
    __nv_bfloat16* __restrict__ tl, int K, int N)
{
    __shared__ float tile[32][33];
    int n0 = blockIdx.x * 32, k0 = blockIdx.y * 32;
    int tx = threadIdx.x & 31, ty = threadIdx.x >> 5;
    #pragma unroll
    for (int j = 0; j < 4; j++)
        tile[ty + 8*j][tx] = W[(size_t)(k0 + ty + 8*j) * N + n0 + tx];
    __syncthreads();
    #pragma unroll
    for (int j = 0; j < 4; j++) {
        float v = tile[tx][ty + 8*j];
        __nv_bfloat16 h, l;
        split1(v, h, l);
        size_t idx = (size_t)(n0 + ty + 8*j) * K + k0 + tx;
        th[idx] = h; tl[idx] = l;
    }
}

__global__ __launch_bounds__(256) void bias_build(
    const float* __restrict__ relpos, float* __restrict__ tab)
{
    int h = blockIdx.x;
    int r = blockIdx.y * 256 + threadIdx.x;
    int bkt;
    if (r < 16) bkt = r;
    else {
        bkt = 16 + (int)(logf((float)r * 0.0625f) * (16.0f / 2.0794415416798357f));
        if (bkt > 31) bkt = 31;
    }
    tab[h * 1024 + r] = relpos[h * 32 + bkt];
}

// ---------------- RMSNorm -----------------------------------------------------
__global__ __launch_bounds__(256) void rmsnorm_kernel(
    const float* __restrict__ x, const float* __restrict__ w,
    float* __restrict__ of32, __nv_bfloat16* __restrict__ ohi,
    __nv_bfloat16* __restrict__ olo)
{
    int row = blockIdx.x;
    const float* xr = x + (size_t)row * Dv;
    int tid = threadIdx.x;
    int d0 = tid * 4;
    float4 v = *(const float4*)&xr[d0];
    float s = v.x*v.x + v.y*v.y + v.z*v.z + v.w*v.w;
    #pragma unroll
    for (int off = 16; off; off >>= 1) s += __shfl_xor_sync(0xffffffffu, s, off);
    __shared__ float red[8];
    __shared__ float inv_s;
    if ((tid & 31) == 0) red[tid >> 5] = s;
    __syncthreads();
    if (tid == 0) {
        float t = 0.f;
        #pragma unroll
        for (int i = 0; i < 8; i++) t += red[i];
        inv_s = rsqrtf(t * (1.0f / Dv) + 1e-6f);
    }
    __syncthreads();
    float inv = inv_s;
    float4 wv = *(const float4*)&w[d0];
    float r[4];
    r[0] = v.x*inv*wv.x; r[1] = v.y*inv*wv.y; r[2] = v.z*inv*wv.z; r[3] = v.w*inv*wv.w;
    size_t o = (size_t)row * Dv + d0;
    if (of32) { float4 rr; rr.x=r[0]; rr.y=r[1]; rr.z=r[2]; rr.w=r[3]; *(float4*)&of32[o] = rr; }
    __nv_bfloat16 h[4], l[4];
    #pragma unroll
    for (int i = 0; i < 4; i++) split1(r[i], h[i], l[i]);
    *(uint2*)&ohi[o] = *(uint2*)h;
    *(uint2*)&olo[o] = *(uint2*)l;
}

// ---------------- tensor-core GEMM on pre-split operands ----------------------
#define TG_SEG 4096
#define TG_BUF (4*TG_SEG)
#define TG_SMEM (2*TG_BUF*2)

__device__ __forceinline__ unsigned sw_elem(int row, int c) {
    return (unsigned)(row * 32 + ((c ^ ((row >> 1) & 3)) << 3));
}

__global__ __launch_bounds__(256, 2) void tgemm_kernel(
    const __nv_bfloat16* __restrict__ Ahi, const __nv_bfloat16* __restrict__ Alo,
    const __nv_bfloat16* __restrict__ Bh,  const __nv_bfloat16* __restrict__ Bl,
    float* __restrict__ Cf, __nv_bfloat16* __restrict__ Chi, __nv_bfloat16* __restrict__ Clo,
    int M, int N, int K, float alpha,
    const float* __restrict__ res, const float* __restrict__ gate)
{
    extern __shared__ __align__(16) __nv_bfloat16 tgsm[];
    unsigned sbase = (unsigned)__cvta_generic_to_shared(tgsm);

    int tid  = threadIdx.x;
    int m0   = blockIdx.y * 128;
    int n0   = blockIdx.x * 128;
    int wid  = tid >> 5, lane = tid & 31;
    int g    = lane >> 2, tig = lane & 3;
    int l7   = lane & 7, sub = lane >> 3;
    int wm   = (wid & 1) * 64;
    int wn   = (wid >> 1) * 32;

    float acc[4][4][4];
    #pragma unroll
    for (int i = 0; i < 4; i++)
        #pragma unroll
        for (int j = 0; j < 4; j++)
            #pragma unroll
            for (int r = 0; r < 4; r++) acc[i][j][r] = 0.f;

#define TG_ISSUE(tt, bufb) do {                                                  \
    size_t k0i = (size_t)(tt) * 32;                                              \
    unsigned base = sbase + (unsigned)(bufb) * (TG_BUF * 2);                     \
    _Pragma("unroll")                                                            \
    for (int i_ = 0; i_ < 2; i_++) {                                             \
        int cc = tid + i_ * 256; int row = cc >> 2; int c4 = cc & 3;             \
        unsigned so = sw_elem(row, c4) * 2;                                      \
        size_t ga = (size_t)(m0 + row) * K + k0i + c4 * 8;                       \
        size_t gb = (size_t)(n0 + row) * K + k0i + c4 * 8;                       \
        CPA16(base + so,                 Ahi + ga);                              \
        CPA16(base + TG_SEG*2 + so,      Alo + ga);                              \
        CPA16(base + 2*TG_SEG*2 + so,    Bh + gb);                               \
        CPA16(base + 3*TG_SEG*2 + so,    Bl + gb);                               \
    }                                                                            \
    asm volatile("cp.async.commit_group;");                                      \
} while (0)

    TG_ISSUE(0, 0);
    int nk = K >> 5;
    for (int t = 0; t < nk; t++) {
        if (t + 1 < nk) {
            TG_ISSUE(t + 1, (t + 1) & 1);
            asm volatile("cp.async.wait_group 1;");
        } else {
            asm volatile("cp.async.wait_group 0;");
        }
        __syncthreads();

        unsigned bufo = sbase + (unsigned)(t & 1) * (TG_BUF * 2);
        #pragma unroll
        for (int ks = 0; ks < 2; ks++) {
            unsigned bh_[8], bl_[8];
            #pragma unroll
            for (int p = 0; p < 2; p++) {
                int nrow = wn + p * 16 + ((sub >> 1) << 3) + l7;
                int cB = ks * 2 + (sub & 1);
                unsigned ab = bufo + 2 * TG_SEG * 2 + sw_elem(nrow, cB) * 2;
                LDSM4(bh_[4*p+0], bh_[4*p+1], bh_[4*p+2], bh_[4*p+3], ab);
                unsigned abl = ab + TG_SEG * 2;
                LDSM4(bl_[4*p+0], bl_[4*p+1], bl_[4*p+2], bl_[4*p+3], abl);
            }
            #pragma unroll
            for (int mt = 0; mt < 4; mt++) {
                int arow = wm + mt * 16 + ((sub & 1) << 3) + l7;
                int cA = ks * 2 + (sub >> 1);
                unsigned aa = bufo + sw_elem(arow, cA) * 2;
                unsigned ah[4], al[4];
                LDSM4(ah[0], ah[1], ah[2], ah[3], aa);
                LDSM4(al[0], al[1], al[2], al[3], aa + TG_SEG * 2);
                #pragma unroll
                for (int nt = 0; nt < 4; nt++) {
                    mma16816(acc[mt][nt], ah, &bh_[nt * 2]);
                    mma16816(acc[mt][nt], ah, &bl_[nt * 2]);
                    mma16816(acc[mt][nt], al, &bh_[nt * 2]);
                }
            }
        }
        __syncthreads();
    }
#undef TG_ISSUE

    #pragma unroll
    for (int mt = 0; mt < 4; mt++) {
        #pragma unroll
        for (int half = 0; half < 2; half++) {
            int m = m0 + wm + mt * 16 + g + half * 8;
            #pragma unroll
            for (int nt = 0; nt < 4; nt++) {
                int n = n0 + wn + nt * 8 + 2 * tig;
                size_t idx = (size_t)m * N + n;
                float v0 = acc[mt][nt][half * 2 + 0] * alpha;
                float v1 = acc[mt][nt][half * 2 + 1] * alpha;
                if (res) {
                    float2 rv = *(const float2*)&res[idx];
                    v0 += rv.x; v1 += rv.y;
                }
                if (gate) {
                    float2 gv = *(const float2*)&gate[idx];
                    v0 *= gelu_f(gv.x); v1 *= gelu_f(gv.y);
                }
                if (Cf) {
                    float2 o; o.x = v0; o.y = v1;
                    *(float2*)&Cf[idx] = o;
                } else {
                    unsigned hh, ll;
                    split2(v0, v1, hh, ll);
                    *(unsigned*)&Chi[idx] = hh;
                    *(unsigned*)&Clo[idx] = ll;
                }
            }
        }
    }
}

// ---------------- MMA flash attention -----------------------------------------
// smem: Qhi 16K | Qlo 16K | 2x{Khi 8K,Klo 8K,Vhi 8K,Vlo 8K} | bias 4K = 100 KB
#define FA_QLO 16384
#define FA_KV  32768
#define FA_BIAS 98304
#define FA_SMEM 102400

__global__ __launch_bounds__(256) void fattn_kernel(
    const __nv_bfloat16* __restrict__ qh, const __nv_bfloat16* __restrict__ qlo_,
    const __nv_bfloat16* __restrict__ kh, const __nv_bfloat16* __restrict__ kl,
    const __nv_bfloat16* __restrict__ vh, const __nv_bfloat16* __restrict__ vl,
    const __nv_bfloat16* __restrict__ pkh, const __nv_bfloat16* __restrict__ pkl,
    const __nv_bfloat16* __restrict__ pvh, const __nv_bfloat16* __restrict__ pvl,
    const float* __restrict__ biasTab,
    __nv_bfloat16* __restrict__ obh, __nv_bfloat16* __restrict__ obl,
    int sel, int causal)
{
    extern __shared__ __align__(16) char fsm[];
    unsigned sb = (unsigned)__cvta_generic_to_shared(fsm);
    const float* sbias = (const float*)(fsm + FA_BIAS);
    int tid = threadIdx.x, wid = tid >> 5, lane = tid & 31;
    int g = lane >> 2, tig = lane & 3;
    int bhid = blockIdx.y; int b = bhid >> 4, h = bhid & 15;
    int q0 = blockIdx.x * BQ;
    int row0 = wid * 16;

    int ntile = causal ? ((Pv + q0 + BQ + 63) >> 6) : NKT;
    int lastk = Pv + q0 + row0 + 15;       // last key this warp can see (causal)

    const __nv_bfloat16* msrc[4] = {kh, kl, vh, vl};
    const __nv_bfloat16* psrc[4] = {pkh, pkl, pvh, pvl};
    int rk = tid >> 3, ck = tid & 7;

    // ---- prologue: stage Q (hi/lo) + bias table ----
    #pragma unroll
    for (int i = 0; i < 8; i++) {
        int arr = i >> 2;
        int r = rk + (i & 3) * 32;
        unsigned dst = sb + (arr ? FA_QLO : 0) + r * 128 + (((ck ^ (r & 7))) << 4);
        const __nv_bfloat16* src = (arr ? qlo_ : qh) +
            (((size_t)(b * Lv + q0 + r) * Hv + h) * HDv + ck * 8);
        CPA16(dst, src);
    }
    if (causal) CPA16(sb + FA_BIAS + tid * 16, biasTab + h * 1024 + tid * 4);

#define FA_STAGE(t, bufb) do {                                                   \
    int tb_ = (t) * 64;                                                          \
    _Pragma("unroll")                                                            \
    for (int a_ = 0; a_ < 4; a_++) {                                             \
        _Pragma("unroll")                                                        \
        for (int i2 = 0; i2 < 2; i2++) {                                         \
            int r = rk + i2 * 32;                                                \
            unsigned dst = sb + FA_KV + (unsigned)(bufb) * 32768 + a_ * 8192     \
                           + r * 128 + ((ck ^ (r & 7)) << 4);                    \
            int gk = tb_ + r;                                                    \
            const __nv_bfloat16* src;                                            \
            if (gk < Pv)                                                         \
                src = psrc[a_] + ((((size_t)(b * 2 + sel) * Pv + gk) * Hv + h) * HDv + ck * 8); \
            else                                                                 \
                src = msrc[a_] + (((size_t)(b * Lv + (gk < KTOT ? gk - Pv : 0)) * Hv + h) * HDv + ck * 8); \
            if (gk < KTOT) { CPA16(dst, src); } else { CPA16Z(dst, src); }       \
        }                                                                        \
    }                                                                            \
    asm volatile("cp.async.commit_group;");                                      \
} while (0)

    FA_STAGE(0, 0);                        // commits Q+bias+tile0 as group 0
    if (ntile > 1) FA_STAGE(1, 1);

    unsigned qhF[4][4], qlF[4][4];
    float S[8][4], O[8][4];
    #pragma unroll
    for (int i = 0; i < 8; i++) { O[i][0]=0.f; O[i][1]=0.f; O[i][2]=0.f; O[i][3]=0.f; }
    float m_lo = -1e30f, m_hi = -1e30f, l_lo = 0.f, l_hi = 0.f;
    int qrow_lo = q0 + row0 + g, qrow_hi = qrow_lo + 8;

    for (int t = 0; t < ntile; t++) {
        if (t + 1 < ntile) asm volatile("cp.async.wait_group 1;");
        else               asm volatile("cp.async.wait_group 0;");
        __syncthreads();

        if (t == 0) {      // load Q fragments once
            int lrow = row0 + (lane & 15);
            int cb = lane >> 4;
            #pragma unroll
            for (int ks = 0; ks < 4; ks++) {
                int ch = (ks * 2 + cb) ^ (lrow & 7);
                unsigned a = sb + lrow * 128 + (ch << 4);
                LDSM4(qhF[ks][0], qhF[ks][1], qhF[ks][2], qhF[ks][3], a);
                LDSM4(qlF[ks][0], qlF[ks][1], qlF[ks][2], qlF[ks][3], a + FA_QLO);
            }
        }

        bool act = causal ? (t * 64 <= lastk) : true;
        if (act) {
            unsigned kvb = sb + FA_KV + (unsigned)(t & 1) * 32768;
            #pragma unroll
            for (int i = 0; i < 8; i++) { S[i][0]=0.f; S[i][1]=0.f; S[i][2]=0.f; S[i][3]=0.f; }

            // ---- QK^T ----
            int krow = ((lane >> 4) << 3) + (lane & 7);
            int kcb = (lane >> 3) & 1;
            #pragma unroll
            for (int ks = 0; ks < 4; ks++) {
                #pragma unroll
                for (int j = 0; j < 4; j++) {
                    int kr = j * 16 + krow;
                    int ch = (ks * 2 + kcb) ^ (kr & 7);
                    unsigned ka = kvb + kr * 128 + (ch << 4);
                    unsigned bh_[4], bl_[4];
                    LDSM4(bh_[0], bh_[1], bh_[2], bh_[3], ka);
                    LDSM4(bl_[0], bl_[1], bl_[2], bl_[3], ka + 8192);
                    mma16816(S[2*j],   qhF[ks], bh_);
                    mma16816(S[2*j],   qhF[ks], bl_);
                    mma16816(S[2*j],   qlF[ks], bh_);
                    mma16816(S[2*j+1], qhF[ks], bh_ + 2);
                    mma16816(S[2*j+1], qhF[ks], bl_ + 2);
                    mma16816(S[2*j+1], qlF[ks], bh_ + 2);
                }
            }

            // ---- mask + bias ----
            int tb = t * 64;
            #pragma unroll
            for (int nt = 0; nt < 8; nt++) {
                #pragma unroll
                for (int u = 0; u < 2; u++) {
                    int key = tb + nt * 8 + 2 * tig + u;
                    if (key >= KTOT) { S[nt][u] = -1e10f; S[nt][2+u] = -1e10f; }
                    else if (causal) {
                        int kp = key - Pv;
                        if (kp >= 0) {
                            if (kp > qrow_lo) S[nt][u]   = -1e10f; else S[nt][u]   += sbias[qrow_lo - kp];
                            if (kp > qrow_hi) S[nt][2+u] = -1e10f; else S[nt][2+u] += sbias[qrow_hi - kp];
                        }
                    }
                }
            }

            // ---- online softmax (fragment-resident) ----
            float tm0 = -1e30f, tm1 = -1e30f;
            #pragma unroll
            for (int nt = 0; nt < 8; nt++) {
                tm0 = fmaxf(tm0, fmaxf(S[nt][0], S[nt][1]));
                tm1 = fmaxf(tm1, fmaxf(S[nt][2], S[nt][3]));
            }
            tm0 = fmaxf(tm0, __shfl_xor_sync(0xffffffffu, tm0, 1));
            tm0 = fmaxf(tm0, __shfl_xor_sync(0xffffffffu, tm0, 2));
            tm1 = fmaxf(tm1, __shfl_xor_sync(0xffffffffu, tm1, 1));
            tm1 = fmaxf(tm1, __shfl_xor_sync(0xffffffffu, tm1, 2));
            float mn0 = fmaxf(m_lo, tm0), mn1 = fmaxf(m_hi, tm1);
            float c0 = __expf(m_lo - mn0), c1 = __expf(m_hi - mn1);
            m_lo = mn0; m_hi = mn1;
            float s0 = 0.f, s1 = 0.f;
            #pragma unroll
            for (int nt = 0; nt < 8; nt++) {
                S[nt][0] = __expf(S[nt][0] - mn0); s0 += S[nt][0];
                S[nt][1] = __expf(S[nt][1] - mn0); s0 += S[nt][1];
                S[nt][2] = __expf(S[nt][2] - mn1); s1 += S[nt][2];
                S[nt][3] = __expf(S[nt][3] - mn1); s1 += S[nt][3];
            }
            s0 += __shfl_xor_sync(0xffffffffu, s0, 1);
            s0 += __shfl_xor_sync(0xffffffffu, s0, 2);
            s1 += __shfl_xor_sync(0xffffffffu, s1, 1);
            s1 += __shfl_xor_sync(0xffffffffu, s1, 2);
            l_lo = l_lo * c0 + s0; l_hi = l_hi * c1 + s1;
            #pragma unroll
            for (int nt = 0; nt < 8; nt++) {
                O[nt][0] *= c0; O[nt][1] *= c0; O[nt][2] *= c1; O[nt][3] *= c1;
            }

            // ---- P @ V ----
            int vrow = ((lane >> 3) & 1) * 8 + (lane & 7);
            int vcb = lane >> 4;
            #pragma unroll
            for (int ks = 0; ks < 4; ks++) {
                unsigned pah[4], pal[4];
                split2(S[2*ks][0],   S[2*ks][1],   pah[0], pal[0]);
                split2(S[2*ks][2],   S[2*ks][3],   pah[1], pal[1]);
                split2(S[2*ks+1][0], S[2*ks+1][1], pah[2], pal[2]);
                split2(S[2*ks+1][2], S[2*ks+1][3], pah[3], pal[3]);
                int vr = ks * 16 + vrow;
                #pragma unroll
                for (int j = 0; j < 4; j++) {
                    int ch = (2*j + vcb) ^ (vr & 7);
                    unsigned va = kvb + 16384 + vr * 128 + (ch << 4);
                    unsigned bh_[4], bl_[4];
                    LDSM4T(bh_[0], bh_[1], bh_[2], bh_[3], va);
                    LDSM4T(bl_[0], bl_[1], bl_[2], bl_[3], va + 8192);
                    mma16816(O[2*j],   pah, bh_);
                    mma16816(O[2*j],   pah, bl_);
                    mma16816(O[2*j],   pal, bh_);
                    mma16816(O[2*j+1], pah, bh_ + 2);
                    mma16816(O[2*j+1], pah, bl_ + 2);
                    mma16816(O[2*j+1], pal, bh_ + 2);
                }
            }
        }
        __syncthreads();
        if (t + 2 < ntile) FA_STAGE(t + 2, t & 1);
    }
#undef FA_STAGE

    float inv0 = 1.f / l_lo, inv1 = 1.f / l_hi;
    size_t base_lo = ((size_t)(b * Lv + qrow_lo) * Hv + h) * HDv + 2 * tig;
    size_t base_hi = ((size_t)(b * Lv + qrow_hi) * Hv + h) * HDv + 2 * tig;
    #pragma unroll
    for (int nt = 0; nt < 8; nt++) {
        unsigned h01, l01, h23, l23;
        split2(O[nt][0] * inv0, O[nt][1] * inv0, h01, l01);
        split2(O[nt][2] * inv1, O[nt][3] * inv1, h23, l23);
        *(unsigned*)&obh[base_lo + nt * 8] = h01;
        *(unsigned*)&obl[base_lo + nt * 8] = l01;
        *(unsigned*)&obh[base_hi + nt * 8] = h23;
        *(unsigned*)&obl[base_hi + nt * 8] = l23;
    }
}

// ---------------- per-example adapter -----------------------------------------
__global__ __launch_bounds__(64) void adapter_down(
    const float* __restrict__ lz, const float* __restrict__ wd,
    const float* __restrict__ bd, float* __restrict__ az)
{
    int b = blockIdx.y, l = blockIdx.x, a = threadIdx.x;
    const float* xr = lz + (size_t)(b * Lv + l) * Dv;
    const float* wb = wd + (size_t)b * Dv * Av;
    float s = 0.f;
    #pragma unroll 4
    for (int dd = 0; dd < Dv; dd++) s += xr[dd] * wb[dd * Av + a];
    s += bd[b * Av + a];
    az[(size_t)(b * Lv + l) * Av + a] = gelu_f(s);
}

__global__ __launch_bounds__(256) void adapter_up(
    const float* __restrict__ az, const float* __restrict__ wu,
    const float* __restrict__ bu, float* __restrict__ out)
{
    int b = blockIdx.y, l = blockIdx.x;
    __shared__ float ash[Av];
    int tid = threadIdx.x;
    if (tid < Av) ash[tid] = az[(size_t)(b * Lv + l) * Av + tid];
    __syncthreads();
    const float* wb = wu + (size_t)b * Av * Dv;
    size_t o = (size_t)(b * Lv + l) * Dv;
    for (int dd = tid; dd < Dv; dd += 256) {
        float s = bu[b * Dv + dd];
        #pragma unroll 8
        for (int a = 0; a < Av; a++) s += ash[a] * wb[a * Dv + dd];
        out[o + dd] += s;
    }
}

// ---------------- driver -------------------------------------------------------
extern "C" void kernel_launch(void* const* d_in, const int* in_sizes, int n_in,
                              void* d_out, int out_size)
{
    const float* inputs  = (const float*)d_in[0];
    const float* encoded = (const float*)d_in[1];
    const float* awd     = (const float*)d_in[2];
    const float* awu     = (const float*)d_in[3];
    const float* abd     = (const float*)d_in[4];
    const float* abu     = (const float*)d_in[5];
    const float* pk      = (const float*)d_in[6];
    const float* pvv     = (const float*)d_in[7];
    const float* ln1     = (const float*)d_in[8];
    const float* ln2     = (const float*)d_in[9];
    const float* ln3     = (const float*)d_in[10];
    const float* sa_wq   = (const float*)d_in[11];
    const float* sa_wk   = (const float*)d_in[12];
    const float* sa_wv   = (const float*)d_in[13];
    const float* sa_wo   = (const float*)d_in[14];
    const float* ca_wq   = (const float*)d_in[15];
    const float* ca_wk   = (const float*)d_in[16];
    const float* ca_wv   = (const float*)d_in[17];
    const float* ca_wo   = (const float*)d_in[18];
    const float* relpos  = (const float*)d_in[19];
    const float* wi0     = (const float*)d_in[20];
    const float* wi1     = (const float*)d_in[21];
    const float* wo_mlp  = (const float*)d_in[22];
    float* out = (float*)d_out;

    float *xn, *x, *y, *h0, *az, *bias;
    __nv_bfloat16 *xnh, *xnl, *ench, *encl, *atth, *attl, *h1h, *h1l, *wth, *wtl;
    __nv_bfloat16 *qh, *ql, *kh, *kl, *vh, *vl, *pkh, *pkl, *pvh, *pvl;
    cudaGetSymbolAddress((void**)&xn,   g_xn);
    cudaGetSymbolAddress((void**)&xnh,  g_xnh);
    cudaGetSymbolAddress((void**)&xnl,  g_xnl);
    cudaGetSymbolAddress((void**)&ench, g_ench);
    cudaGetSymbolAddress((void**)&encl, g_encl);
    cudaGetSymbolAddress((void**)&atth, g_atth);
    cudaGetSymbolAddress((void**)&attl, g_attl);
    cudaGetSymbolAddress((void**)&qh,   g_qh);
    cudaGetSymbolAddress((void**)&ql,   g_ql);
    cudaGetSymbolAddress((void**)&kh,   g_kh);
    cudaGetSymbolAddress((void**)&kl,   g_kl);
    cudaGetSymbolAddress((void**)&vh,   g_vh);
    cudaGetSymbolAddress((void**)&vl,   g_vl);
    cudaGetSymbolAddress((void**)&pkh,  g_pkh);
    cudaGetSymbolAddress((void**)&pkl,  g_pkl);
    cudaGetSymbolAddress((void**)&pvh,  g_pvh);
    cudaGetSymbolAddress((void**)&pvl,  g_pvl);
    cudaGetSymbolAddress((void**)&bias, g_bias);
    cudaGetSymbolAddress((void**)&x,    g_x);
    cudaGetSymbolAddress((void**)&y,    g_y);
    cudaGetSymbolAddress((void**)&h0,   g_h0);
    cudaGetSymbolAddress((void**)&h1h,  g_h1h);
    cudaGetSymbolAddress((void**)&h1l,  g_h1l);
    cudaGetSymbolAddress((void**)&az,   g_az);
    cudaGetSymbolAddress((void**)&wth,  g_wth);
    cudaGetSymbolAddress((void**)&wtl,  g_wtl);

    cudaFuncSetAttribute(fattn_kernel, cudaFuncAttributeMaxDynamicSharedMemorySize, FA_SMEM);
    cudaFuncSetAttribute(tgemm_kernel, cudaFuncAttributeMaxDynamicSharedMemorySize, TG_SMEM);

    const int M = Bv * Lv;
    dim3 g8(8, 32), g22(22, 32);
    dim3 ga(Lv / BQ, Bv * Hv);
    dim3 tsq(32, 32), tswi(88, 32), tswo(32, 88);
    const float qs = 0.125f;

    // ---- conversions (weights, encoded, prefix, bias table) ----
    tsplit_kernel<<<tsq, 256>>>(sa_wq, wth + O_SAWQ, wtl + O_SAWQ, 1024, 1024);
    tsplit_kernel<<<tsq, 256>>>(sa_wk, wth + O_SAWK, wtl + O_SAWK, 1024, 1024);
    tsplit_kernel<<<tsq, 256>>>(sa_wv, wth + O_SAWV, wtl + O_SAWV, 1024, 1024);
    tsplit_kernel<<<tsq, 256>>>(sa_wo, wth + O_SAWO, wtl + O_SAWO, 1024, 1024);
    tsplit_kernel<<<tsq, 256>>>(ca_wq, wth + O_CAWQ, wtl + O_CAWQ, 1024, 1024);
    tsplit_kernel<<<tsq, 256>>>(ca_wk, wth + O_CAWK, wtl + O_CAWK, 1024, 1024);
    tsplit_kernel<<<tsq, 256>>>(ca_wv, wth + O_CAWV, wtl + O_CAWV, 1024, 1024);
    tsplit_kernel<<<tsq, 256>>>(ca_wo, wth + O_CAWO, wtl + O_CAWO, 1024, 1024);
    tsplit_kernel<<<tswi, 256>>>(wi0,    wth + O_WI0, wtl + O_WI0, 1024, 2816);
    tsplit_kernel<<<tswi, 256>>>(wi1,    wth + O_WI1, wtl + O_WI1, 1024, 2816);
    tsplit_kernel<<<tswo, 256>>>(wo_mlp, wth + O_WO,  wtl + O_WO,  2816, 1024);
    split_kernel<<<(M * Dv / 4 + 255) / 256, 256>>>(encoded, ench, encl, M * Dv / 4);
    split_kernel<<<(PFXN / 4 + 255) / 256, 256>>>(pk,  pkh, pkl, PFXN / 4);
    split_kernel<<<(PFXN / 4 + 255) / 256, 256>>>(pvv, pvh, pvl, PFXN / 4);
    bias_build<<<dim3(Hv, 4), 256>>>(relpos, bias);

    // ---- self-attention block ----
    rmsnorm_kernel<<<M, 256>>>(inputs, ln1, nullptr, xnh, xnl);
    tgemm_kernel<<<g8, 256, TG_SMEM>>>(xnh, xnl, wth + O_SAWQ, wtl + O_SAWQ,
                                       nullptr, qh, ql, M, 1024, 1024, qs, nullptr, nullptr);
    tgemm_kernel<<<g8, 256, TG_SMEM>>>(xnh, xnl, wth + O_SAWK, wtl + O_SAWK,
                                       nullptr, kh, kl, M, 1024, 1024, 1.f, nullptr, nullptr);
    tgemm_kernel<<<g8, 256, TG_SMEM>>>(xnh, xnl, wth + O_SAWV, wtl + O_SAWV,
                                       nullptr, vh, vl, M, 1024, 1024, 1.f, nullptr, nullptr);
    fattn_kernel<<<ga, 256, FA_SMEM>>>(qh, ql, kh, kl, vh, vl, pkh, pkl, pvh, pvl,
                                       bias, atth, attl, 0, 1);
    tgemm_kernel<<<g8, 256, TG_SMEM>>>(atth, attl, wth + O_SAWO, wtl + O_SAWO,
                                       x, nullptr, nullptr, M, 1024, 1024, 1.f, inputs, nullptr);

    // ---- cross-attention block ----
    rmsnorm_kernel<<<M, 256>>>(x, ln2, nullptr, xnh, xnl);
    tgemm_kernel<<<g8, 256, TG_SMEM>>>(xnh, xnl, wth + O_CAWQ, wtl + O_CAWQ,
                                       nullptr, qh, ql, M, 1024, 1024, qs, nullptr, nullptr);
    tgemm_kernel<<<g8, 256, TG_SMEM>>>(ench, encl, wth + O_CAWK, wtl + O_CAWK,
                                       nullptr, kh, kl, M, 1024, 1024, 1.f, nullptr, nullptr);
    tgemm_kernel<<<g8, 256, TG_SMEM>>>(ench, encl, wth + O_CAWV, wtl + O_CAWV,
                                       nullptr, vh, vl, M, 1024, 1024, 1.f, nullptr, nullptr);
    fattn_kernel<<<ga, 256, FA_SMEM>>>(qh, ql, kh, kl, vh, vl, pkh, pkl, pvh, pvl,
                                       bias, atth, attl, 1, 0);
    tgemm_kernel<<<g8, 256, TG_SMEM>>>(atth, attl, wth + O_CAWO, wtl + O_CAWO,
                                       y, nullptr, nullptr, M, 1024, 1024, 1.f, x, nullptr);

    // ---- MLP + adapter ----
    rmsnorm_kernel<<<M, 256>>>(y, ln3, xn, xnh, xnl);
    tgemm_kernel<<<g22, 256, TG_SMEM>>>(xnh, xnl, wth + O_WI0, wtl + O_WI0,
                                        h0, nullptr, nullptr, M, Fv, 1024, 1.f, nullptr, nullptr);
    tgemm_kernel<<<g22, 256, TG_SMEM>>>(xnh, xnl, wth + O_WI1, wtl + O_WI1,
                                        nullptr, h1h, h1l, M, Fv, 1024, 1.f, nullptr, h0);
    tgemm_kernel<<<g8, 256, TG_SMEM>>>(h1h, h1l, wth + O_WO, wtl + O_WO,
                                       out, nullptr, nullptr, M, 1024, Fv, 1.f, y, nullptr);
    adapter_down<<<dim3(Lv, Bv), 64>>>(xn, awd, abd, az);
    adapter_up<<<dim3(Lv, Bv), 256>>>(az, awu, abu, out);
}

// round 9
// speedup vs baseline: 1.9511x; 1.0019x over previous
#include <cuda_runtime.h>
#include <cuda_bf16.h>
#include <math.h>

#define Bv 4
#define Lv 1024
#define Dv 1024
#define Hv 16
#define HDv 64
#define Fv 2816
#define Av 64
#define Pv 30
#define KTOT (Pv + Lv)
#define NKT 17
#define BQ 128

#define NSQ (1024*1024)
#define NWI (1024*2816)
#define O_SAWQ ((size_t)0)
#define O_SAWK ((size_t)1*NSQ)
#define O_SAWV ((size_t)2*NSQ)
#define O_SAWO ((size_t)3*NSQ)
#define O_CAWQ ((size_t)4*NSQ)
#define O_CAWK ((size_t)5*NSQ)
#define O_CAWV ((size_t)6*NSQ)
#define O_CAWO ((size_t)7*NSQ)
#define O_WI0  ((size_t)8*NSQ)
#define O_WI1  (O_WI0 + NWI)
#define O_WO   (O_WI1 + NWI)
#define W_TOT  (O_WO + NWI)
#define PFXN   (Bv*2*Pv*Hv*HDv)

// ---------------- scratch ----------------------------------------------------
__device__ float g_xn[Bv*Lv*Dv];
__device__ __nv_bfloat16 g_xnh[Bv*Lv*Dv], g_xnl[Bv*Lv*Dv];
__device__ __nv_bfloat16 g_ench[Bv*Lv*Dv], g_encl[Bv*Lv*Dv];
__device__ __nv_bfloat16 g_atth[Bv*Lv*Dv], g_attl[Bv*Lv*Dv];
__device__ __nv_bfloat16 g_qkvh[Bv*Lv*3*Dv], g_qkvl[Bv*Lv*3*Dv];
__device__ __nv_bfloat16 g_cqh[Bv*Lv*Dv], g_cql[Bv*Lv*Dv];
__device__ __nv_bfloat16 g_pkh[PFXN], g_pkl[PFXN], g_pvh[PFXN], g_pvl[PFXN];
__device__ float g_bias[Hv*1024];
__device__ float g_x [Bv*Lv*Dv];
__device__ float g_y [Bv*Lv*Dv];
__device__ float g_h0[Bv*Lv*Fv];
__device__ __nv_bfloat16 g_h1h[Bv*Lv*Fv], g_h1l[Bv*Lv*Fv];
__device__ float g_az[Bv*Lv*Av];
__device__ __nv_bfloat16 g_wth[W_TOT], g_wtl[W_TOT];

__device__ __forceinline__ float gelu_f(float x) {
    float x3 = x * x * x;
    return 0.5f * x * (1.0f + tanhf(0.7978845608028654f * (x + 0.044715f * x3)));
}

__device__ __forceinline__ void split1(float f, __nv_bfloat16& h, __nv_bfloat16& l) {
    h = __float2bfloat16(f);
    l = __float2bfloat16(f - __bfloat162float(h));
}

__device__ __forceinline__ void split2(float f0, float f1, unsigned &hi, unsigned &lo) {
    __nv_bfloat162 h = __floats2bfloat162_rn(f0, f1);
    float r0 = f0 - __bfloat162float(h.x);
    float r1 = f1 - __bfloat162float(h.y);
    __nv_bfloat162 l = __floats2bfloat162_rn(r0, r1);
    hi = *reinterpret_cast<unsigned*>(&h);
    lo = *reinterpret_cast<unsigned*>(&l);
}

__device__ __forceinline__ void mma16816(float* c, const unsigned* a, const unsigned* b) {
    asm volatile(
        "mma.sync.aligned.m16n8k16.row.col.f32.bf16.bf16.f32 "
        "{%0,%1,%2,%3}, {%4,%5,%6,%7}, {%8,%9}, {%0,%1,%2,%3};\n"
        : "+f"(c[0]), "+f"(c[1]), "+f"(c[2]), "+f"(c[3])
        : "r"(a[0]), "r"(a[1]), "r"(a[2]), "r"(a[3]), "r"(b[0]), "r"(b[1]));
}

#define LDSM4(r0,r1,r2,r3,a) \
    asm volatile("ldmatrix.sync.aligned.m8n8.x4.shared.b16 {%0,%1,%2,%3}, [%4];" \
        : "=r"(r0),"=r"(r1),"=r"(r2),"=r"(r3) : "r"(a))
#define LDSM4T(r0,r1,r2,r3,a) \
    asm volatile("ldmatrix.sync.aligned.m8n8.x4.trans.shared.b16 {%0,%1,%2,%3}, [%4];" \
        : "=r"(r0),"=r"(r1),"=r"(r2),"=r"(r3) : "r"(a))
#define CPA16(dst, src) \
    asm volatile("cp.async.cg.shared.global [%0], [%1], 16;" :: "r"(dst), "l"(src))
#define CPA16Z(dst, src) \
    asm volatile("cp.async.cg.shared.global [%0], [%1], 16, 0;" :: "r"(dst), "l"(src))

// ---------------- conversions -------------------------------------------------
__global__ __launch_bounds__(256) void split_kernel(
    const float* __restrict__ in, __nv_bfloat16* __restrict__ hi,
    __nv_bfloat16* __restrict__ lo, int n4)
{
    int i = blockIdx.x * 256 + threadIdx.x;
    if (i >= n4) return;
    float4 v = *(const float4*)&in[(size_t)i * 4];
    __nv_bfloat16 h[4], l[4];
    split1(v.x, h[0], l[0]); split1(v.y, h[1], l[1]);
    split1(v.z, h[2], l[2]); split1(v.w, h[3], l[3]);
    *(uint2*)&hi[(size_t)i * 4] = *(uint2*)h;
    *(uint2*)&lo[(size_t)i * 4] = *(uint2*)l;
}

// W [K][N] f32 -> Wt [N][K] bf16 hi/lo, scaled (scale must be a power of 2)
__global__ __launch_bounds__(256) void tsplit_kernel(
    const float* __restrict__ W, __nv_bfloat16* __restrict__ th,
    __nv_bfloat16* __restrict__ tl, int K, int N, float scale)
{
    __shared__ float tile[32][33];
    int n0 = blockIdx.x * 32, k0 = blockIdx.y * 32;
    int tx = threadIdx.x & 31, ty = threadIdx.x >> 5;
    #pragma unroll
    for (int j = 0; j < 4; j++)
        tile[ty + 8*j][tx] = W[(size_t)(k0 + ty + 8*j) * N + n0 + tx];
    __syncthreads();
    #pragma unroll
    for (int j = 0; j < 4; j++) {
        float v = tile[tx][ty + 8*j] * scale;
        __nv_bfloat16 h, l;
        split1(v, h, l);
        size_t idx = (size_t)(n0 + ty + 8*j) * K + k0 + tx;
        th[idx] = h; tl[idx] = l;
    }
}

__global__ __launch_bounds__(256) void bias_build(
    const float* __restrict__ relpos, float* __restrict__ tab)
{
    int h = blockIdx.x;
    int r = blockIdx.y * 256 + threadIdx.x;
    int bkt;
    if (r < 16) bkt = r;
    else {
        bkt = 16 + (int)(logf((float)r * 0.0625f) * (16.0f / 2.0794415416798357f));
        if (bkt > 31) bkt = 31;
    }
    tab[h * 1024 + r] = relpos[h * 32 + bkt];
}

// ---------------- RMSNorm -----------------------------------------------------
__global__ __launch_bounds__(256) void rmsnorm_kernel(
    const float* __restrict__ x, const float* __restrict__ w,
    float* __restrict__ of32, __nv_bfloat16* __restrict__ ohi,
    __nv_bfloat16* __restrict__ olo)
{
    int row = blockIdx.x;
    const float* xr = x + (size_t)row * Dv;
    int tid = threadIdx.x;
    int d0 = tid * 4;
    float4 v = *(const float4*)&xr[d0];
    float s = v.x*v.x + v.y*v.y + v.z*v.z + v.w*v.w;
    #pragma unroll
    for (int off = 16; off; off >>= 1) s += __shfl_xor_sync(0xffffffffu, s, off);
    __shared__ float red[8];
    __shared__ float inv_s;
    if ((tid & 31) == 0) red[tid >> 5] = s;
    __syncthreads();
    if (tid == 0) {
        float t = 0.f;
        #pragma unroll
        for (int i = 0; i < 8; i++) t += red[i];
        inv_s = rsqrtf(t * (1.0f / Dv) + 1e-6f);
    }
    __syncthreads();
    float inv = inv_s;
    float4 wv = *(const float4*)&w[d0];
    float r[4];
    r[0] = v.x*inv*wv.x; r[1] = v.y*inv*wv.y; r[2] = v.z*inv*wv.z; r[3] = v.w*inv*wv.w;
    size_t o = (size_t)row * Dv + d0;
    if (of32) { float4 rr; rr.x=r[0]; rr.y=r[1]; rr.z=r[2]; rr.w=r[3]; *(float4*)&of32[o] = rr; }
    __nv_bfloat16 h[4], l[4];
    #pragma unroll
    for (int i = 0; i < 4; i++) split1(r[i], h[i], l[i]);
    *(uint2*)&ohi[o] = *(uint2*)h;
    *(uint2*)&olo[o] = *(uint2*)l;
}

// ---------------- tensor-core GEMM, 3-stage cp.async, 1 sync/tile ------------
#define TG_SEG 4096
#define TG_BUF (4*TG_SEG)
#define TG_SMEM (3*TG_BUF*2)      /* 96 KB */

__device__ __forceinline__ unsigned sw_elem(int row, int c) {
    return (unsigned)(row * 32 + ((c ^ ((row >> 1) & 3)) << 3));
}

__global__ __launch_bounds__(256, 2) void tgemm_kernel(
    const __nv_bfloat16* __restrict__ Ahi, const __nv_bfloat16* __restrict__ Alo,
    const __nv_bfloat16* __restrict__ Bh,  const __nv_bfloat16* __restrict__ Bl,
    float* __restrict__ Cf, __nv_bfloat16* __restrict__ Chi, __nv_bfloat16* __restrict__ Clo,
    int M, int N, int K,
    const float* __restrict__ res, const float* __restrict__ gate)
{
    extern __shared__ __align__(16) __nv_bfloat16 tgsm[];
    unsigned sbase = (unsigned)__cvta_generic_to_shared(tgsm);

    int tid  = threadIdx.x;
    int m0   = blockIdx.y * 128;
    int n0   = blockIdx.x * 128;
    int wid  = tid >> 5, lane = tid & 31;
    int g    = lane >> 2, tig = lane & 3;
    int l7   = lane & 7, sub = lane >> 3;
    int wm   = (wid & 1) * 64;
    int wn   = (wid >> 1) * 32;

    float acc[4][4][4];
    #pragma unroll
    for (int i = 0; i < 4; i++)
        #pragma unroll
        for (int j = 0; j < 4; j++)
            #pragma unroll
            for (int r = 0; r < 4; r++) acc[i][j][r] = 0.f;

#define TG_ISSUE(tt, bufb) do {                                                  \
    size_t k0i = (size_t)(tt) * 32;                                              \
    unsigned base = sbase + (unsigned)(bufb) * (TG_BUF * 2);                     \
    _Pragma("unroll")                                                            \
    for (int i_ = 0; i_ < 2; i_++) {                                             \
        int cc = tid + i_ * 256; int row = cc >> 2; int c4 = cc & 3;             \
        unsigned so = sw_elem(row, c4) * 2;                                      \
        size_t ga = (size_t)(m0 + row) * K + k0i + c4 * 8;                       \
        size_t gb = (size_t)(n0 + row) * K + k0i + c4 * 8;                       \
        CPA16(base + so,                 Ahi + ga);                              \
        CPA16(base + TG_SEG*2 + so,      Alo + ga);                              \
        CPA16(base + 2*TG_SEG*2 + so,    Bh + gb);                               \
        CPA16(base + 3*TG_SEG*2 + so,    Bl + gb);                               \
    }                                                                            \
    asm volatile("cp.async.commit_group;");                                      \
} while (0)

    int nk = K >> 5;
    TG_ISSUE(0, 0);
    if (nk > 1) TG_ISSUE(1, 1);

    int buf = 0;
    for (int t = 0; t < nk; t++) {
        if (t + 1 < nk) asm volatile("cp.async.wait_group 1;");
        else            asm volatile("cp.async.wait_group 0;");
        __syncthreads();

        if (t + 2 < nk) {
            int nb = buf + 2; if (nb >= 3) nb -= 3;
            TG_ISSUE(t + 2, nb);
        }

        unsigned bufo = sbase + (unsigned)buf * (TG_BUF * 2);
        #pragma unroll
        for (int ks = 0; ks < 2; ks++) {
            unsigned bh_[8], bl_[8];
            #pragma unroll
            for (int p = 0; p < 2; p++) {
                int nrow = wn + p * 16 + ((sub >> 1) << 3) + l7;
                int cB = ks * 2 + (sub & 1);
                unsigned ab = bufo + 2 * TG_SEG * 2 + sw_elem(nrow, cB) * 2;
                LDSM4(bh_[4*p+0], bh_[4*p+1], bh_[4*p+2], bh_[4*p+3], ab);
                LDSM4(bl_[4*p+0], bl_[4*p+1], bl_[4*p+2], bl_[4*p+3], ab + TG_SEG * 2);
            }
            #pragma unroll
            for (int mt = 0; mt < 4; mt++) {
                int arow = wm + mt * 16 + ((sub & 1) << 3) + l7;
                int cA = ks * 2 + (sub >> 1);
                unsigned aa = bufo + sw_elem(arow, cA) * 2;
                unsigned ah[4], al[4];
                LDSM4(ah[0], ah[1], ah[2], ah[3], aa);
                LDSM4(al[0], al[1], al[2], al[3], aa + TG_SEG * 2);
                #pragma unroll
                for (int nt = 0; nt < 4; nt++) {
                    mma16816(acc[mt][nt], ah, &bh_[nt * 2]);
                    mma16816(acc[mt][nt], ah, &bl_[nt * 2]);
                    mma16816(acc[mt][nt], al, &bh_[nt * 2]);
                }
            }
        }
        if (++buf == 3) buf = 0;
    }
#undef TG_ISSUE

    #pragma unroll
    for (int mt = 0; mt < 4; mt++) {
        #pragma unroll
        for (int half = 0; half < 2; half++) {
            int m = m0 + wm + mt * 16 + g + half * 8;
            #pragma unroll
            for (int nt = 0; nt < 4; nt++) {
                int n = n0 + wn + nt * 8 + 2 * tig;
                size_t idx = (size_t)m * N + n;
                float v0 = acc[mt][nt][half * 2 + 0];
                float v1 = acc[mt][nt][half * 2 + 1];
                if (res) {
                    float2 rv = *(const float2*)&res[idx];
                    v0 += rv.x; v1 += rv.y;
                }
                if (gate) {
                    float2 gv = *(const float2*)&gate[idx];
                    v0 *= gelu_f(gv.x); v1 *= gelu_f(gv.y);
                }
                if (Cf) {
                    float2 o; o.x = v0; o.y = v1;
                    *(float2*)&Cf[idx] = o;
                } else {
                    unsigned hh, ll;
                    split2(v0, v1, hh, ll);
                    *(unsigned*)&Chi[idx] = hh;
                    *(unsigned*)&Clo[idx] = ll;
                }
            }
        }
    }
}

// ---------------- MMA flash attention (strided q/kv for fused layouts) --------
#define FA_QLO 16384
#define FA_KV  32768
#define FA_BIAS 98304
#define FA_SMEM 102400

__global__ __launch_bounds__(256) void fattn_kernel(
    const __nv_bfloat16* __restrict__ qh, const __nv_bfloat16* __restrict__ qlo_,
    const __nv_bfloat16* __restrict__ kh, const __nv_bfloat16* __restrict__ kl,
    const __nv_bfloat16* __restrict__ vh, const __nv_bfloat16* __restrict__ vl,
    int qstride, int kvstride,
    const __nv_bfloat16* __restrict__ pkh, const __nv_bfloat16* __restrict__ pkl,
    const __nv_bfloat16* __restrict__ pvh, const __nv_bfloat16* __restrict__ pvl,
    const float* __restrict__ biasTab,
    __nv_bfloat16* __restrict__ obh, __nv_bfloat16* __restrict__ obl,
    int sel, int causal)
{
    extern __shared__ __align__(16) char fsm[];
    unsigned sb = (unsigned)__cvta_generic_to_shared(fsm);
    const float* sbias = (const float*)(fsm + FA_BIAS);
    int tid = threadIdx.x, wid = tid >> 5, lane = tid & 31;
    int g = lane >> 2, tig = lane & 3;
    int bhid = blockIdx.y; int b = bhid >> 4, h = bhid & 15;
    int q0 = blockIdx.x * BQ;
    int row0 = wid * 16;

    int ntile = causal ? ((Pv + q0 + BQ + 63) >> 6) : NKT;
    int lastk = Pv + q0 + row0 + 15;

    const __nv_bfloat16* msrc[4] = {kh, kl, vh, vl};
    const __nv_bfloat16* psrc[4] = {pkh, pkl, pvh, pvl};
    int rk = tid >> 3, ck = tid & 7;

    #pragma unroll
    for (int i = 0; i < 8; i++) {
        int arr = i >> 2;
        int r = rk + (i & 3) * 32;
        unsigned dst = sb + (arr ? FA_QLO : 0) + r * 128 + (((ck ^ (r & 7))) << 4);
        const __nv_bfloat16* src = (arr ? qlo_ : qh) +
            ((size_t)(b * Lv + q0 + r) * qstride + h * HDv + ck * 8);
        CPA16(dst, src);
    }
    if (causal) CPA16(sb + FA_BIAS + tid * 16, biasTab + h * 1024 + tid * 4);

#define FA_STAGE(t, bufb) do {                                                   \
    int tb_ = (t) * 64;                                                          \
    _Pragma("unroll")                                                            \
    for (int a_ = 0; a_ < 4; a_++) {                                             \
        _Pragma("unroll")                                                        \
        for (int i2 = 0; i2 < 2; i2++) {                                         \
            int r = rk + i2 * 32;                                                \
            unsigned dst = sb + FA_KV + (unsigned)(bufb) * 32768 + a_ * 8192     \
                           + r * 128 + ((ck ^ (r & 7)) << 4);                    \
            int gk = tb_ + r;                                                    \
            const __nv_bfloat16* src;                                            \
            if (gk < Pv)                                                         \
                src = psrc[a_] + ((((size_t)(b * 2 + sel) * Pv + gk) * Hv + h) * HDv + ck * 8); \
            else                                                                 \
                src = msrc[a_] + ((size_t)(b * Lv + (gk < KTOT ? gk - Pv : 0)) * kvstride + h * HDv + ck * 8); \
            if (gk < KTOT) { CPA16(dst, src); } else { CPA16Z(dst, src); }       \
        }                                                                        \
    }                                                                            \
    asm volatile("cp.async.commit_group;");                                      \
} while (0)

    FA_STAGE(0, 0);
    if (ntile > 1) FA_STAGE(1, 1);

    unsigned qhF[4][4], qlF[4][4];
    float S[8][4], O[8][4];
    #pragma unroll
    for (int i = 0; i < 8; i++) { O[i][0]=0.f; O[i][1]=0.f; O[i][2]=0.f; O[i][3]=0.f; }
    float m_lo = -1e30f, m_hi = -1e30f, l_lo = 0.f, l_hi = 0.f;
    int qrow_lo = q0 + row0 + g, qrow_hi = qrow_lo + 8;

    for (int t = 0; t < ntile; t++) {
        if (t + 1 < ntile) asm volatile("cp.async.wait_group 1;");
        else               asm volatile("cp.async.wait_group 0;");
        __syncthreads();

        if (t == 0) {
            int lrow = row0 + (lane & 15);
            int cb = lane >> 4;
            #pragma unroll
            for (int ks = 0; ks < 4; ks++) {
                int ch = (ks * 2 + cb) ^ (lrow & 7);
                unsigned a = sb + lrow * 128 + (ch << 4);
                LDSM4(qhF[ks][0], qhF[ks][1], qhF[ks][2], qhF[ks][3], a);
                LDSM4(qlF[ks][0], qlF[ks][1], qlF[ks][2], qlF[ks][3], a + FA_QLO);
            }
        }

        bool act = causal ? (t * 64 <= lastk) : true;
        if (act) {
            unsigned kvb = sb + FA_KV + (unsigned)(t & 1) * 32768;
            #pragma unroll
            for (int i = 0; i < 8; i++) { S[i][0]=0.f; S[i][1]=0.f; S[i][2]=0.f; S[i][3]=0.f; }

            int krow = ((lane >> 4) << 3) + (lane & 7);
            int kcb = (lane >> 3) & 1;
            #pragma unroll
            for (int ks = 0; ks < 4; ks++) {
                #pragma unroll
                for (int j = 0; j < 4; j++) {
                    int kr = j * 16 + krow;
                    int ch = (ks * 2 + kcb) ^ (kr & 7);
                    unsigned ka = kvb + kr * 128 + (ch << 4);
                    unsigned bh_[4], bl_[4];
                    LDSM4(bh_[0], bh_[1], bh_[2], bh_[3], ka);
                    LDSM4(bl_[0], bl_[1], bl_[2], bl_[3], ka + 8192);
                    mma16816(S[2*j],   qhF[ks], bh_);
                    mma16816(S[2*j],   qhF[ks], bl_);
                    mma16816(S[2*j],   qlF[ks], bh_);
                    mma16816(S[2*j+1], qhF[ks], bh_ + 2);
                    mma16816(S[2*j+1], qhF[ks], bl_ + 2);
                    mma16816(S[2*j+1], qlF[ks], bh_ + 2);
                }
            }

            int tb = t * 64;
            #pragma unroll
            for (int nt = 0; nt < 8; nt++) {
                #pragma unroll
                for (int u = 0; u < 2; u++) {
                    int key = tb + nt * 8 + 2 * tig + u;
                    if (key >= KTOT) { S[nt][u] = -1e10f; S[nt][2+u] = -1e10f; }
                    else if (causal) {
                        int kp = key - Pv;
                        if (kp >= 0) {
                            if (kp > qrow_lo) S[nt][u]   = -1e10f; else S[nt][u]   += sbias[qrow_lo - kp];
                            if (kp > qrow_hi) S[nt][2+u] = -1e10f; else S[nt][2+u] += sbias[qrow_hi - kp];
                        }
                    }
                }
            }

            float tm0 = -1e30f, tm1 = -1e30f;
            #pragma unroll
            for (int nt = 0; nt < 8; nt++) {
                tm0 = fmaxf(tm0, fmaxf(S[nt][0], S[nt][1]));
                tm1 = fmaxf(tm1, fmaxf(S[nt][2], S[nt][3]));
            }
            tm0 = fmaxf(tm0, __shfl_xor_sync(0xffffffffu, tm0, 1));
            tm0 = fmaxf(tm0, __shfl_xor_sync(0xffffffffu, tm0, 2));
            tm1 = fmaxf(tm1, __shfl_xor_sync(0xffffffffu, tm1, 1));
            tm1 = fmaxf(tm1, __shfl_xor_sync(0xffffffffu, tm1, 2));
            float mn0 = fmaxf(m_lo, tm0), mn1 = fmaxf(m_hi, tm1);
            float c0 = __expf(m_lo - mn0), c1 = __expf(m_hi - mn1);
            m_lo = mn0; m_hi = mn1;
            float s0 = 0.f, s1 = 0.f;
            #pragma unroll
            for (int nt = 0; nt < 8; nt++) {
                S[nt][0] = __expf(S[nt][0] - mn0); s0 += S[nt][0];
                S[nt][1] = __expf(S[nt][1] - mn0); s0 += S[nt][1];
                S[nt][2] = __expf(S[nt][2] - mn1); s1 += S[nt][2];
                S[nt][3] = __expf(S[nt][3] - mn1); s1 += S[nt][3];
            }
            s0 += __shfl_xor_sync(0xffffffffu, s0, 1);
            s0 += __shfl_xor_sync(0xffffffffu, s0, 2);
            s1 += __shfl_xor_sync(0xffffffffu, s1, 1);
            s1 += __shfl_xor_sync(0xffffffffu, s1, 2);
            l_lo = l_lo * c0 + s0; l_hi = l_hi * c1 + s1;
            #pragma unroll
            for (int nt = 0; nt < 8; nt++) {
                O[nt][0] *= c0; O[nt][1] *= c0; O[nt][2] *= c1; O[nt][3] *= c1;
            }

            int vrow = ((lane >> 3) & 1) * 8 + (lane & 7);
            int vcb = lane >> 4;
            #pragma unroll
            for (int ks = 0; ks < 4; ks++) {
                unsigned pah[4], pal[4];
                split2(S[2*ks][0],   S[2*ks][1],   pah[0], pal[0]);
                split2(S[2*ks][2],   S[2*ks][3],   pah[1], pal[1]);
                split2(S[2*ks+1][0], S[2*ks+1][1], pah[2], pal[2]);
                split2(S[2*ks+1][2], S[2*ks+1][3], pah[3], pal[3]);
                int vr = ks * 16 + vrow;
                #pragma unroll
                for (int j = 0; j < 4; j++) {
                    int ch = (2*j + vcb) ^ (vr & 7);
                    unsigned va = kvb + 16384 + vr * 128 + (ch << 4);
                    unsigned bh_[4], bl_[4];
                    LDSM4T(bh_[0], bh_[1], bh_[2], bh_[3], va);
                    LDSM4T(bl_[0], bl_[1], bl_[2], bl_[3], va + 8192);
                    mma16816(O[2*j],   pah, bh_);
                    mma16816(O[2*j],   pah, bl_);
                    mma16816(O[2*j],   pal, bh_);
                    mma16816(O[2*j+1], pah, bh_ + 2);
                    mma16816(O[2*j+1], pah, bl_ + 2);
                    mma16816(O[2*j+1], pal, bh_ + 2);
                }
            }
        }
        __syncthreads();
        if (t + 2 < ntile) FA_STAGE(t + 2, t & 1);
    }
#undef FA_STAGE

    float inv0 = 1.f / l_lo, inv1 = 1.f / l_hi;
    size_t base_lo = ((size_t)(b * Lv + qrow_lo) * Hv + h) * HDv + 2 * tig;
    size_t base_hi = ((size_t)(b * Lv + qrow_hi) * Hv + h) * HDv + 2 * tig;
    #pragma unroll
    for (int nt = 0; nt < 8; nt++) {
        unsigned h01, l01, h23, l23;
        split2(O[nt][0] * inv0, O[nt][1] * inv0, h01, l01);
        split2(O[nt][2] * inv1, O[nt][3] * inv1, h23, l23);
        *(unsigned*)&obh[base_lo + nt * 8] = h01;
        *(unsigned*)&obl[base_lo + nt * 8] = l01;
        *(unsigned*)&obh[base_hi + nt * 8] = h23;
        *(unsigned*)&obl[base_hi + nt * 8] = l23;
    }
}

// ---------------- per-example adapter -----------------------------------------
__global__ __launch_bounds__(64) void adapter_down(
    const float* __restrict__ lz, const float* __restrict__ wd,
    const float* __restrict__ bd, float* __restrict__ az)
{
    int b = blockIdx.y, l = blockIdx.x, a = threadIdx.x;
    const float* xr = lz + (size_t)(b * Lv + l) * Dv;
    const float* wb = wd + (size_t)b * Dv * Av;
    float s = 0.f;
    #pragma unroll 4
    for (int dd = 0; dd < Dv; dd++) s += xr[dd] * wb[dd * Av + a];
    s += bd[b * Av + a];
    az[(size_t)(b * Lv + l) * Av + a] = gelu_f(s);
}

__global__ __launch_bounds__(256) void adapter_up(
    const float* __restrict__ az, const float* __restrict__ wu,
    const float* __restrict__ bu, float* __restrict__ out)
{
    int b = blockIdx.y, l = blockIdx.x;
    __shared__ float ash[Av];
    int tid = threadIdx.x;
    if (tid < Av) ash[tid] = az[(size_t)(b * Lv + l) * Av + tid];
    __syncthreads();
    const float* wb = wu + (size_t)b * Av * Dv;
    size_t o = (size_t)(b * Lv + l) * Dv;
    for (int dd = tid; dd < Dv; dd += 256) {
        float s = bu[b * Dv + dd];
        #pragma unroll 8
        for (int a = 0; a < Av; a++) s += ash[a] * wb[a * Dv + dd];
        out[o + dd] += s;
    }
}

// ---------------- driver -------------------------------------------------------
extern "C" void kernel_launch(void* const* d_in, const int* in_sizes, int n_in,
                              void* d_out, int out_size)
{
    const float* inputs  = (const float*)d_in[0];
    const float* encoded = (const float*)d_in[1];
    const float* awd     = (const float*)d_in[2];
    const float* awu     = (const float*)d_in[3];
    const float* abd     = (const float*)d_in[4];
    const float* abu     = (const float*)d_in[5];
    const float* pk      = (const float*)d_in[6];
    const float* pvv     = (const float*)d_in[7];
    const float* ln1     = (const float*)d_in[8];
    const float* ln2     = (const float*)d_in[9];
    const float* ln3     = (const float*)d_in[10];
    const float* sa_wq   = (const float*)d_in[11];
    const float* sa_wk   = (const float*)d_in[12];
    const float* sa_wv   = (const float*)d_in[13];
    const float* sa_wo   = (const float*)d_in[14];
    const float* ca_wq   = (const float*)d_in[15];
    const float* ca_wk   = (const float*)d_in[16];
    const float* ca_wv   = (const float*)d_in[17];
    const float* ca_wo   = (const float*)d_in[18];
    const float* relpos  = (const float*)d_in[19];
    const float* wi0     = (const float*)d_in[20];
    const float* wi1     = (const float*)d_in[21];
    const float* wo_mlp  = (const float*)d_in[22];
    float* out = (float*)d_out;

    float *xn, *x, *y, *h0, *az, *bias;
    __nv_bfloat16 *xnh, *xnl, *ench, *encl, *atth, *attl, *h1h, *h1l, *wth, *wtl;
    __nv_bfloat16 *qkvh, *qkvl, *cqh, *cql, *pkh, *pkl, *pvh, *pvl;
    cudaGetSymbolAddress((void**)&xn,   g_xn);
    cudaGetSymbolAddress((void**)&xnh,  g_xnh);
    cudaGetSymbolAddress((void**)&xnl,  g_xnl);
    cudaGetSymbolAddress((void**)&ench, g_ench);
    cudaGetSymbolAddress((void**)&encl, g_encl);
    cudaGetSymbolAddress((void**)&atth, g_atth);
    cudaGetSymbolAddress((void**)&attl, g_attl);
    cudaGetSymbolAddress((void**)&qkvh, g_qkvh);
    cudaGetSymbolAddress((void**)&qkvl, g_qkvl);
    cudaGetSymbolAddress((void**)&cqh,  g_cqh);
    cudaGetSymbolAddress((void**)&cql,  g_cql);
    cudaGetSymbolAddress((void**)&pkh,  g_pkh);
    cudaGetSymbolAddress((void**)&pkl,  g_pkl);
    cudaGetSymbolAddress((void**)&pvh,  g_pvh);
    cudaGetSymbolAddress((void**)&pvl,  g_pvl);
    cudaGetSymbolAddress((void**)&bias, g_bias);
    cudaGetSymbolAddress((void**)&x,    g_x);
    cudaGetSymbolAddress((void**)&y,    g_y);
    cudaGetSymbolAddress((void**)&h0,   g_h0);
    cudaGetSymbolAddress((void**)&h1h,  g_h1h);
    cudaGetSymbolAddress((void**)&h1l,  g_h1l);
    cudaGetSymbolAddress((void**)&az,   g_az);
    cudaGetSymbolAddress((void**)&wth,  g_wth);
    cudaGetSymbolAddress((void**)&wtl,  g_wtl);

    cudaFuncSetAttribute(fattn_kernel, cudaFuncAttributeMaxDynamicSharedMemorySize, FA_SMEM);
    cudaFuncSetAttribute(tgemm_kernel, cudaFuncAttributeMaxDynamicSharedMemorySize, TG_SMEM);

    const int M = Bv * Lv;
    dim3 g8(8, 32), g16(16, 32), g22(22, 32), g24(24, 32);
    dim3 ga(Lv / BQ, Bv * Hv);
    dim3 tsq(32, 32), tswi(88, 32), tswo(32, 88);

    // qs=0.125 folded exactly into Q weight split (power of two)
    // Order chosen so launch #6 (ncu -s 5 -c 1) is the fused QKV tgemm.
    rmsnorm_kernel<<<M, 256>>>(inputs, ln1, nullptr, xnh, xnl);            // 1
    tsplit_kernel<<<tsq, 256>>>(sa_wq, wth + O_SAWQ, wtl + O_SAWQ, 1024, 1024, 0.125f); // 2
    tsplit_kernel<<<tsq, 256>>>(sa_wk, wth + O_SAWK, wtl + O_SAWK, 1024, 1024, 1.f);    // 3
    tsplit_kernel<<<tsq, 256>>>(sa_wv, wth + O_SAWV, wtl + O_SAWV, 1024, 1024, 1.f);    // 4
    bias_build<<<dim3(Hv, 4), 256>>>(relpos, bias);                        // 5
    tgemm_kernel<<<g24, 256, TG_SMEM>>>(xnh, xnl, wth + O_SAWQ, wtl + O_SAWQ,
                                        nullptr, qkvh, qkvl, M, 3072, 1024, nullptr, nullptr); // 6 (profiled)
    split_kernel<<<(PFXN / 4 + 255) / 256, 256>>>(pk,  pkh, pkl, PFXN / 4);
    split_kernel<<<(PFXN / 4 + 255) / 256, 256>>>(pvv, pvh, pvl, PFXN / 4);
    fattn_kernel<<<ga, 256, FA_SMEM>>>(qkvh, qkvl, qkvh + 1024, qkvl + 1024,
                                       qkvh + 2048, qkvl + 2048, 3072, 3072,
                                       pkh, pkl, pvh, pvl, bias, atth, attl, 0, 1);
    tsplit_kernel<<<tsq, 256>>>(sa_wo, wth + O_SAWO, wtl + O_SAWO, 1024, 1024, 1.f);
    tgemm_kernel<<<g8, 256, TG_SMEM>>>(atth, attl, wth + O_SAWO, wtl + O_SAWO,
                                       x, nullptr, nullptr, M, 1024, 1024, inputs, nullptr);

    // ---- cross-attention block ----
    rmsnorm_kernel<<<M, 256>>>(x, ln2, nullptr, xnh, xnl);
    tsplit_kernel<<<tsq, 256>>>(ca_wq, wth + O_CAWQ, wtl + O_CAWQ, 1024, 1024, 0.125f);
    tgemm_kernel<<<g8, 256, TG_SMEM>>>(xnh, xnl, wth + O_CAWQ, wtl + O_CAWQ,
                                       nullptr, cqh, cql, M, 1024, 1024, nullptr, nullptr);
    split_kernel<<<(M * Dv / 4 + 255) / 256, 256>>>(encoded, ench, encl, M * Dv / 4);
    tsplit_kernel<<<tsq, 256>>>(ca_wk, wth + O_CAWK, wtl + O_CAWK, 1024, 1024, 1.f);
    tsplit_kernel<<<tsq, 256>>>(ca_wv, wth + O_CAWV, wtl + O_CAWV, 1024, 1024, 1.f);
    tgemm_kernel<<<g16, 256, TG_SMEM>>>(ench, encl, wth + O_CAWK, wtl + O_CAWK,
                                        nullptr, qkvh, qkvl, M, 2048, 1024, nullptr, nullptr);
    fattn_kernel<<<ga, 256, FA_SMEM>>>(cqh, cql, qkvh, qkvl,
                                       qkvh + 1024, qkvl + 1024, 1024, 2048,
                                       pkh, pkl, pvh, pvl, bias, atth, attl, 1, 0);
    tsplit_kernel<<<tsq, 256>>>(ca_wo, wth + O_CAWO, wtl + O_CAWO, 1024, 1024, 1.f);
    tgemm_kernel<<<g8, 256, TG_SMEM>>>(atth, attl, wth + O_CAWO, wtl + O_CAWO,
                                       y, nullptr, nullptr, M, 1024, 1024, x, nullptr);

    // ---- MLP + adapter ----
    rmsnorm_kernel<<<M, 256>>>(y, ln3, xn, xnh, xnl);
    tsplit_kernel<<<tswi, 256>>>(wi0, wth + O_WI0, wtl + O_WI0, 1024, 2816, 1.f);
    tsplit_kernel<<<tswi, 256>>>(wi1, wth + O_WI1, wtl + O_WI1, 1024, 2816, 1.f);
    tgemm_kernel<<<g22, 256, TG_SMEM>>>(xnh, xnl, wth + O_WI0, wtl + O_WI0,
                                        h0, nullptr, nullptr, M, Fv, 1024, nullptr, nullptr);
    tgemm_kernel<<<g22, 256, TG_SMEM>>>(xnh, xnl, wth + O_WI1, wtl + O_WI1,
                                        nullptr, h1h, h1l, M, Fv, 1024, nullptr, h0);
    tsplit_kernel<<<tswo, 256>>>(wo_mlp, wth + O_WO, wtl + O_WO, 2816, 1024, 1.f);
    tgemm_kernel<<<g8, 256, TG_SMEM>>>(h1h, h1l, wth + O_WO, wtl + O_WO,
                                       out, nullptr, nullptr, M, 1024, Fv, y, nullptr);
    adapter_down<<<dim3(Lv, Bv), 64>>>(xn, awd, abd, az);
    adapter_up<<<dim3(Lv, Bv), 256>>>(az, awu, abu, out);
}

// round 11
// speedup vs baseline: 1.9834x; 1.0165x over previous
#include <cuda_runtime.h>
#include <cuda_bf16.h>
#include <math.h>

#define Bv 4
#define Lv 1024
#define Dv 1024
#define Hv 16
#define HDv 64
#define Fv 2816
#define Av 64
#define Pv 30
#define KTOT (Pv + Lv)
#define NKT 17
#define BQ 128

#define NSQ (1024*1024)
#define NWI (1024*2816)
#define O_SAWQ ((size_t)0)
#define O_SAWK ((size_t)1*NSQ)
#define O_SAWV ((size_t)2*NSQ)
#define O_SAWO ((size_t)3*NSQ)
#define O_CAWQ ((size_t)4*NSQ)
#define O_CAWK ((size_t)5*NSQ)
#define O_CAWV ((size_t)6*NSQ)
#define O_CAWO ((size_t)7*NSQ)
#define O_WI0  ((size_t)8*NSQ)
#define O_WI1  (O_WI0 + NWI)
#define O_WO   (O_WI1 + NWI)
#define W_TOT  (O_WO + NWI)
#define PFXN   (Bv*2*Pv*Hv*HDv)

// ---------------- scratch ----------------------------------------------------
__device__ float g_xn[Bv*Lv*Dv];
__device__ __nv_bfloat16 g_xnh[Bv*Lv*Dv], g_xnl[Bv*Lv*Dv];
__device__ __nv_bfloat16 g_ench[Bv*Lv*Dv], g_encl[Bv*Lv*Dv];
__device__ __nv_bfloat16 g_atth[Bv*Lv*Dv], g_attl[Bv*Lv*Dv];
__device__ __nv_bfloat16 g_qkvh[Bv*Lv*3*Dv], g_qkvl[Bv*Lv*3*Dv];
__device__ __nv_bfloat16 g_cqh[Bv*Lv*Dv], g_cql[Bv*Lv*Dv];
__device__ __nv_bfloat16 g_pkh[PFXN], g_pkl[PFXN], g_pvh[PFXN], g_pvl[PFXN];
__device__ float g_bias[Hv*1024];
__device__ float g_x [Bv*Lv*Dv];
__device__ float g_y [Bv*Lv*Dv];
__device__ float g_h0[Bv*Lv*Fv];
__device__ __nv_bfloat16 g_h1h[Bv*Lv*Fv], g_h1l[Bv*Lv*Fv];
__device__ float g_az[Bv*Lv*Av];
__device__ __nv_bfloat16 g_wth[W_TOT], g_wtl[W_TOT];

__device__ __forceinline__ float gelu_f(float x) {
    float x3 = x * x * x;
    return 0.5f * x * (1.0f + tanhf(0.7978845608028654f * (x + 0.044715f * x3)));
}

__device__ __forceinline__ void split1(float f, __nv_bfloat16& h, __nv_bfloat16& l) {
    h = __float2bfloat16(f);
    l = __float2bfloat16(f - __bfloat162float(h));
}

__device__ __forceinline__ void split2(float f0, float f1, unsigned &hi, unsigned &lo) {
    __nv_bfloat162 h = __floats2bfloat162_rn(f0, f1);
    float r0 = f0 - __bfloat162float(h.x);
    float r1 = f1 - __bfloat162float(h.y);
    __nv_bfloat162 l = __floats2bfloat162_rn(r0, r1);
    hi = *reinterpret_cast<unsigned*>(&h);
    lo = *reinterpret_cast<unsigned*>(&l);
}

__device__ __forceinline__ void mma16816(float* c, const unsigned* a, const unsigned* b) {
    asm volatile(
        "mma.sync.aligned.m16n8k16.row.col.f32.bf16.bf16.f32 "
        "{%0,%1,%2,%3}, {%4,%5,%6,%7}, {%8,%9}, {%0,%1,%2,%3};\n"
        : "+f"(c[0]), "+f"(c[1]), "+f"(c[2]), "+f"(c[3])
        : "r"(a[0]), "r"(a[1]), "r"(a[2]), "r"(a[3]), "r"(b[0]), "r"(b[1]));
}

#define LDSM4(r0,r1,r2,r3,a) \
    asm volatile("ldmatrix.sync.aligned.m8n8.x4.shared.b16 {%0,%1,%2,%3}, [%4];" \
        : "=r"(r0),"=r"(r1),"=r"(r2),"=r"(r3) : "r"(a))
#define LDSM4T(r0,r1,r2,r3,a) \
    asm volatile("ldmatrix.sync.aligned.m8n8.x4.trans.shared.b16 {%0,%1,%2,%3}, [%4];" \
        : "=r"(r0),"=r"(r1),"=r"(r2),"=r"(r3) : "r"(a))
#define CPA16(dst, src) \
    asm volatile("cp.async.cg.shared.global [%0], [%1], 16;" :: "r"(dst), "l"(src))
#define CPA16Z(dst, src) \
    asm volatile("cp.async.cg.shared.global [%0], [%1], 16, 0;" :: "r"(dst), "l"(src))

// ---------------- conversions -------------------------------------------------
__global__ __launch_bounds__(256) void split_kernel(
    const float* __restrict__ in, __nv_bfloat16* __restrict__ hi,
    __nv_bfloat16* __restrict__ lo, int n4)
{
    int i = blockIdx.x * 256 + threadIdx.x;
    if (i >= n4) return;
    float4 v = *(const float4*)&in[(size_t)i * 4];
    __nv_bfloat16 h[4], l[4];
    split1(v.x, h[0], l[0]); split1(v.y, h[1], l[1]);
    split1(v.z, h[2], l[2]); split1(v.w, h[3], l[3]);
    *(uint2*)&hi[(size_t)i * 4] = *(uint2*)h;
    *(uint2*)&lo[(size_t)i * 4] = *(uint2*)l;
}

__global__ __launch_bounds__(256) void tsplit_kernel(
    const float* __restrict__ W, __nv_bfloat16* __restrict__ th,
    __nv_bfloat16* __restrict__ tl, int K, int N, float scale)
{
    __shared__ float tile[32][33];
    int n0 = blockIdx.x * 32, k0 = blockIdx.y * 32;
    int tx = threadIdx.x & 31, ty = threadIdx.x >> 5;
    #pragma unroll
    for (int j = 0; j < 4; j++)
        tile[ty + 8*j][tx] = W[(size_t)(k0 + ty + 8*j) * N + n0 + tx];
    __syncthreads();
    #pragma unroll
    for (int j = 0; j < 4; j++) {
        float v = tile[tx][ty + 8*j] * scale;
        __nv_bfloat16 h, l;
        split1(v, h, l);
        size_t idx = (size_t)(n0 + ty + 8*j) * K + k0 + tx;
        th[idx] = h; tl[idx] = l;
    }
}

__global__ __launch_bounds__(256) void bias_build(
    const float* __restrict__ relpos, float* __restrict__ tab)
{
    int h = blockIdx.x;
    int r = blockIdx.y * 256 + threadIdx.x;
    int bkt;
    if (r < 16) bkt = r;
    else {
        bkt = 16 + (int)(logf((float)r * 0.0625f) * (16.0f / 2.0794415416798357f));
        if (bkt > 31) bkt = 31;
    }
    tab[h * 1024 + r] = relpos[h * 32 + bkt];
}

// ---------------- RMSNorm -----------------------------------------------------
__global__ __launch_bounds__(256) void rmsnorm_kernel(
    const float* __restrict__ x, const float* __restrict__ w,
    float* __restrict__ of32, __nv_bfloat16* __restrict__ ohi,
    __nv_bfloat16* __restrict__ olo)
{
    int row = blockIdx.x;
    const float* xr = x + (size_t)row * Dv;
    int tid = threadIdx.x;
    int d0 = tid * 4;
    float4 v = *(const float4*)&xr[d0];
    float s = v.x*v.x + v.y*v.y + v.z*v.z + v.w*v.w;
    #pragma unroll
    for (int off = 16; off; off >>= 1) s += __shfl_xor_sync(0xffffffffu, s, off);
    __shared__ float red[8];
    __shared__ float inv_s;
    if ((tid & 31) == 0) red[tid >> 5] = s;
    __syncthreads();
    if (tid == 0) {
        float t = 0.f;
        #pragma unroll
        for (int i = 0; i < 8; i++) t += red[i];
        inv_s = rsqrtf(t * (1.0f / Dv) + 1e-6f);
    }
    __syncthreads();
    float inv = inv_s;
    float4 wv = *(const float4*)&w[d0];
    float r[4];
    r[0] = v.x*inv*wv.x; r[1] = v.y*inv*wv.y; r[2] = v.z*inv*wv.z; r[3] = v.w*inv*wv.w;
    size_t o = (size_t)row * Dv + d0;
    if (of32) { float4 rr; rr.x=r[0]; rr.y=r[1]; rr.z=r[2]; rr.w=r[3]; *(float4*)&of32[o] = rr; }
    __nv_bfloat16 h[4], l[4];
    #pragma unroll
    for (int i = 0; i < 4; i++) split1(r[i], h[i], l[i]);
    *(uint2*)&ohi[o] = *(uint2*)h;
    *(uint2*)&olo[o] = *(uint2*)l;
}

// ---------------- tensor-core GEMM, 3-stage cp.async, 1 sync/tile ------------
#define TG_SEG 4096
#define TG_BUF (4*TG_SEG)
#define TG_SMEM (3*TG_BUF*2)      /* 96 KB */

__device__ __forceinline__ unsigned sw_elem(int row, int c) {
    return (unsigned)(row * 32 + ((c ^ ((row >> 1) & 3)) << 3));
}

__global__ __launch_bounds__(256, 2) void tgemm_kernel(
    const __nv_bfloat16* __restrict__ Ahi, const __nv_bfloat16* __restrict__ Alo,
    const __nv_bfloat16* __restrict__ Bh,  const __nv_bfloat16* __restrict__ Bl,
    float* __restrict__ Cf, __nv_bfloat16* __restrict__ Chi, __nv_bfloat16* __restrict__ Clo,
    int M, int N, int K,
    const float* __restrict__ res, const float* __restrict__ gate)
{
    extern __shared__ __align__(16) __nv_bfloat16 tgsm[];
    unsigned sbase = (unsigned)__cvta_generic_to_shared(tgsm);

    int tid  = threadIdx.x;
    int m0   = blockIdx.y * 128;
    int n0   = blockIdx.x * 128;
    int wid  = tid >> 5, lane = tid & 31;
    int g    = lane >> 2, tig = lane & 3;
    int l7   = lane & 7, sub = lane >> 3;
    int wm   = (wid & 1) * 64;
    int wn   = (wid >> 1) * 32;

    float acc[4][4][4];
    #pragma unroll
    for (int i = 0; i < 4; i++)
        #pragma unroll
        for (int j = 0; j < 4; j++)
            #pragma unroll
            for (int r = 0; r < 4; r++) acc[i][j][r] = 0.f;

#define TG_ISSUE(tt, bufb) do {                                                  \
    size_t k0i = (size_t)(tt) * 32;                                              \
    unsigned base = sbase + (unsigned)(bufb) * (TG_BUF * 2);                     \
    _Pragma("unroll")                                                            \
    for (int i_ = 0; i_ < 2; i_++) {                                             \
        int cc = tid + i_ * 256; int row = cc >> 2; int c4 = cc & 3;             \
        unsigned so = sw_elem(row, c4) * 2;                                      \
        size_t ga = (size_t)(m0 + row) * K + k0i + c4 * 8;                       \
        size_t gb = (size_t)(n0 + row) * K + k0i + c4 * 8;                       \
        CPA16(base + so,                 Ahi + ga);                              \
        CPA16(base + TG_SEG*2 + so,      Alo + ga);                              \
        CPA16(base + 2*TG_SEG*2 + so,    Bh + gb);                               \
        CPA16(base + 3*TG_SEG*2 + so,    Bl + gb);                               \
    }                                                                            \
    asm volatile("cp.async.commit_group;");                                      \
} while (0)

    int nk = K >> 5;
    TG_ISSUE(0, 0);
    if (nk > 1) TG_ISSUE(1, 1);

    int buf = 0;
    for (int t = 0; t < nk; t++) {
        if (t + 1 < nk) asm volatile("cp.async.wait_group 1;");
        else            asm volatile("cp.async.wait_group 0;");
        __syncthreads();

        if (t + 2 < nk) {
            int nb = buf + 2; if (nb >= 3) nb -= 3;
            TG_ISSUE(t + 2, nb);
        }

        unsigned bufo = sbase + (unsigned)buf * (TG_BUF * 2);
        #pragma unroll
        for (int ks = 0; ks < 2; ks++) {
            unsigned bh_[8], bl_[8];
            #pragma unroll
            for (int p = 0; p < 2; p++) {
                int nrow = wn + p * 16 + ((sub >> 1) << 3) + l7;
                int cB = ks * 2 + (sub & 1);
                unsigned ab = bufo + 2 * TG_SEG * 2 + sw_elem(nrow, cB) * 2;
                LDSM4(bh_[4*p+0], bh_[4*p+1], bh_[4*p+2], bh_[4*p+3], ab);
                LDSM4(bl_[4*p+0], bl_[4*p+1], bl_[4*p+2], bl_[4*p+3], ab + TG_SEG * 2);
            }
            #pragma unroll
            for (int mt = 0; mt < 4; mt++) {
                int arow = wm + mt * 16 + ((sub & 1) << 3) + l7;
                int cA = ks * 2 + (sub >> 1);
                unsigned aa = bufo + sw_elem(arow, cA) * 2;
                unsigned ah[4], al[4];
                LDSM4(ah[0], ah[1], ah[2], ah[3], aa);
                LDSM4(al[0], al[1], al[2], al[3], aa + TG_SEG * 2);
                // term-major order: consecutive MMAs hit different accumulators
                // (RAW distance 4 instead of 1); per-acc order hh,hl,lh preserved.
                #pragma unroll
                for (int nt = 0; nt < 4; nt++)
                    mma16816(acc[mt][nt], ah, &bh_[nt * 2]);
                #pragma unroll
                for (int nt = 0; nt < 4; nt++)
                    mma16816(acc[mt][nt], ah, &bl_[nt * 2]);
                #pragma unroll
                for (int nt = 0; nt < 4; nt++)
                    mma16816(acc[mt][nt], al, &bh_[nt * 2]);
            }
        }
        if (++buf == 3) buf = 0;
    }
#undef TG_ISSUE

    #pragma unroll
    for (int mt = 0; mt < 4; mt++) {
        #pragma unroll
        for (int half = 0; half < 2; half++) {
            int m = m0 + wm + mt * 16 + g + half * 8;
            #pragma unroll
            for (int nt = 0; nt < 4; nt++) {
                int n = n0 + wn + nt * 8 + 2 * tig;
                size_t idx = (size_t)m * N + n;
                float v0 = acc[mt][nt][half * 2 + 0];
                float v1 = acc[mt][nt][half * 2 + 1];
                if (res) {
                    float2 rv = *(const float2*)&res[idx];
                    v0 += rv.x; v1 += rv.y;
                }
                if (gate) {
                    float2 gv = *(const float2*)&gate[idx];
                    v0 *= gelu_f(gv.x); v1 *= gelu_f(gv.y);
                }
                if (Cf) {
                    float2 o; o.x = v0; o.y = v1;
                    *(float2*)&Cf[idx] = o;
                } else {
                    unsigned hh, ll;
                    split2(v0, v1, hh, ll);
                    *(unsigned*)&Chi[idx] = hh;
                    *(unsigned*)&Clo[idx] = ll;
                }
            }
        }
    }
}

// ---------------- MMA flash attention (strided q/kv for fused layouts) --------
#define FA_QLO 16384
#define FA_KV  32768
#define FA_BIAS 98304
#define FA_SMEM 102400

__global__ __launch_bounds__(256) void fattn_kernel(
    const __nv_bfloat16* __restrict__ qh, const __nv_bfloat16* __restrict__ qlo_,
    const __nv_bfloat16* __restrict__ kh, const __nv_bfloat16* __restrict__ kl,
    const __nv_bfloat16* __restrict__ vh, const __nv_bfloat16* __restrict__ vl,
    int qstride, int kvstride,
    const __nv_bfloat16* __restrict__ pkh, const __nv_bfloat16* __restrict__ pkl,
    const __nv_bfloat16* __restrict__ pvh, const __nv_bfloat16* __restrict__ pvl,
    const float* __restrict__ biasTab,
    __nv_bfloat16* __restrict__ obh, __nv_bfloat16* __restrict__ obl,
    int sel, int causal)
{
    extern __shared__ __align__(16) char fsm[];
    unsigned sb = (unsigned)__cvta_generic_to_shared(fsm);
    const float* sbias = (const float*)(fsm + FA_BIAS);
    int tid = threadIdx.x, wid = tid >> 5, lane = tid & 31;
    int g = lane >> 2, tig = lane & 3;
    int bhid = blockIdx.y; int b = bhid >> 4, h = bhid & 15;
    int q0 = blockIdx.x * BQ;
    int row0 = wid * 16;

    int ntile = causal ? ((Pv + q0 + BQ + 63) >> 6) : NKT;
    int lastk = Pv + q0 + row0 + 15;

    const __nv_bfloat16* msrc[4] = {kh, kl, vh, vl};
    const __nv_bfloat16* psrc[4] = {pkh, pkl, pvh, pvl};
    int rk = tid >> 3, ck = tid & 7;

    #pragma unroll
    for (int i = 0; i < 8; i++) {
        int arr = i >> 2;
        int r = rk + (i & 3) * 32;
        unsigned dst = sb + (arr ? FA_QLO : 0) + r * 128 + (((ck ^ (r & 7))) << 4);
        const __nv_bfloat16* src = (arr ? qlo_ : qh) +
            ((size_t)(b * Lv + q0 + r) * qstride + h * HDv + ck * 8);
        CPA16(dst, src);
    }
    if (causal) CPA16(sb + FA_BIAS + tid * 16, biasTab + h * 1024 + tid * 4);

#define FA_STAGE(t, bufb) do {                                                   \
    int tb_ = (t) * 64;                                                          \
    _Pragma("unroll")                                                            \
    for (int a_ = 0; a_ < 4; a_++) {                                             \
        _Pragma("unroll")                                                        \
        for (int i2 = 0; i2 < 2; i2++) {                                         \
            int r = rk + i2 * 32;                                                \
            unsigned dst = sb + FA_KV + (unsigned)(bufb) * 32768 + a_ * 8192     \
                           + r * 128 + ((ck ^ (r & 7)) << 4);                    \
            int gk = tb_ + r;                                                    \
            const __nv_bfloat16* src;                                            \
            if (gk < Pv)                                                         \
                src = psrc[a_] + ((((size_t)(b * 2 + sel) * Pv + gk) * Hv + h) * HDv + ck * 8); \
            else                                                                 \
                src = msrc[a_] + ((size_t)(b * Lv + (gk < KTOT ? gk - Pv : 0)) * kvstride + h * HDv + ck * 8); \
            if (gk < KTOT) { CPA16(dst, src); } else { CPA16Z(dst, src); }       \
        }                                                                        \
    }                                                                            \
    asm volatile("cp.async.commit_group;");                                      \
} while (0)

    FA_STAGE(0, 0);
    if (ntile > 1) FA_STAGE(1, 1);

    unsigned qhF[4][4], qlF[4][4];
    float S[8][4], O[8][4];
    #pragma unroll
    for (int i = 0; i < 8; i++) { O[i][0]=0.f; O[i][1]=0.f; O[i][2]=0.f; O[i][3]=0.f; }
    float m_lo = -1e30f, m_hi = -1e30f, l_lo = 0.f, l_hi = 0.f;
    int qrow_lo = q0 + row0 + g, qrow_hi = qrow_lo + 8;

    for (int t = 0; t < ntile; t++) {
        if (t + 1 < ntile) asm volatile("cp.async.wait_group 1;");
        else               asm volatile("cp.async.wait_group 0;");
        __syncthreads();

        if (t == 0) {
            int lrow = row0 + (lane & 15);
            int cb = lane >> 4;
            #pragma unroll
            for (int ks = 0; ks < 4; ks++) {
                int ch = (ks * 2 + cb) ^ (lrow & 7);
                unsigned a = sb + lrow * 128 + (ch << 4);
                LDSM4(qhF[ks][0], qhF[ks][1], qhF[ks][2], qhF[ks][3], a);
                LDSM4(qlF[ks][0], qlF[ks][1], qlF[ks][2], qlF[ks][3], a + FA_QLO);
            }
        }

        bool act = causal ? (t * 64 <= lastk) : true;
        if (act) {
            unsigned kvb = sb + FA_KV + (unsigned)(t & 1) * 32768;
            #pragma unroll
            for (int i = 0; i < 8; i++) { S[i][0]=0.f; S[i][1]=0.f; S[i][2]=0.f; S[i][3]=0.f; }

            int krow = ((lane >> 4) << 3) + (lane & 7);
            int kcb = (lane >> 3) & 1;
            #pragma unroll
            for (int ks = 0; ks < 4; ks++) {
                #pragma unroll
                for (int j = 0; j < 4; j++) {
                    int kr = j * 16 + krow;
                    int ch = (ks * 2 + kcb) ^ (kr & 7);
                    unsigned ka = kvb + kr * 128 + (ch << 4);
                    unsigned bh_[4], bl_[4];
                    LDSM4(bh_[0], bh_[1], bh_[2], bh_[3], ka);
                    LDSM4(bl_[0], bl_[1], bl_[2], bl_[3], ka + 8192);
                    // interleave the two C-fragments: RAW distance 2
                    mma16816(S[2*j],   qhF[ks], bh_);
                    mma16816(S[2*j+1], qhF[ks], bh_ + 2);
                    mma16816(S[2*j],   qhF[ks], bl_);
                    mma16816(S[2*j+1], qhF[ks], bl_ + 2);
                    mma16816(S[2*j],   qlF[ks], bh_);
                    mma16816(S[2*j+1], qlF[ks], bh_ + 2);
                }
            }

            int tb = t * 64;
            #pragma unroll
            for (int nt = 0; nt < 8; nt++) {
                #pragma unroll
                for (int u = 0; u < 2; u++) {
                    int key = tb + nt * 8 + 2 * tig + u;
                    if (key >= KTOT) { S[nt][u] = -1e10f; S[nt][2+u] = -1e10f; }
                    else if (causal) {
                        int kp = key - Pv;
                        if (kp >= 0) {
                            if (kp > qrow_lo) S[nt][u]   = -1e10f; else S[nt][u]   += sbias[qrow_lo - kp];
                            if (kp > qrow_hi) S[nt][2+u] = -1e10f; else S[nt][2+u] += sbias[qrow_hi - kp];
                        }
                    }
                }
            }

            float tm0 = -1e30f, tm1 = -1e30f;
            #pragma unroll
            for (int nt = 0; nt < 8; nt++) {
                tm0 = fmaxf(tm0, fmaxf(S[nt][0], S[nt][1]));
                tm1 = fmaxf(tm1, fmaxf(S[nt][2], S[nt][3]));
            }
            tm0 = fmaxf(tm0, __shfl_xor_sync(0xffffffffu, tm0, 1));
            tm0 = fmaxf(tm0, __shfl_xor_sync(0xffffffffu, tm0, 2));
            tm1 = fmaxf(tm1, __shfl_xor_sync(0xffffffffu, tm1, 1));
            tm1 = fmaxf(tm1, __shfl_xor_sync(0xffffffffu, tm1, 2));
            float mn0 = fmaxf(m_lo, tm0), mn1 = fmaxf(m_hi, tm1);
            float c0 = __expf(m_lo - mn0), c1 = __expf(m_hi - mn1);
            m_lo = mn0; m_hi = mn1;
            float s0 = 0.f, s1 = 0.f;
            #pragma unroll
            for (int nt = 0; nt < 8; nt++) {
                S[nt][0] = __expf(S[nt][0] - mn0); s0 += S[nt][0];
                S[nt][1] = __expf(S[nt][1] - mn0); s0 += S[nt][1];
                S[nt][2] = __expf(S[nt][2] - mn1); s1 += S[nt][2];
                S[nt][3] = __expf(S[nt][3] - mn1); s1 += S[nt][3];
            }
            s0 += __shfl_xor_sync(0xffffffffu, s0, 1);
            s0 += __shfl_xor_sync(0xffffffffu, s0, 2);
            s1 += __shfl_xor_sync(0xffffffffu, s1, 1);
            s1 += __shfl_xor_sync(0xffffffffu, s1, 2);
            l_lo = l_lo * c0 + s0; l_hi = l_hi * c1 + s1;
            #pragma unroll
            for (int nt = 0; nt < 8; nt++) {
                O[nt][0] *= c0; O[nt][1] *= c0; O[nt][2] *= c1; O[nt][3] *= c1;
            }

            int vrow = ((lane >> 3) & 1) * 8 + (lane & 7);
            int vcb = lane >> 4;
            #pragma unroll
            for (int ks = 0; ks < 4; ks++) {
                unsigned pah[4], pal[4];
                split2(S[2*ks][0],   S[2*ks][1],   pah[0], pal[0]);
                split2(S[2*ks][2],   S[2*ks][3],   pah[1], pal[1]);
                split2(S[2*ks+1][0], S[2*ks+1][1], pah[2], pal[2]);
                split2(S[2*ks+1][2], S[2*ks+1][3], pah[3], pal[3]);
                int vr = ks * 16 + vrow;
                #pragma unroll
                for (int j = 0; j < 4; j++) {
                    int ch = (2*j + vcb) ^ (vr & 7);
                    unsigned va = kvb + 16384 + vr * 128 + (ch << 4);
                    unsigned bh_[4], bl_[4];
                    LDSM4T(bh_[0], bh_[1], bh_[2], bh_[3], va);
                    LDSM4T(bl_[0], bl_[1], bl_[2], bl_[3], va + 8192);
                    // interleave O[2j] / O[2j+1]: RAW distance 2
                    mma16816(O[2*j],   pah, bh_);
                    mma16816(O[2*j+1], pah, bh_ + 2);
                    mma16816(O[2*j],   pah, bl_);
                    mma16816(O[2*j+1], pah, bl_ + 2);
                    mma16816(O[2*j],   pal, bh_);
                    mma16816(O[2*j+1], pal, bh_ + 2);
                }
            }
        }
        __syncthreads();
        if (t + 2 < ntile) FA_STAGE(t + 2, t & 1);
    }
#undef FA_STAGE

    float inv0 = 1.f / l_lo, inv1 = 1.f / l_hi;
    size_t base_lo = ((size_t)(b * Lv + qrow_lo) * Hv + h) * HDv + 2 * tig;
    size_t base_hi = ((size_t)(b * Lv + qrow_hi) * Hv + h) * HDv + 2 * tig;
    #pragma unroll
    for (int nt = 0; nt < 8; nt++) {
        unsigned h01, l01, h23, l23;
        split2(O[nt][0] * inv0, O[nt][1] * inv0, h01, l01);
        split2(O[nt][2] * inv1, O[nt][3] * inv1, h23, l23);
        *(unsigned*)&obh[base_lo + nt * 8] = h01;
        *(unsigned*)&obl[base_lo + nt * 8] = l01;
        *(unsigned*)&obh[base_hi + nt * 8] = h23;
        *(unsigned*)&obl[base_hi + nt * 8] = l23;
    }
}

// ---------------- per-example adapter -----------------------------------------
// 256 threads: 64 a-cols x 4 k-slices; smem reduce
__global__ __launch_bounds__(256) void adapter_down(
    const float* __restrict__ lz, const float* __restrict__ wd,
    const float* __restrict__ bd, float* __restrict__ az)
{
    __shared__ float part[4][Av];
    int b = blockIdx.y, l = blockIdx.x;
    int a = threadIdx.x & 63, kg = threadIdx.x >> 6;
    const float* xr = lz + (size_t)(b * Lv + l) * Dv + kg * 256;
    const float* wb = wd + (size_t)b * Dv * Av + (size_t)kg * 256 * Av + a;
    float s = 0.f;
    #pragma unroll 8
    for (int dd = 0; dd < 256; dd++) s += xr[dd] * wb[(size_t)dd * Av];
    part[kg][a] = s;
    __syncthreads();
    if (threadIdx.x < Av) {
        float t = part[0][threadIdx.x] + part[1][threadIdx.x]
                + part[2][threadIdx.x] + part[3][threadIdx.x]
                + bd[b * Av + threadIdx.x];
        az[(size_t)(b * Lv + l) * Av + threadIdx.x] = gelu_f(t);
    }
}

__global__ __launch_bounds__(256) void adapter_up(
    const float* __restrict__ az, const float* __restrict__ wu,
    const float* __restrict__ bu, float* __restrict__ out)
{
    int b = blockIdx.y, l = blockIdx.x;
    __shared__ float ash[Av];
    int tid = threadIdx.x;
    if (tid < Av) ash[tid] = az[(size_t)(b * Lv + l) * Av + tid];
    __syncthreads();
    const float* wb = wu + (size_t)b * Av * Dv;
    size_t o = (size_t)(b * Lv + l) * Dv;
    for (int dd = tid; dd < Dv; dd += 256) {
        float s = bu[b * Dv + dd];
        #pragma unroll 8
        for (int a = 0; a < Av; a++) s += ash[a] * wb[a * Dv + dd];
        out[o + dd] += s;
    }
}

// ---------------- driver -------------------------------------------------------
extern "C" void kernel_launch(void* const* d_in, const int* in_sizes, int n_in,
                              void* d_out, int out_size)
{
    const float* inputs  = (const float*)d_in[0];
    const float* encoded = (const float*)d_in[1];
    const float* awd     = (const float*)d_in[2];
    const float* awu     = (const float*)d_in[3];
    const float* abd     = (const float*)d_in[4];
    const float* abu     = (const float*)d_in[5];
    const float* pk      = (const float*)d_in[6];
    const float* pvv     = (const float*)d_in[7];
    const float* ln1     = (const float*)d_in[8];
    const float* ln2     = (const float*)d_in[9];
    const float* ln3     = (const float*)d_in[10];
    const float* sa_wq   = (const float*)d_in[11];
    const float* sa_wk   = (const float*)d_in[12];
    const float* sa_wv   = (const float*)d_in[13];
    const float* sa_wo   = (const float*)d_in[14];
    const float* ca_wq   = (const float*)d_in[15];
    const float* ca_wk   = (const float*)d_in[16];
    const float* ca_wv   = (const float*)d_in[17];
    const float* ca_wo   = (const float*)d_in[18];
    const float* relpos  = (const float*)d_in[19];
    const float* wi0     = (const float*)d_in[20];
    const float* wi1     = (const float*)d_in[21];
    const float* wo_mlp  = (const float*)d_in[22];
    float* out = (float*)d_out;

    float *xn, *x, *y, *h0, *az, *bias;
    __nv_bfloat16 *xnh, *xnl, *ench, *encl, *atth, *attl, *h1h, *h1l, *wth, *wtl;
    __nv_bfloat16 *qkvh, *qkvl, *cqh, *cql, *pkh, *pkl, *pvh, *pvl;
    cudaGetSymbolAddress((void**)&xn,   g_xn);
    cudaGetSymbolAddress((void**)&xnh,  g_xnh);
    cudaGetSymbolAddress((void**)&xnl,  g_xnl);
    cudaGetSymbolAddress((void**)&ench, g_ench);
    cudaGetSymbolAddress((void**)&encl, g_encl);
    cudaGetSymbolAddress((void**)&atth, g_atth);
    cudaGetSymbolAddress((void**)&attl, g_attl);
    cudaGetSymbolAddress((void**)&qkvh, g_qkvh);
    cudaGetSymbolAddress((void**)&qkvl, g_qkvl);
    cudaGetSymbolAddress((void**)&cqh,  g_cqh);
    cudaGetSymbolAddress((void**)&cql,  g_cql);
    cudaGetSymbolAddress((void**)&pkh,  g_pkh);
    cudaGetSymbolAddress((void**)&pkl,  g_pkl);
    cudaGetSymbolAddress((void**)&pvh,  g_pvh);
    cudaGetSymbolAddress((void**)&pvl,  g_pvl);
    cudaGetSymbolAddress((void**)&bias, g_bias);
    cudaGetSymbolAddress((void**)&x,    g_x);
    cudaGetSymbolAddress((void**)&y,    g_y);
    cudaGetSymbolAddress((void**)&h0,   g_h0);
    cudaGetSymbolAddress((void**)&h1h,  g_h1h);
    cudaGetSymbolAddress((void**)&h1l,  g_h1l);
    cudaGetSymbolAddress((void**)&az,   g_az);
    cudaGetSymbolAddress((void**)&wth,  g_wth);
    cudaGetSymbolAddress((void**)&wtl,  g_wtl);

    cudaFuncSetAttribute(fattn_kernel, cudaFuncAttributeMaxDynamicSharedMemorySize, FA_SMEM);
    cudaFuncSetAttribute(tgemm_kernel, cudaFuncAttributeMaxDynamicSharedMemorySize, TG_SMEM);

    const int M = Bv * Lv;
    dim3 g8(8, 32), g16(16, 32), g22(22, 32), g24(24, 32);
    dim3 ga(Lv / BQ, Bv * Hv);
    dim3 tsq(32, 32), tswi(88, 32), tswo(32, 88);

    // qs=0.125 folded exactly into Q weight split (power of two)
    // Order keeps launch #6 (ncu -s 5 -c 1) = fused QKV tgemm.
    rmsnorm_kernel<<<M, 256>>>(inputs, ln1, nullptr, xnh, xnl);            // 1
    tsplit_kernel<<<tsq, 256>>>(sa_wq, wth + O_SAWQ, wtl + O_SAWQ, 1024, 1024, 0.125f); // 2
    tsplit_kernel<<<tsq, 256>>>(sa_wk, wth + O_SAWK, wtl + O_SAWK, 1024, 1024, 1.f);    // 3
    tsplit_kernel<<<tsq, 256>>>(sa_wv, wth + O_SAWV, wtl + O_SAWV, 1024, 1024, 1.f);    // 4
    bias_build<<<dim3(Hv, 4), 256>>>(relpos, bias);                        // 5
    tgemm_kernel<<<g24, 256, TG_SMEM>>>(xnh, xnl, wth + O_SAWQ, wtl + O_SAWQ,
                                        nullptr, qkvh, qkvl, M, 3072, 1024, nullptr, nullptr); // 6
    split_kernel<<<(PFXN / 4 + 255) / 256, 256>>>(pk,  pkh, pkl, PFXN / 4);
    split_kernel<<<(PFXN / 4 + 255) / 256, 256>>>(pvv, pvh, pvl, PFXN / 4);
    fattn_kernel<<<ga, 256, FA_SMEM>>>(qkvh, qkvl, qkvh + 1024, qkvl + 1024,
                                       qkvh + 2048, qkvl + 2048, 3072, 3072,
                                       pkh, pkl, pvh, pvl, bias, atth, attl, 0, 1);
    tsplit_kernel<<<tsq, 256>>>(sa_wo, wth + O_SAWO, wtl + O_SAWO, 1024, 1024, 1.f);
    tgemm_kernel<<<g8, 256, TG_SMEM>>>(atth, attl, wth + O_SAWO, wtl + O_SAWO,
                                       x, nullptr, nullptr, M, 1024, 1024, inputs, nullptr);

    // ---- cross-attention block ----
    rmsnorm_kernel<<<M, 256>>>(x, ln2, nullptr, xnh, xnl);
    tsplit_kernel<<<tsq, 256>>>(ca_wq, wth + O_CAWQ, wtl + O_CAWQ, 1024, 1024, 0.125f);
    tgemm_kernel<<<g8, 256, TG_SMEM>>>(xnh, xnl, wth + O_CAWQ, wtl + O_CAWQ,
                                       nullptr, cqh, cql, M, 1024, 1024, nullptr, nullptr);
    split_kernel<<<(M * Dv / 4 + 255) / 256, 256>>>(encoded, ench, encl, M * Dv / 4);
    tsplit_kernel<<<tsq, 256>>>(ca_wk, wth + O_CAWK, wtl + O_CAWK, 1024, 1024, 1.f);
    tsplit_kernel<<<tsq, 256>>>(ca_wv, wth + O_CAWV, wtl + O_CAWV, 1024, 1024, 1.f);
    tgemm_kernel<<<g16, 256, TG_SMEM>>>(ench, encl, wth + O_CAWK, wtl + O_CAWK,
                                        nullptr, qkvh, qkvl, M, 2048, 1024, nullptr, nullptr);
    fattn_kernel<<<ga, 256, FA_SMEM>>>(cqh, cql, qkvh, qkvl,
                                       qkvh + 1024, qkvl + 1024, 1024, 2048,
                                       pkh, pkl, pvh, pvl, bias, atth, attl, 1, 0);
    tsplit_kernel<<<tsq, 256>>>(ca_wo, wth + O_CAWO, wtl + O_CAWO, 1024, 1024, 1.f);
    tgemm_kernel<<<g8, 256, TG_SMEM>>>(atth, attl, wth + O_CAWO, wtl + O_CAWO,
                                       y, nullptr, nullptr, M, 1024, 1024, x, nullptr);

    // ---- MLP + adapter ----
    rmsnorm_kernel<<<M, 256>>>(y, ln3, xn, xnh, xnl);
    tsplit_kernel<<<tswi, 256>>>(wi0, wth + O_WI0, wtl + O_WI0, 1024, 2816, 1.f);
    tsplit_kernel<<<tswi, 256>>>(wi1, wth + O_WI1, wtl + O_WI1, 1024, 2816, 1.f);
    tgemm_kernel<<<g22, 256, TG_SMEM>>>(xnh, xnl, wth + O_WI0, wtl + O_WI0,
                                        h0, nullptr, nullptr, M, Fv, 1024, nullptr, nullptr);
    tgemm_kernel<<<g22, 256, TG_SMEM>>>(xnh, xnl, wth + O_WI1, wtl + O_WI1,
                                        nullptr, h1h, h1l, M, Fv, 1024, nullptr, h0);
    tsplit_kernel<<<tswo, 256>>>(wo_mlp, wth + O_WO, wtl + O_WO, 2816, 1024, 1.f);
    tgemm_kernel<<<g8, 256, TG_SMEM>>>(h1h, h1l, wth + O_WO, wtl + O_WO,
                                       out, nullptr, nullptr, M, 1024, Fv, y, nullptr);
    adapter_down<<<dim3(Lv, Bv), 256>>>(xn, awd, abd, az);
    adapter_up<<<dim3(Lv, Bv), 256>>>(az, awu, abu, out);
}

// round 15
// speedup vs baseline: 2.1227x; 1.0702x over previous
#include <cuda_runtime.h>
#include <cuda_bf16.h>
#include <math.h>

#define Bv 4
#define Lv 1024
#define Dv 1024
#define Hv 16
#define HDv 64
#define Fv 2816
#define Av 64
#define Pv 30
#define KTOT (Pv + Lv)
#define NKT 17
#define BQ 128

#define NSQ (1024*1024)
#define NWI (1024*2816)
#define O_SAWQ ((size_t)0)
#define O_SAWK ((size_t)1*NSQ)
#define O_SAWV ((size_t)2*NSQ)
#define O_SAWO ((size_t)3*NSQ)
#define O_CAWQ ((size_t)4*NSQ)
#define O_CAWK ((size_t)5*NSQ)
#define O_CAWV ((size_t)6*NSQ)
#define O_CAWO ((size_t)7*NSQ)
#define O_WI0  ((size_t)8*NSQ)
#define O_WI1  (O_WI0 + NWI)
#define O_WO   (O_WI1 + NWI)
#define W_TOT  (O_WO + NWI)
#define PFXN   (Bv*2*Pv*Hv*HDv)

// ---------------- scratch ----------------------------------------------------
__device__ float g_xn[Bv*Lv*Dv];
__device__ __nv_bfloat16 g_xnh[Bv*Lv*Dv], g_xnl[Bv*Lv*Dv];
__device__ __nv_bfloat16 g_ench[Bv*Lv*Dv], g_encl[Bv*Lv*Dv];
__device__ __nv_bfloat16 g_atth[Bv*Lv*Dv], g_attl[Bv*Lv*Dv];
__device__ __nv_bfloat16 g_qkvh[Bv*Lv*3*Dv], g_qkvl[Bv*Lv*3*Dv];
__device__ __nv_bfloat16 g_ckvh[Bv*Lv*2*Dv], g_ckvl[Bv*Lv*2*Dv];
__device__ __nv_bfloat16 g_cqh[Bv*Lv*Dv], g_cql[Bv*Lv*Dv];
__device__ __nv_bfloat16 g_pkh[PFXN], g_pkl[PFXN], g_pvh[PFXN], g_pvl[PFXN];
__device__ float g_bias[Hv*1024];
__device__ float g_x [Bv*Lv*Dv];
__device__ float g_y [Bv*Lv*Dv];
__device__ float g_h0[Bv*Lv*Fv];
__device__ __nv_bfloat16 g_h1h[Bv*Lv*Fv], g_h1l[Bv*Lv*Fv];
__device__ float g_az[Bv*Lv*Av];
__device__ __nv_bfloat16 g_wth[W_TOT], g_wtl[W_TOT];

__device__ __forceinline__ float gelu_f(float x) {
    float x3 = x * x * x;
    return 0.5f * x * (1.0f + tanhf(0.7978845608028654f * (x + 0.044715f * x3)));
}

__device__ __forceinline__ void split1(float f, __nv_bfloat16& h, __nv_bfloat16& l) {
    h = __float2bfloat16(f);
    l = __float2bfloat16(f - __bfloat162float(h));
}

__device__ __forceinline__ void split2(float f0, float f1, unsigned &hi, unsigned &lo) {
    __nv_bfloat162 h = __floats2bfloat162_rn(f0, f1);
    float r0 = f0 - __bfloat162float(h.x);
    float r1 = f1 - __bfloat162float(h.y);
    __nv_bfloat162 l = __floats2bfloat162_rn(r0, r1);
    hi = *reinterpret_cast<unsigned*>(&h);
    lo = *reinterpret_cast<unsigned*>(&l);
}

__device__ __forceinline__ void mma16816(float* c, const unsigned* a, const unsigned* b) {
    asm volatile(
        "mma.sync.aligned.m16n8k16.row.col.f32.bf16.bf16.f32 "
        "{%0,%1,%2,%3}, {%4,%5,%6,%7}, {%8,%9}, {%0,%1,%2,%3};\n"
        : "+f"(c[0]), "+f"(c[1]), "+f"(c[2]), "+f"(c[3])
        : "r"(a[0]), "r"(a[1]), "r"(a[2]), "r"(a[3]), "r"(b[0]), "r"(b[1]));
}

#define LDSM4(r0,r1,r2,r3,a) \
    asm volatile("ldmatrix.sync.aligned.m8n8.x4.shared.b16 {%0,%1,%2,%3}, [%4];" \
        : "=r"(r0),"=r"(r1),"=r"(r2),"=r"(r3) : "r"(a))
#define LDSM4T(r0,r1,r2,r3,a) \
    asm volatile("ldmatrix.sync.aligned.m8n8.x4.trans.shared.b16 {%0,%1,%2,%3}, [%4];" \
        : "=r"(r0),"=r"(r1),"=r"(r2),"=r"(r3) : "r"(a))
#define CPA16(dst, src) \
    asm volatile("cp.async.cg.shared.global [%0], [%1], 16;" :: "r"(dst), "l"(src))
#define CPA16Z(dst, src) \
    asm volatile("cp.async.cg.shared.global [%0], [%1], 16, 0;" :: "r"(dst), "l"(src))

// ---------------- conversions -------------------------------------------------
__global__ __launch_bounds__(256) void split_kernel(
    const float* __restrict__ in, __nv_bfloat16* __restrict__ hi,
    __nv_bfloat16* __restrict__ lo, int n4)
{
    int i = blockIdx.x * 256 + threadIdx.x;
    if (i >= n4) return;
    float4 v = *(const float4*)&in[(size_t)i * 4];
    __nv_bfloat16 h[4], l[4];
    split1(v.x, h[0], l[0]); split1(v.y, h[1], l[1]);
    split1(v.z, h[2], l[2]); split1(v.w, h[3], l[3]);
    *(uint2*)&hi[(size_t)i * 4] = *(uint2*)h;
    *(uint2*)&lo[(size_t)i * 4] = *(uint2*)l;
}

__global__ __launch_bounds__(256) void tsplit_kernel(
    const float* __restrict__ W, __nv_bfloat16* __restrict__ th,
    __nv_bfloat16* __restrict__ tl, int K, int N, float scale)
{
    __shared__ float tile[32][33];
    int n0 = blockIdx.x * 32, k0 = blockIdx.y * 32;
    int tx = threadIdx.x & 31, ty = threadIdx.x >> 5;
    #pragma unroll
    for (int j = 0; j < 4; j++)
        tile[ty + 8*j][tx] = W[(size_t)(k0 + ty + 8*j) * N + n0 + tx];
    __syncthreads();
    #pragma unroll
    for (int j = 0; j < 4; j++) {
        float v = tile[tx][ty + 8*j] * scale;
        __nv_bfloat16 h, l;
        split1(v, h, l);
        size_t idx = (size_t)(n0 + ty + 8*j) * K + k0 + tx;
        th[idx] = h; tl[idx] = l;
    }
}

__global__ __launch_bounds__(256) void bias_build(
    const float* __restrict__ relpos, float* __restrict__ tab)
{
    int h = blockIdx.x;
    int r = blockIdx.y * 256 + threadIdx.x;
    int bkt;
    if (r < 16) bkt = r;
    else {
        bkt = 16 + (int)(logf((float)r * 0.0625f) * (16.0f / 2.0794415416798357f));
        if (bkt > 31) bkt = 31;
    }
    tab[h * 1024 + r] = relpos[h * 32 + bkt];
}

// ---------------- RMSNorm -----------------------------------------------------
__global__ __launch_bounds__(256) void rmsnorm_kernel(
    const float* __restrict__ x, const float* __restrict__ w,
    float* __restrict__ of32, __nv_bfloat16* __restrict__ ohi,
    __nv_bfloat16* __restrict__ olo)
{
    int row = blockIdx.x;
    const float* xr = x + (size_t)row * Dv;
    int tid = threadIdx.x;
    int d0 = tid * 4;
    float4 v = *(const float4*)&xr[d0];
    float s = v.x*v.x + v.y*v.y + v.z*v.z + v.w*v.w;
    #pragma unroll
    for (int off = 16; off; off >>= 1) s += __shfl_xor_sync(0xffffffffu, s, off);
    __shared__ float red[8];
    __shared__ float inv_s;
    if ((tid & 31) == 0) red[tid >> 5] = s;
    __syncthreads();
    if (tid == 0) {
        float t = 0.f;
        #pragma unroll
        for (int i = 0; i < 8; i++) t += red[i];
        inv_s = rsqrtf(t * (1.0f / Dv) + 1e-6f);
    }
    __syncthreads();
    float inv = inv_s;
    float4 wv = *(const float4*)&w[d0];
    float r[4];
    r[0] = v.x*inv*wv.x; r[1] = v.y*inv*wv.y; r[2] = v.z*inv*wv.z; r[3] = v.w*inv*wv.w;
    size_t o = (size_t)row * Dv + d0;
    if (of32) { float4 rr; rr.x=r[0]; rr.y=r[1]; rr.z=r[2]; rr.w=r[3]; *(float4*)&of32[o] = rr; }
    __nv_bfloat16 h[4], l[4];
    #pragma unroll
    for (int i = 0; i < 4; i++) split1(r[i], h[i], l[i]);
    *(uint2*)&ohi[o] = *(uint2*)h;
    *(uint2*)&olo[o] = *(uint2*)l;
}

// ---------------- tensor-core GEMM, 3-stage cp.async, 1 sync/tile ------------
#define TG_SEG 4096
#define TG_BUF (4*TG_SEG)
#define TG_SMEM (3*TG_BUF*2)      /* 96 KB */

__device__ __forceinline__ unsigned sw_elem(int row, int c) {
    return (unsigned)(row * 32 + ((c ^ ((row >> 1) & 3)) << 3));
}

__global__ __launch_bounds__(256, 2) void tgemm_kernel(
    const __nv_bfloat16* __restrict__ Ahi, const __nv_bfloat16* __restrict__ Alo,
    const __nv_bfloat16* __restrict__ Bh,  const __nv_bfloat16* __restrict__ Bl,
    float* __restrict__ Cf, __nv_bfloat16* __restrict__ Chi, __nv_bfloat16* __restrict__ Clo,
    int M, int N, int K,
    const float* __restrict__ res, const float* __restrict__ gate)
{
    extern __shared__ __align__(16) __nv_bfloat16 tgsm[];
    unsigned sbase = (unsigned)__cvta_generic_to_shared(tgsm);

    int tid  = threadIdx.x;
    int m0   = blockIdx.y * 128;
    int n0   = blockIdx.x * 128;
    int wid  = tid >> 5, lane = tid & 31;
    int g    = lane >> 2, tig = lane & 3;
    int l7   = lane & 7, sub = lane >> 3;
    int wm   = (wid & 1) * 64;
    int wn   = (wid >> 1) * 32;

    float acc[4][4][4];
    #pragma unroll
    for (int i = 0; i < 4; i++)
        #pragma unroll
        for (int j = 0; j < 4; j++)
            #pragma unroll
            for (int r = 0; r < 4; r++) acc[i][j][r] = 0.f;

#define TG_ISSUE(tt, bufb) do {                                                  \
    size_t k0i = (size_t)(tt) * 32;                                              \
    unsigned base = sbase + (unsigned)(bufb) * (TG_BUF * 2);                     \
    _Pragma("unroll")                                                            \
    for (int i_ = 0; i_ < 2; i_++) {                                             \
        int cc = tid + i_ * 256; int row = cc >> 2; int c4 = cc & 3;             \
        unsigned so = sw_elem(row, c4) * 2;                                      \
        size_t ga = (size_t)(m0 + row) * K + k0i + c4 * 8;                       \
        size_t gb = (size_t)(n0 + row) * K + k0i + c4 * 8;                       \
        CPA16(base + so,                 Ahi + ga);                              \
        CPA16(base + TG_SEG*2 + so,      Alo + ga);                              \
        CPA16(base + 2*TG_SEG*2 + so,    Bh + gb);                               \
        CPA16(base + 3*TG_SEG*2 + so,    Bl + gb);                               \
    }                                                                            \
    asm volatile("cp.async.commit_group;");                                      \
} while (0)

    int nk = K >> 5;
    TG_ISSUE(0, 0);
    if (nk > 1) TG_ISSUE(1, 1);

    int buf = 0;
    for (int t = 0; t < nk; t++) {
        if (t + 1 < nk) asm volatile("cp.async.wait_group 1;");
        else            asm volatile("cp.async.wait_group 0;");
        __syncthreads();

        if (t + 2 < nk) {
            int nb = buf + 2; if (nb >= 3) nb -= 3;
            TG_ISSUE(t + 2, nb);
        }

        unsigned bufo = sbase + (unsigned)buf * (TG_BUF * 2);
        #pragma unroll
        for (int ks = 0; ks < 2; ks++) {
            unsigned bh_[8], bl_[8];
            #pragma unroll
            for (int p = 0; p < 2; p++) {
                int nrow = wn + p * 16 + ((sub >> 1) << 3) + l7;
                int cB = ks * 2 + (sub & 1);
                unsigned ab = bufo + 2 * TG_SEG * 2 + sw_elem(nrow, cB) * 2;
                LDSM4(bh_[4*p+0], bh_[4*p+1], bh_[4*p+2], bh_[4*p+3], ab);
                LDSM4(bl_[4*p+0], bl_[4*p+1], bl_[4*p+2], bl_[4*p+3], ab + TG_SEG * 2);
            }
            #pragma unroll
            for (int mt = 0; mt < 4; mt++) {
                int arow = wm + mt * 16 + ((sub & 1) << 3) + l7;
                int cA = ks * 2 + (sub >> 1);
                unsigned aa = bufo + sw_elem(arow, cA) * 2;
                unsigned ah[4], al[4];
                LDSM4(ah[0], ah[1], ah[2], ah[3], aa);
                LDSM4(al[0], al[1], al[2], al[3], aa + TG_SEG * 2);
                #pragma unroll
                for (int nt = 0; nt < 4; nt++)
                    mma16816(acc[mt][nt], ah, &bh_[nt * 2]);
                #pragma unroll
                for (int nt = 0; nt < 4; nt++)
                    mma16816(acc[mt][nt], ah, &bl_[nt * 2]);
                #pragma unroll
                for (int nt = 0; nt < 4; nt++)
                    mma16816(acc[mt][nt], al, &bh_[nt * 2]);
            }
        }
        if (++buf == 3) buf = 0;
    }
#undef TG_ISSUE

    #pragma unroll
    for (int mt = 0; mt < 4; mt++) {
        #pragma unroll
        for (int half = 0; half < 2; half++) {
            int m = m0 + wm + mt * 16 + g + half * 8;
            #pragma unroll
            for (int nt = 0; nt < 4; nt++) {
                int n = n0 + wn + nt * 8 + 2 * tig;
                size_t idx = (size_t)m * N + n;
                float v0 = acc[mt][nt][half * 2 + 0];
                float v1 = acc[mt][nt][half * 2 + 1];
                if (res) {
                    float2 rv = *(const float2*)&res[idx];
                    v0 += rv.x; v1 += rv.y;
                }
                if (gate) {
                    float2 gv = *(const float2*)&gate[idx];
                    v0 *= gelu_f(gv.x); v1 *= gelu_f(gv.y);
                }
                if (Cf) {
                    float2 o; o.x = v0; o.y = v1;
                    *(float2*)&Cf[idx] = o;
                } else {
                    unsigned hh, ll;
                    split2(v0, v1, hh, ll);
                    *(unsigned*)&Chi[idx] = hh;
                    *(unsigned*)&Clo[idx] = ll;
                }
            }
        }
    }
}

// ---------------- MMA flash attention (strided q/kv for fused layouts) --------
#define FA_QLO 16384
#define FA_KV  32768
#define FA_BIAS 98304
#define FA_SMEM 102400

__global__ __launch_bounds__(256) void fattn_kernel(
    const __nv_bfloat16* __restrict__ qh, const __nv_bfloat16* __restrict__ qlo_,
    const __nv_bfloat16* __restrict__ kh, const __nv_bfloat16* __restrict__ kl,
    const __nv_bfloat16* __restrict__ vh, const __nv_bfloat16* __restrict__ vl,
    int qstride, int kvstride,
    const __nv_bfloat16* __restrict__ pkh, const __nv_bfloat16* __restrict__ pkl,
    const __nv_bfloat16* __restrict__ pvh, const __nv_bfloat16* __restrict__ pvl,
    const float* __restrict__ biasTab,
    __nv_bfloat16* __restrict__ obh, __nv_bfloat16* __restrict__ obl,
    int sel, int causal)
{
    extern __shared__ __align__(16) char fsm[];
    unsigned sb = (unsigned)__cvta_generic_to_shared(fsm);
    const float* sbias = (const float*)(fsm + FA_BIAS);
    int tid = threadIdx.x, wid = tid >> 5, lane = tid & 31;
    int g = lane >> 2, tig = lane & 3;
    int bhid = blockIdx.y; int b = bhid >> 4, h = bhid & 15;
    int q0 = blockIdx.x * BQ;
    int row0 = wid * 16;

    int ntile = causal ? ((Pv + q0 + BQ + 63) >> 6) : NKT;
    int lastk = Pv + q0 + row0 + 15;

    const __nv_bfloat16* msrc[4] = {kh, kl, vh, vl};
    const __nv_bfloat16* psrc[4] = {pkh, pkl, pvh, pvl};
    int rk = tid >> 3, ck = tid & 7;

    #pragma unroll
    for (int i = 0; i < 8; i++) {
        int arr = i >> 2;
        int r = rk + (i & 3) * 32;
        unsigned dst = sb + (arr ? FA_QLO : 0) + r * 128 + (((ck ^ (r & 7))) << 4);
        const __nv_bfloat16* src = (arr ? qlo_ : qh) +
            ((size_t)(b * Lv + q0 + r) * qstride + h * HDv + ck * 8);
        CPA16(dst, src);
    }
    if (causal) CPA16(sb + FA_BIAS + tid * 16, biasTab + h * 1024 + tid * 4);

#define FA_STAGE(t, bufb) do {                                                   \
    int tb_ = (t) * 64;                                                          \
    _Pragma("unroll")                                                            \
    for (int a_ = 0; a_ < 4; a_++) {                                             \
        _Pragma("unroll")                                                        \
        for (int i2 = 0; i2 < 2; i2++) {                                         \
            int r = rk + i2 * 32;                                                \
            unsigned dst = sb + FA_KV + (unsigned)(bufb) * 32768 + a_ * 8192     \
                           + r * 128 + ((ck ^ (r & 7)) << 4);                    \
            int gk = tb_ + r;                                                    \
            const __nv_bfloat16* src;                                            \
            if (gk < Pv)                                                         \
                src = psrc[a_] + ((((size_t)(b * 2 + sel) * Pv + gk) * Hv + h) * HDv + ck * 8); \
            else                                                                 \
                src = msrc[a_] + ((size_t)(b * Lv + (gk < KTOT ? gk - Pv : 0)) * kvstride + h * HDv + ck * 8); \
            if (gk < KTOT) { CPA16(dst, src); } else { CPA16Z(dst, src); }       \
        }                                                                        \
    }                                                                            \
    asm volatile("cp.async.commit_group;");                                      \
} while (0)

    FA_STAGE(0, 0);
    if (ntile > 1) FA_STAGE(1, 1);

    unsigned qhF[4][4], qlF[4][4];
    float S[8][4], O[8][4];
    #pragma unroll
    for (int i = 0; i < 8; i++) { O[i][0]=0.f; O[i][1]=0.f; O[i][2]=0.f; O[i][3]=0.f; }
    float m_lo = -1e30f, m_hi = -1e30f, l_lo = 0.f, l_hi = 0.f;
    int qrow_lo = q0 + row0 + g, qrow_hi = qrow_lo + 8;

    for (int t = 0; t < ntile; t++) {
        if (t + 1 < ntile) asm volatile("cp.async.wait_group 1;");
        else               asm volatile("cp.async.wait_group 0;");
        __syncthreads();

        if (t == 0) {
            int lrow = row0 + (lane & 15);
            int cb = lane >> 4;
            #pragma unroll
            for (int ks = 0; ks < 4; ks++) {
                int ch = (ks * 2 + cb) ^ (lrow & 7);
                unsigned a = sb + lrow * 128 + (ch << 4);
                LDSM4(qhF[ks][0], qhF[ks][1], qhF[ks][2], qhF[ks][3], a);
                LDSM4(qlF[ks][0], qlF[ks][1], qlF[ks][2], qlF[ks][3], a + FA_QLO);
            }
        }

        bool act = causal ? (t * 64 <= lastk) : true;
        if (act) {
            unsigned kvb = sb + FA_KV + (unsigned)(t & 1) * 32768;
            #pragma unroll
            for (int i = 0; i < 8; i++) { S[i][0]=0.f; S[i][1]=0.f; S[i][2]=0.f; S[i][3]=0.f; }

            int krow = ((lane >> 4) << 3) + (lane & 7);
            int kcb = (lane >> 3) & 1;
            #pragma unroll
            for (int ks = 0; ks < 4; ks++) {
                #pragma unroll
                for (int j = 0; j < 4; j++) {
                    int kr = j * 16 + krow;
                    int ch = (ks * 2 + kcb) ^ (kr & 7);
                    unsigned ka = kvb + kr * 128 + (ch << 4);
                    unsigned bh_[4], bl_[4];
                    LDSM4(bh_[0], bh_[1], bh_[2], bh_[3], ka);
                    LDSM4(bl_[0], bl_[1], bl_[2], bl_[3], ka + 8192);
                    mma16816(S[2*j],   qhF[ks], bh_);
                    mma16816(S[2*j+1], qhF[ks], bh_ + 2);
                    mma16816(S[2*j],   qhF[ks], bl_);
                    mma16816(S[2*j+1], qhF[ks], bl_ + 2);
                    mma16816(S[2*j],   qlF[ks], bh_);
                    mma16816(S[2*j+1], qlF[ks], bh_ + 2);
                }
            }

            int tb = t * 64;
            #pragma unroll
            for (int nt = 0; nt < 8; nt++) {
                #pragma unroll
                for (int u = 0; u < 2; u++) {
                    int key = tb + nt * 8 + 2 * tig + u;
                    if (key >= KTOT) { S[nt][u] = -1e10f; S[nt][2+u] = -1e10f; }
                    else if (causal) {
                        int kp = key - Pv;
                        if (kp >= 0) {
                            if (kp > qrow_lo) S[nt][u]   = -1e10f; else S[nt][u]   += sbias[qrow_lo - kp];
                            if (kp > qrow_hi) S[nt][2+u] = -1e10f; else S[nt][2+u] += sbias[qrow_hi - kp];
                        }
                    }
                }
            }

            float tm0 = -1e30f, tm1 = -1e30f;
            #pragma unroll
            for (int nt = 0; nt < 8; nt++) {
                tm0 = fmaxf(tm0, fmaxf(S[nt][0], S[nt][1]));
                tm1 = fmaxf(tm1, fmaxf(S[nt][2], S[nt][3]));
            }
            tm0 = fmaxf(tm0, __shfl_xor_sync(0xffffffffu, tm0, 1));
            tm0 = fmaxf(tm0, __shfl_xor_sync(0xffffffffu, tm0, 2));
            tm1 = fmaxf(tm1, __shfl_xor_sync(0xffffffffu, tm1, 1));
            tm1 = fmaxf(tm1, __shfl_xor_sync(0xffffffffu, tm1, 2));
            float mn0 = fmaxf(m_lo, tm0), mn1 = fmaxf(m_hi, tm1);
            float c0 = __expf(m_lo - mn0), c1 = __expf(m_hi - mn1);
            m_lo = mn0; m_hi = mn1;
            float s0 = 0.f, s1 = 0.f;
            #pragma unroll
            for (int nt = 0; nt < 8; nt++) {
                S[nt][0] = __expf(S[nt][0] - mn0); s0 += S[nt][0];
                S[nt][1] = __expf(S[nt][1] - mn0); s0 += S[nt][1];
                S[nt][2] = __expf(S[nt][2] - mn1); s1 += S[nt][2];
                S[nt][3] = __expf(S[nt][3] - mn1); s1 += S[nt][3];
            }
            s0 += __shfl_xor_sync(0xffffffffu, s0, 1);
            s0 += __shfl_xor_sync(0xffffffffu, s0, 2);
            s1 += __shfl_xor_sync(0xffffffffu, s1, 1);
            s1 += __shfl_xor_sync(0xffffffffu, s1, 2);
            l_lo = l_lo * c0 + s0; l_hi = l_hi * c1 + s1;
            #pragma unroll
            for (int nt = 0; nt < 8; nt++) {
                O[nt][0] *= c0; O[nt][1] *= c0; O[nt][2] *= c1; O[nt][3] *= c1;
            }

            int vrow = ((lane >> 3) & 1) * 8 + (lane & 7);
            int vcb = lane >> 4;
            #pragma unroll
            for (int ks = 0; ks < 4; ks++) {
                unsigned pah[4], pal[4];
                split2(S[2*ks][0],   S[2*ks][1],   pah[0], pal[0]);
                split2(S[2*ks][2],   S[2*ks][3],   pah[1], pal[1]);
                split2(S[2*ks+1][0], S[2*ks+1][1], pah[2], pal[2]);
                split2(S[2*ks+1][2], S[2*ks+1][3], pah[3], pal[3]);
                int vr = ks * 16 + vrow;
                #pragma unroll
                for (int j = 0; j < 4; j++) {
                    int ch = (2*j + vcb) ^ (vr & 7);
                    unsigned va = kvb + 16384 + vr * 128 + (ch << 4);
                    unsigned bh_[4], bl_[4];
                    LDSM4T(bh_[0], bh_[1], bh_[2], bh_[3], va);
                    LDSM4T(bl_[0], bl_[1], bl_[2], bl_[3], va + 8192);
                    mma16816(O[2*j],   pah, bh_);
                    mma16816(O[2*j+1], pah, bh_ + 2);
                    mma16816(O[2*j],   pah, bl_);
                    mma16816(O[2*j+1], pah, bl_ + 2);
                    mma16816(O[2*j],   pal, bh_);
                    mma16816(O[2*j+1], pal, bh_ + 2);
                }
            }
        }
        __syncthreads();
        if (t + 2 < ntile) FA_STAGE(t + 2, t & 1);
    }
#undef FA_STAGE

    float inv0 = 1.f / l_lo, inv1 = 1.f / l_hi;
    size_t base_lo = ((size_t)(b * Lv + qrow_lo) * Hv + h) * HDv + 2 * tig;
    size_t base_hi = ((size_t)(b * Lv + qrow_hi) * Hv + h) * HDv + 2 * tig;
    #pragma unroll
    for (int nt = 0; nt < 8; nt++) {
        unsigned h01, l01, h23, l23;
        split2(O[nt][0] * inv0, O[nt][1] * inv0, h01, l01);
        split2(O[nt][2] * inv1, O[nt][3] * inv1, h23, l23);
        *(unsigned*)&obh[base_lo + nt * 8] = h01;
        *(unsigned*)&obl[base_lo + nt * 8] = l01;
        *(unsigned*)&obh[base_hi + nt * 8] = h23;
        *(unsigned*)&obl[base_hi + nt * 8] = l23;
    }
}

// ---------------- per-example adapter -----------------------------------------
__global__ __launch_bounds__(256) void adapter_down(
    const float* __restrict__ lz, const float* __restrict__ wd,
    const float* __restrict__ bd, float* __restrict__ az)
{
    __shared__ float part[4][Av];
    int b = blockIdx.y, l = blockIdx.x;
    int a = threadIdx.x & 63, kg = threadIdx.x >> 6;
    const float* xr = lz + (size_t)(b * Lv + l) * Dv + kg * 256;
    const float* wb = wd + (size_t)b * Dv * Av + (size_t)kg * 256 * Av + a;
    float s = 0.f;
    #pragma unroll 8
    for (int dd = 0; dd < 256; dd++) s += xr[dd] * wb[(size_t)dd * Av];
    part[kg][a] = s;
    __syncthreads();
    if (threadIdx.x < Av) {
        float t = part[0][threadIdx.x] + part[1][threadIdx.x]
                + part[2][threadIdx.x] + part[3][threadIdx.x]
                + bd[b * Av + threadIdx.x];
        az[(size_t)(b * Lv + l) * Av + threadIdx.x] = gelu_f(t);
    }
}

__global__ __launch_bounds__(256) void adapter_up(
    const float* __restrict__ az, const float* __restrict__ wu,
    const float* __restrict__ bu, float* __restrict__ out)
{
    int b = blockIdx.y, l = blockIdx.x;
    __shared__ float ash[Av];
    int tid = threadIdx.x;
    if (tid < Av) ash[tid] = az[(size_t)(b * Lv + l) * Av + tid];
    __syncthreads();
    const float* wb = wu + (size_t)b * Av * Dv;
    size_t o = (size_t)(b * Lv + l) * Dv;
    for (int dd = tid; dd < Dv; dd += 256) {
        float s = bu[b * Dv + dd];
        #pragma unroll 8
        for (int a = 0; a < Av; a++) s += ash[a] * wb[a * Dv + dd];
        out[o + dd] += s;
    }
}

// ---------------- driver -------------------------------------------------------
extern "C" void kernel_launch(void* const* d_in, const int* in_sizes, int n_in,
                              void* d_out, int out_size)
{
    const float* inputs  = (const float*)d_in[0];
    const float* encoded = (const float*)d_in[1];
    const float* awd     = (const float*)d_in[2];
    const float* awu     = (const float*)d_in[3];
    const float* abd     = (const float*)d_in[4];
    const float* abu     = (const float*)d_in[5];
    const float* pk      = (const float*)d_in[6];
    const float* pvv     = (const float*)d_in[7];
    const float* ln1     = (const float*)d_in[8];
    const float* ln2     = (const float*)d_in[9];
    const float* ln3     = (const float*)d_in[10];
    const float* sa_wq   = (const float*)d_in[11];
    const float* sa_wk   = (const float*)d_in[12];
    const float* sa_wv   = (const float*)d_in[13];
    const float* sa_wo   = (const float*)d_in[14];
    const float* ca_wq   = (const float*)d_in[15];
    const float* ca_wk   = (const float*)d_in[16];
    const float* ca_wv   = (const float*)d_in[17];
    const float* ca_wo   = (const float*)d_in[18];
    const float* relpos  = (const float*)d_in[19];
    const float* wi0     = (const float*)d_in[20];
    const float* wi1     = (const float*)d_in[21];
    const float* wo_mlp  = (const float*)d_in[22];
    float* out = (float*)d_out;

    float *xn, *x, *y, *h0, *az, *bias;
    __nv_bfloat16 *xnh, *xnl, *ench, *encl, *atth, *attl, *h1h, *h1l, *wth, *wtl;
    __nv_bfloat16 *qkvh, *qkvl, *ckvh, *ckvl, *cqh, *cql, *pkh, *pkl, *pvh, *pvl;
    cudaGetSymbolAddress((void**)&xn,   g_xn);
    cudaGetSymbolAddress((void**)&xnh,  g_xnh);
    cudaGetSymbolAddress((void**)&xnl,  g_xnl);
    cudaGetSymbolAddress((void**)&ench, g_ench);
    cudaGetSymbolAddress((void**)&encl, g_encl);
    cudaGetSymbolAddress((void**)&atth, g_atth);
    cudaGetSymbolAddress((void**)&attl, g_attl);
    cudaGetSymbolAddress((void**)&qkvh, g_qkvh);
    cudaGetSymbolAddress((void**)&qkvl, g_qkvl);
    cudaGetSymbolAddress((void**)&ckvh, g_ckvh);
    cudaGetSymbolAddress((void**)&ckvl, g_ckvl);
    cudaGetSymbolAddress((void**)&cqh,  g_cqh);
    cudaGetSymbolAddress((void**)&cql,  g_cql);
    cudaGetSymbolAddress((void**)&pkh,  g_pkh);
    cudaGetSymbolAddress((void**)&pkl,  g_pkl);
    cudaGetSymbolAddress((void**)&pvh,  g_pvh);
    cudaGetSymbolAddress((void**)&pvl,  g_pvl);
    cudaGetSymbolAddress((void**)&bias, g_bias);
    cudaGetSymbolAddress((void**)&x,    g_x);
    cudaGetSymbolAddress((void**)&y,    g_y);
    cudaGetSymbolAddress((void**)&h0,   g_h0);
    cudaGetSymbolAddress((void**)&h1h,  g_h1h);
    cudaGetSymbolAddress((void**)&h1l,  g_h1l);
    cudaGetSymbolAddress((void**)&az,   g_az);
    cudaGetSymbolAddress((void**)&wth,  g_wth);
    cudaGetSymbolAddress((void**)&wtl,  g_wtl);

    cudaFuncSetAttribute(fattn_kernel, cudaFuncAttributeMaxDynamicSharedMemorySize, FA_SMEM);
    cudaFuncSetAttribute(tgemm_kernel, cudaFuncAttributeMaxDynamicSharedMemorySize, TG_SMEM);

    const int M = Bv * Lv;
    dim3 g8(8, 32), g16(16, 32), g22(22, 32), g24(24, 32);
    dim3 ga(Lv / BQ, Bv * Hv);
    dim3 tsq(32, 32), tswi(88, 32), tswo(32, 88);

    // ---- fork a side stream into the capture ----
    cudaStream_t s1;
    cudaStreamCreateWithFlags(&s1, cudaStreamNonBlocking);
    cudaEvent_t evFork, evA, evPfx, evCq, evCkv, evCo, evW, evRn3, evAd;
    cudaEventCreateWithFlags(&evFork, cudaEventDisableTiming);
    cudaEventCreateWithFlags(&evA,    cudaEventDisableTiming);
    cudaEventCreateWithFlags(&evPfx,  cudaEventDisableTiming);
    cudaEventCreateWithFlags(&evCq,   cudaEventDisableTiming);
    cudaEventCreateWithFlags(&evCkv,  cudaEventDisableTiming);
    cudaEventCreateWithFlags(&evCo,   cudaEventDisableTiming);
    cudaEventCreateWithFlags(&evW,    cudaEventDisableTiming);
    cudaEventCreateWithFlags(&evRn3,  cudaEventDisableTiming);
    cudaEventCreateWithFlags(&evAd,   cudaEventDisableTiming);

    cudaEventRecord(evFork, 0);
    cudaStreamWaitEvent(s1, evFork, 0);

    // ---- side stream: input-only work (conversions + cross-KV GEMM) ----
    tsplit_kernel<<<tsq, 256, 0, s1>>>(sa_wq, wth + O_SAWQ, wtl + O_SAWQ, 1024, 1024, 0.125f);
    tsplit_kernel<<<tsq, 256, 0, s1>>>(sa_wk, wth + O_SAWK, wtl + O_SAWK, 1024, 1024, 1.f);
    tsplit_kernel<<<tsq, 256, 0, s1>>>(sa_wv, wth + O_SAWV, wtl + O_SAWV, 1024, 1024, 1.f);
    cudaEventRecord(evA, s1);
    split_kernel<<<(PFXN / 4 + 255) / 256, 256, 0, s1>>>(pk,  pkh, pkl, PFXN / 4);
    split_kernel<<<(PFXN / 4 + 255) / 256, 256, 0, s1>>>(pvv, pvh, pvl, PFXN / 4);
    bias_build<<<dim3(Hv, 4), 256, 0, s1>>>(relpos, bias);
    cudaEventRecord(evPfx, s1);
    tsplit_kernel<<<tsq, 256, 0, s1>>>(ca_wq, wth + O_CAWQ, wtl + O_CAWQ, 1024, 1024, 0.125f);
    cudaEventRecord(evCq, s1);
    split_kernel<<<(M * Dv / 4 + 255) / 256, 256, 0, s1>>>(encoded, ench, encl, M * Dv / 4);
    tsplit_kernel<<<tsq, 256, 0, s1>>>(ca_wk, wth + O_CAWK, wtl + O_CAWK, 1024, 1024, 1.f);
    tsplit_kernel<<<tsq, 256, 0, s1>>>(ca_wv, wth + O_CAWV, wtl + O_CAWV, 1024, 1024, 1.f);
    tgemm_kernel<<<g16, 256, TG_SMEM, s1>>>(ench, encl, wth + O_CAWK, wtl + O_CAWK,
                                            nullptr, ckvh, ckvl, M, 2048, 1024, nullptr, nullptr);
    cudaEventRecord(evCkv, s1);
    tsplit_kernel<<<tsq, 256, 0, s1>>>(ca_wo, wth + O_CAWO, wtl + O_CAWO, 1024, 1024, 1.f);
    cudaEventRecord(evCo, s1);
    tsplit_kernel<<<tswi, 256, 0, s1>>>(wi0, wth + O_WI0, wtl + O_WI0, 1024, 2816, 1.f);
    tsplit_kernel<<<tswi, 256, 0, s1>>>(wi1, wth + O_WI1, wtl + O_WI1, 1024, 2816, 1.f);
    tsplit_kernel<<<tswo, 256, 0, s1>>>(wo_mlp, wth + O_WO, wtl + O_WO, 2816, 1024, 1.f);
    cudaEventRecord(evW, s1);

    // ---- main stream: critical path (up to rmsnorm3) ----
    rmsnorm_kernel<<<M, 256>>>(inputs, ln1, nullptr, xnh, xnl);
    cudaStreamWaitEvent(0, evA, 0);
    tgemm_kernel<<<g24, 256, TG_SMEM>>>(xnh, xnl, wth + O_SAWQ, wtl + O_SAWQ,
                                        nullptr, qkvh, qkvl, M, 3072, 1024, nullptr, nullptr);
    cudaStreamWaitEvent(0, evPfx, 0);
    fattn_kernel<<<ga, 256, FA_SMEM>>>(qkvh, qkvl, qkvh + 1024, qkvl + 1024,
                                       qkvh + 2048, qkvl + 2048, 3072, 3072,
                                       pkh, pkl, pvh, pvl, bias, atth, attl, 0, 1);
    tsplit_kernel<<<tsq, 256>>>(sa_wo, wth + O_SAWO, wtl + O_SAWO, 1024, 1024, 1.f);
    tgemm_kernel<<<g8, 256, TG_SMEM>>>(atth, attl, wth + O_SAWO, wtl + O_SAWO,
                                       x, nullptr, nullptr, M, 1024, 1024, inputs, nullptr);

    rmsnorm_kernel<<<M, 256>>>(x, ln2, nullptr, xnh, xnl);
    cudaStreamWaitEvent(0, evCq, 0);
    tgemm_kernel<<<g8, 256, TG_SMEM>>>(xnh, xnl, wth + O_CAWQ, wtl + O_CAWQ,
                                       nullptr, cqh, cql, M, 1024, 1024, nullptr, nullptr);
    cudaStreamWaitEvent(0, evCkv, 0);
    fattn_kernel<<<ga, 256, FA_SMEM>>>(cqh, cql, ckvh, ckvl,
                                       ckvh + 1024, ckvl + 1024, 1024, 2048,
                                       pkh, pkl, pvh, pvl, bias, atth, attl, 1, 0);
    cudaStreamWaitEvent(0, evCo, 0);
    tgemm_kernel<<<g8, 256, TG_SMEM>>>(atth, attl, wth + O_CAWO, wtl + O_CAWO,
                                       y, nullptr, nullptr, M, 1024, 1024, x, nullptr);

    rmsnorm_kernel<<<M, 256>>>(y, ln3, xn, xnh, xnl);
    cudaEventRecord(evRn3, 0);

    // ---- side stream: adapter_down (issued AFTER evRn3 is recorded on host) --
    cudaStreamWaitEvent(s1, evRn3, 0);
    adapter_down<<<dim3(Lv, Bv), 256, 0, s1>>>(xn, awd, abd, az);
    cudaEventRecord(evAd, s1);

    // ---- main stream: MLP + join ----
    cudaStreamWaitEvent(0, evW, 0);
    tgemm_kernel<<<g22, 256, TG_SMEM>>>(xnh, xnl, wth + O_WI0, wtl + O_WI0,
                                        h0, nullptr, nullptr, M, Fv, 1024, nullptr, nullptr);
    tgemm_kernel<<<g22, 256, TG_SMEM>>>(xnh, xnl, wth + O_WI1, wtl + O_WI1,
                                        nullptr, h1h, h1l, M, Fv, 1024, nullptr, h0);
    tgemm_kernel<<<g8, 256, TG_SMEM>>>(h1h, h1l, wth + O_WO, wtl + O_WO,
                                       out, nullptr, nullptr, M, 1024, Fv, y, nullptr);
    cudaStreamWaitEvent(0, evAd, 0);
    adapter_up<<<dim3(Lv, Bv), 256>>>(az, awu, abu, out);
}

// round 16
// speedup vs baseline: 2.2336x; 1.0522x over previous
#include <cuda_runtime.h>
#include <cuda_bf16.h>
#include <math.h>

#define Bv 4
#define Lv 1024
#define Dv 1024
#define Hv 16
#define HDv 64
#define Fv 2816
#define Av 64
#define Pv 30
#define KTOT (Pv + Lv)
#define NKT 17
#define BQ 128

#define NSQ (1024*1024)
#define NWI (1024*2816)
#define O_SAWQ ((size_t)0)
#define O_SAWK ((size_t)1*NSQ)
#define O_SAWV ((size_t)2*NSQ)
#define O_SAWO ((size_t)3*NSQ)
#define O_CAWQ ((size_t)4*NSQ)
#define O_CAWK ((size_t)5*NSQ)
#define O_CAWV ((size_t)6*NSQ)
#define O_CAWO ((size_t)7*NSQ)
#define O_WI0  ((size_t)8*NSQ)
#define O_WI1  (O_WI0 + NWI)
#define O_WO   (O_WI1 + NWI)
#define W_TOT  (O_WO + NWI)
#define PFXN   (Bv*2*Pv*Hv*HDv)

// ---------------- scratch ----------------------------------------------------
__device__ float g_xn[Bv*Lv*Dv];
__device__ __nv_bfloat16 g_xnh[Bv*Lv*Dv], g_xnl[Bv*Lv*Dv];
__device__ __nv_bfloat16 g_ench[Bv*Lv*Dv], g_encl[Bv*Lv*Dv];
__device__ __nv_bfloat16 g_atth[Bv*Lv*Dv], g_attl[Bv*Lv*Dv];
__device__ __nv_bfloat16 g_qkvh[Bv*Lv*3*Dv], g_qkvl[Bv*Lv*3*Dv];
__device__ __nv_bfloat16 g_ckvh[Bv*Lv*2*Dv], g_ckvl[Bv*Lv*2*Dv];
__device__ __nv_bfloat16 g_cqh[Bv*Lv*Dv], g_cql[Bv*Lv*Dv];
__device__ __nv_bfloat16 g_pkh[PFXN], g_pkl[PFXN], g_pvh[PFXN], g_pvl[PFXN];
__device__ float g_bias[Hv*1024];
__device__ float g_x [Bv*Lv*Dv];
__device__ float g_y [Bv*Lv*Dv];
__device__ float g_h0[Bv*Lv*Fv];
__device__ __nv_bfloat16 g_h1h[Bv*Lv*Fv], g_h1l[Bv*Lv*Fv];
__device__ float g_az[Bv*Lv*Av];
__device__ __nv_bfloat16 g_wth[W_TOT], g_wtl[W_TOT];

__device__ __forceinline__ float gelu_f(float x) {
    float x3 = x * x * x;
    return 0.5f * x * (1.0f + tanhf(0.7978845608028654f * (x + 0.044715f * x3)));
}

__device__ __forceinline__ void split1(float f, __nv_bfloat16& h, __nv_bfloat16& l) {
    h = __float2bfloat16(f);
    l = __float2bfloat16(f - __bfloat162float(h));
}

__device__ __forceinline__ void split2(float f0, float f1, unsigned &hi, unsigned &lo) {
    __nv_bfloat162 h = __floats2bfloat162_rn(f0, f1);
    float r0 = f0 - __bfloat162float(h.x);
    float r1 = f1 - __bfloat162float(h.y);
    __nv_bfloat162 l = __floats2bfloat162_rn(r0, r1);
    hi = *reinterpret_cast<unsigned*>(&h);
    lo = *reinterpret_cast<unsigned*>(&l);
}

__device__ __forceinline__ void mma16816(float* c, const unsigned* a, const unsigned* b) {
    asm volatile(
        "mma.sync.aligned.m16n8k16.row.col.f32.bf16.bf16.f32 "
        "{%0,%1,%2,%3}, {%4,%5,%6,%7}, {%8,%9}, {%0,%1,%2,%3};\n"
        : "+f"(c[0]), "+f"(c[1]), "+f"(c[2]), "+f"(c[3])
        : "r"(a[0]), "r"(a[1]), "r"(a[2]), "r"(a[3]), "r"(b[0]), "r"(b[1]));
}

#define LDSM4(r0,r1,r2,r3,a) \
    asm volatile("ldmatrix.sync.aligned.m8n8.x4.shared.b16 {%0,%1,%2,%3}, [%4];" \
        : "=r"(r0),"=r"(r1),"=r"(r2),"=r"(r3) : "r"(a))
#define LDSM4T(r0,r1,r2,r3,a) \
    asm volatile("ldmatrix.sync.aligned.m8n8.x4.trans.shared.b16 {%0,%1,%2,%3}, [%4];" \
        : "=r"(r0),"=r"(r1),"=r"(r2),"=r"(r3) : "r"(a))
#define CPA16(dst, src) \
    asm volatile("cp.async.cg.shared.global [%0], [%1], 16;" :: "r"(dst), "l"(src))
#define CPA16Z(dst, src) \
    asm volatile("cp.async.cg.shared.global [%0], [%1], 16, 0;" :: "r"(dst), "l"(src))

// ---------------- conversions -------------------------------------------------
__global__ __launch_bounds__(256) void split_kernel(
    const float* __restrict__ in, __nv_bfloat16* __restrict__ hi,
    __nv_bfloat16* __restrict__ lo, int n4)
{
    int i = blockIdx.x * 256 + threadIdx.x;
    if (i >= n4) return;
    float4 v = *(const float4*)&in[(size_t)i * 4];
    __nv_bfloat16 h[4], l[4];
    split1(v.x, h[0], l[0]); split1(v.y, h[1], l[1]);
    split1(v.z, h[2], l[2]); split1(v.w, h[3], l[3]);
    *(uint2*)&hi[(size_t)i * 4] = *(uint2*)h;
    *(uint2*)&lo[(size_t)i * 4] = *(uint2*)l;
}

__global__ __launch_bounds__(256) void tsplit_kernel(
    const float* __restrict__ W, __nv_bfloat16* __restrict__ th,
    __nv_bfloat16* __restrict__ tl, int K, int N, float scale)
{
    __shared__ float tile[32][33];
    int n0 = blockIdx.x * 32, k0 = blockIdx.y * 32;
    int tx = threadIdx.x & 31, ty = threadIdx.x >> 5;
    #pragma unroll
    for (int j = 0; j < 4; j++)
        tile[ty + 8*j][tx] = W[(size_t)(k0 + ty + 8*j) * N + n0 + tx];
    __syncthreads();
    #pragma unroll
    for (int j = 0; j < 4; j++) {
        float v = tile[tx][ty + 8*j] * scale;
        __nv_bfloat16 h, l;
        split1(v, h, l);
        size_t idx = (size_t)(n0 + ty + 8*j) * K + k0 + tx;
        th[idx] = h; tl[idx] = l;
    }
}

__global__ __launch_bounds__(256) void bias_build(
    const float* __restrict__ relpos, float* __restrict__ tab)
{
    int h = blockIdx.x;
    int r = blockIdx.y * 256 + threadIdx.x;
    int bkt;
    if (r < 16) bkt = r;
    else {
        bkt = 16 + (int)(logf((float)r * 0.0625f) * (16.0f / 2.0794415416798357f));
        if (bkt > 31) bkt = 31;
    }
    tab[h * 1024 + r] = relpos[h * 32 + bkt];
}

// ---------------- RMSNorm -----------------------------------------------------
__global__ __launch_bounds__(256) void rmsnorm_kernel(
    const float* __restrict__ x, const float* __restrict__ w,
    float* __restrict__ of32, __nv_bfloat16* __restrict__ ohi,
    __nv_bfloat16* __restrict__ olo)
{
    int row = blockIdx.x;
    const float* xr = x + (size_t)row * Dv;
    int tid = threadIdx.x;
    int d0 = tid * 4;
    float4 v = *(const float4*)&xr[d0];
    float s = v.x*v.x + v.y*v.y + v.z*v.z + v.w*v.w;
    #pragma unroll
    for (int off = 16; off; off >>= 1) s += __shfl_xor_sync(0xffffffffu, s, off);
    __shared__ float red[8];
    __shared__ float inv_s;
    if ((tid & 31) == 0) red[tid >> 5] = s;
    __syncthreads();
    if (tid == 0) {
        float t = 0.f;
        #pragma unroll
        for (int i = 0; i < 8; i++) t += red[i];
        inv_s = rsqrtf(t * (1.0f / Dv) + 1e-6f);
    }
    __syncthreads();
    float inv = inv_s;
    float4 wv = *(const float4*)&w[d0];
    float r[4];
    r[0] = v.x*inv*wv.x; r[1] = v.y*inv*wv.y; r[2] = v.z*inv*wv.z; r[3] = v.w*inv*wv.w;
    size_t o = (size_t)row * Dv + d0;
    if (of32) { float4 rr; rr.x=r[0]; rr.y=r[1]; rr.z=r[2]; rr.w=r[3]; *(float4*)&of32[o] = rr; }
    __nv_bfloat16 h[4], l[4];
    #pragma unroll
    for (int i = 0; i < 4; i++) split1(r[i], h[i], l[i]);
    *(uint2*)&ohi[o] = *(uint2*)h;
    *(uint2*)&olo[o] = *(uint2*)l;
}

// ---------------- tensor-core GEMM, 3-stage cp.async, 1 sync/tile ------------
#define TG_SEG 4096
#define TG_BUF (4*TG_SEG)
#define TG_SMEM (3*TG_BUF*2)      /* 96 KB */

__device__ __forceinline__ unsigned sw_elem(int row, int c) {
    return (unsigned)(row * 32 + ((c ^ ((row >> 1) & 3)) << 3));
}

__global__ __launch_bounds__(256, 2) void tgemm_kernel(
    const __nv_bfloat16* __restrict__ Ahi, const __nv_bfloat16* __restrict__ Alo,
    const __nv_bfloat16* __restrict__ Bh,  const __nv_bfloat16* __restrict__ Bl,
    float* __restrict__ Cf, __nv_bfloat16* __restrict__ Chi, __nv_bfloat16* __restrict__ Clo,
    int M, int N, int K,
    const float* __restrict__ res, const float* __restrict__ gate)
{
    extern __shared__ __align__(16) __nv_bfloat16 tgsm[];
    unsigned sbase = (unsigned)__cvta_generic_to_shared(tgsm);

    int tid  = threadIdx.x;
    int m0   = blockIdx.y * 128;
    int n0   = blockIdx.x * 128;
    int wid  = tid >> 5, lane = tid & 31;
    int g    = lane >> 2, tig = lane & 3;
    int l7   = lane & 7, sub = lane >> 3;
    int wm   = (wid & 1) * 64;
    int wn   = (wid >> 1) * 32;

    float acc[4][4][4];
    #pragma unroll
    for (int i = 0; i < 4; i++)
        #pragma unroll
        for (int j = 0; j < 4; j++)
            #pragma unroll
            for (int r = 0; r < 4; r++) acc[i][j][r] = 0.f;

#define TG_ISSUE(tt, bufb) do {                                                  \
    size_t k0i = (size_t)(tt) * 32;                                              \
    unsigned base = sbase + (unsigned)(bufb) * (TG_BUF * 2);                     \
    _Pragma("unroll")                                                            \
    for (int i_ = 0; i_ < 2; i_++) {                                             \
        int cc = tid + i_ * 256; int row = cc >> 2; int c4 = cc & 3;             \
        unsigned so = sw_elem(row, c4) * 2;                                      \
        size_t ga = (size_t)(m0 + row) * K + k0i + c4 * 8;                       \
        size_t gb = (size_t)(n0 + row) * K + k0i + c4 * 8;                       \
        CPA16(base + so,                 Ahi + ga);                              \
        CPA16(base + TG_SEG*2 + so,      Alo + ga);                              \
        CPA16(base + 2*TG_SEG*2 + so,    Bh + gb);                               \
        CPA16(base + 3*TG_SEG*2 + so,    Bl + gb);                               \
    }                                                                            \
    asm volatile("cp.async.commit_group;");                                      \
} while (0)

    int nk = K >> 5;
    TG_ISSUE(0, 0);
    if (nk > 1) TG_ISSUE(1, 1);

    int buf = 0;
    for (int t = 0; t < nk; t++) {
        if (t + 1 < nk) asm volatile("cp.async.wait_group 1;");
        else            asm volatile("cp.async.wait_group 0;");
        __syncthreads();

        if (t + 2 < nk) {
            int nb = buf + 2; if (nb >= 3) nb -= 3;
            TG_ISSUE(t + 2, nb);
        }

        unsigned bufo = sbase + (unsigned)buf * (TG_BUF * 2);
        #pragma unroll
        for (int ks = 0; ks < 2; ks++) {
            unsigned bh_[8], bl_[8];
            #pragma unroll
            for (int p = 0; p < 2; p++) {
                int nrow = wn + p * 16 + ((sub >> 1) << 3) + l7;
                int cB = ks * 2 + (sub & 1);
                unsigned ab = bufo + 2 * TG_SEG * 2 + sw_elem(nrow, cB) * 2;
                LDSM4(bh_[4*p+0], bh_[4*p+1], bh_[4*p+2], bh_[4*p+3], ab);
                LDSM4(bl_[4*p+0], bl_[4*p+1], bl_[4*p+2], bl_[4*p+3], ab + TG_SEG * 2);
            }
            #pragma unroll
            for (int mt = 0; mt < 4; mt++) {
                int arow = wm + mt * 16 + ((sub & 1) << 3) + l7;
                int cA = ks * 2 + (sub >> 1);
                unsigned aa = bufo + sw_elem(arow, cA) * 2;
                unsigned ah[4], al[4];
                LDSM4(ah[0], ah[1], ah[2], ah[3], aa);
                LDSM4(al[0], al[1], al[2], al[3], aa + TG_SEG * 2);
                #pragma unroll
                for (int nt = 0; nt < 4; nt++)
                    mma16816(acc[mt][nt], ah, &bh_[nt * 2]);
                #pragma unroll
                for (int nt = 0; nt < 4; nt++)
                    mma16816(acc[mt][nt], ah, &bl_[nt * 2]);
                #pragma unroll
                for (int nt = 0; nt < 4; nt++)
                    mma16816(acc[mt][nt], al, &bh_[nt * 2]);
            }
        }
        if (++buf == 3) buf = 0;
    }
#undef TG_ISSUE

    #pragma unroll
    for (int mt = 0; mt < 4; mt++) {
        #pragma unroll
        for (int half = 0; half < 2; half++) {
            int m = m0 + wm + mt * 16 + g + half * 8;
            #pragma unroll
            for (int nt = 0; nt < 4; nt++) {
                int n = n0 + wn + nt * 8 + 2 * tig;
                size_t idx = (size_t)m * N + n;
                float v0 = acc[mt][nt][half * 2 + 0];
                float v1 = acc[mt][nt][half * 2 + 1];
                if (res) {
                    float2 rv = *(const float2*)&res[idx];
                    v0 += rv.x; v1 += rv.y;
                }
                if (gate) {
                    float2 gv = *(const float2*)&gate[idx];
                    v0 *= gelu_f(gv.x); v1 *= gelu_f(gv.y);
                }
                if (Cf) {
                    float2 o; o.x = v0; o.y = v1;
                    *(float2*)&Cf[idx] = o;
                } else {
                    unsigned hh, ll;
                    split2(v0, v1, hh, ll);
                    *(unsigned*)&Chi[idx] = hh;
                    *(unsigned*)&Clo[idx] = ll;
                }
            }
        }
    }
}

// ---------------- MMA flash attention (strided q/kv for fused layouts) --------
#define FA_QLO 16384
#define FA_KV  32768
#define FA_BIAS 98304
#define FA_SMEM 102400

__global__ __launch_bounds__(256) void fattn_kernel(
    const __nv_bfloat16* __restrict__ qh, const __nv_bfloat16* __restrict__ qlo_,
    const __nv_bfloat16* __restrict__ kh, const __nv_bfloat16* __restrict__ kl,
    const __nv_bfloat16* __restrict__ vh, const __nv_bfloat16* __restrict__ vl,
    int qstride, int kvstride,
    const __nv_bfloat16* __restrict__ pkh, const __nv_bfloat16* __restrict__ pkl,
    const __nv_bfloat16* __restrict__ pvh, const __nv_bfloat16* __restrict__ pvl,
    const float* __restrict__ biasTab,
    __nv_bfloat16* __restrict__ obh, __nv_bfloat16* __restrict__ obl,
    int sel, int causal)
{
    extern __shared__ __align__(16) char fsm[];
    unsigned sb = (unsigned)__cvta_generic_to_shared(fsm);
    const float* sbias = (const float*)(fsm + FA_BIAS);
    int tid = threadIdx.x, wid = tid >> 5, lane = tid & 31;
    int g = lane >> 2, tig = lane & 3;
    int bhid = blockIdx.y; int b = bhid >> 4, h = bhid & 15;
    int q0 = blockIdx.x * BQ;
    int row0 = wid * 16;

    int ntile = causal ? ((Pv + q0 + BQ + 63) >> 6) : NKT;
    int lastk = Pv + q0 + row0 + 15;

    const __nv_bfloat16* msrc[4] = {kh, kl, vh, vl};
    const __nv_bfloat16* psrc[4] = {pkh, pkl, pvh, pvl};
    int rk = tid >> 3, ck = tid & 7;

    #pragma unroll
    for (int i = 0; i < 8; i++) {
        int arr = i >> 2;
        int r = rk + (i & 3) * 32;
        unsigned dst = sb + (arr ? FA_QLO : 0) + r * 128 + (((ck ^ (r & 7))) << 4);
        const __nv_bfloat16* src = (arr ? qlo_ : qh) +
            ((size_t)(b * Lv + q0 + r) * qstride + h * HDv + ck * 8);
        CPA16(dst, src);
    }
    if (causal) CPA16(sb + FA_BIAS + tid * 16, biasTab + h * 1024 + tid * 4);

#define FA_STAGE(t, bufb) do {                                                   \
    int tb_ = (t) * 64;                                                          \
    _Pragma("unroll")                                                            \
    for (int a_ = 0; a_ < 4; a_++) {                                             \
        _Pragma("unroll")                                                        \
        for (int i2 = 0; i2 < 2; i2++) {                                         \
            int r = rk + i2 * 32;                                                \
            unsigned dst = sb + FA_KV + (unsigned)(bufb) * 32768 + a_ * 8192     \
                           + r * 128 + ((ck ^ (r & 7)) << 4);                    \
            int gk = tb_ + r;                                                    \
            const __nv_bfloat16* src;                                            \
            if (gk < Pv)                                                         \
                src = psrc[a_] + ((((size_t)(b * 2 + sel) * Pv + gk) * Hv + h) * HDv + ck * 8); \
            else                                                                 \
                src = msrc[a_] + ((size_t)(b * Lv + (gk < KTOT ? gk - Pv : 0)) * kvstride + h * HDv + ck * 8); \
            if (gk < KTOT) { CPA16(dst, src); } else { CPA16Z(dst, src); }       \
        }                                                                        \
    }                                                                            \
    asm volatile("cp.async.commit_group;");                                      \
} while (0)

    FA_STAGE(0, 0);
    if (ntile > 1) FA_STAGE(1, 1);

    unsigned qhF[4][4], qlF[4][4];
    float S[8][4], O[8][4];
    #pragma unroll
    for (int i = 0; i < 8; i++) { O[i][0]=0.f; O[i][1]=0.f; O[i][2]=0.f; O[i][3]=0.f; }
    float m_lo = -1e30f, m_hi = -1e30f, l_lo = 0.f, l_hi = 0.f;
    int qrow_lo = q0 + row0 + g, qrow_hi = qrow_lo + 8;

    for (int t = 0; t < ntile; t++) {
        if (t + 1 < ntile) asm volatile("cp.async.wait_group 1;");
        else               asm volatile("cp.async.wait_group 0;");
        __syncthreads();

        if (t == 0) {
            int lrow = row0 + (lane & 15);
            int cb = lane >> 4;
            #pragma unroll
            for (int ks = 0; ks < 4; ks++) {
                int ch = (ks * 2 + cb) ^ (lrow & 7);
                unsigned a = sb + lrow * 128 + (ch << 4);
                LDSM4(qhF[ks][0], qhF[ks][1], qhF[ks][2], qhF[ks][3], a);
                LDSM4(qlF[ks][0], qlF[ks][1], qlF[ks][2], qlF[ks][3], a + FA_QLO);
            }
        }

        bool act = causal ? (t * 64 <= lastk) : true;
        if (act) {
            unsigned kvb = sb + FA_KV + (unsigned)(t & 1) * 32768;
            #pragma unroll
            for (int i = 0; i < 8; i++) { S[i][0]=0.f; S[i][1]=0.f; S[i][2]=0.f; S[i][3]=0.f; }

            int krow = ((lane >> 4) << 3) + (lane & 7);
            int kcb = (lane >> 3) & 1;
            #pragma unroll
            for (int ks = 0; ks < 4; ks++) {
                #pragma unroll
                for (int j = 0; j < 4; j++) {
                    int kr = j * 16 + krow;
                    int ch = (ks * 2 + kcb) ^ (kr & 7);
                    unsigned ka = kvb + kr * 128 + (ch << 4);
                    unsigned bh_[4], bl_[4];
                    LDSM4(bh_[0], bh_[1], bh_[2], bh_[3], ka);
                    LDSM4(bl_[0], bl_[1], bl_[2], bl_[3], ka + 8192);
                    mma16816(S[2*j],   qhF[ks], bh_);
                    mma16816(S[2*j+1], qhF[ks], bh_ + 2);
                    mma16816(S[2*j],   qhF[ks], bl_);
                    mma16816(S[2*j+1], qhF[ks], bl_ + 2);
                    mma16816(S[2*j],   qlF[ks], bh_);
                    mma16816(S[2*j+1], qlF[ks], bh_ + 2);
                }
            }

            int tb = t * 64;
            #pragma unroll
            for (int nt = 0; nt < 8; nt++) {
                #pragma unroll
                for (int u = 0; u < 2; u++) {
                    int key = tb + nt * 8 + 2 * tig + u;
                    if (key >= KTOT) { S[nt][u] = -1e10f; S[nt][2+u] = -1e10f; }
                    else if (causal) {
                        int kp = key - Pv;
                        if (kp >= 0) {
                            if (kp > qrow_lo) S[nt][u]   = -1e10f; else S[nt][u]   += sbias[qrow_lo - kp];
                            if (kp > qrow_hi) S[nt][2+u] = -1e10f; else S[nt][2+u] += sbias[qrow_hi - kp];
                        }
                    }
                }
            }

            float tm0 = -1e30f, tm1 = -1e30f;
            #pragma unroll
            for (int nt = 0; nt < 8; nt++) {
                tm0 = fmaxf(tm0, fmaxf(S[nt][0], S[nt][1]));
                tm1 = fmaxf(tm1, fmaxf(S[nt][2], S[nt][3]));
            }
            tm0 = fmaxf(tm0, __shfl_xor_sync(0xffffffffu, tm0, 1));
            tm0 = fmaxf(tm0, __shfl_xor_sync(0xffffffffu, tm0, 2));
            tm1 = fmaxf(tm1, __shfl_xor_sync(0xffffffffu, tm1, 1));
            tm1 = fmaxf(tm1, __shfl_xor_sync(0xffffffffu, tm1, 2));
            float mn0 = fmaxf(m_lo, tm0), mn1 = fmaxf(m_hi, tm1);
            float c0 = __expf(m_lo - mn0), c1 = __expf(m_hi - mn1);
            m_lo = mn0; m_hi = mn1;
            float s0 = 0.f, s1 = 0.f;
            #pragma unroll
            for (int nt = 0; nt < 8; nt++) {
                S[nt][0] = __expf(S[nt][0] - mn0); s0 += S[nt][0];
                S[nt][1] = __expf(S[nt][1] - mn0); s0 += S[nt][1];
                S[nt][2] = __expf(S[nt][2] - mn1); s1 += S[nt][2];
                S[nt][3] = __expf(S[nt][3] - mn1); s1 += S[nt][3];
            }
            s0 += __shfl_xor_sync(0xffffffffu, s0, 1);
            s0 += __shfl_xor_sync(0xffffffffu, s0, 2);
            s1 += __shfl_xor_sync(0xffffffffu, s1, 1);
            s1 += __shfl_xor_sync(0xffffffffu, s1, 2);
            l_lo = l_lo * c0 + s0; l_hi = l_hi * c1 + s1;
            #pragma unroll
            for (int nt = 0; nt < 8; nt++) {
                O[nt][0] *= c0; O[nt][1] *= c0; O[nt][2] *= c1; O[nt][3] *= c1;
            }

            int vrow = ((lane >> 3) & 1) * 8 + (lane & 7);
            int vcb = lane >> 4;
            #pragma unroll
            for (int ks = 0; ks < 4; ks++) {
                unsigned pah[4], pal[4];
                split2(S[2*ks][0],   S[2*ks][1],   pah[0], pal[0]);
                split2(S[2*ks][2],   S[2*ks][3],   pah[1], pal[1]);
                split2(S[2*ks+1][0], S[2*ks+1][1], pah[2], pal[2]);
                split2(S[2*ks+1][2], S[2*ks+1][3], pah[3], pal[3]);
                int vr = ks * 16 + vrow;
                #pragma unroll
                for (int j = 0; j < 4; j++) {
                    int ch = (2*j + vcb) ^ (vr & 7);
                    unsigned va = kvb + 16384 + vr * 128 + (ch << 4);
                    unsigned bh_[4], bl_[4];
                    LDSM4T(bh_[0], bh_[1], bh_[2], bh_[3], va);
                    LDSM4T(bl_[0], bl_[1], bl_[2], bl_[3], va + 8192);
                    mma16816(O[2*j],   pah, bh_);
                    mma16816(O[2*j+1], pah, bh_ + 2);
                    mma16816(O[2*j],   pah, bl_);
                    mma16816(O[2*j+1], pah, bl_ + 2);
                    mma16816(O[2*j],   pal, bh_);
                    mma16816(O[2*j+1], pal, bh_ + 2);
                }
            }
        }
        __syncthreads();
        if (t + 2 < ntile) FA_STAGE(t + 2, t & 1);
    }
#undef FA_STAGE

    float inv0 = 1.f / l_lo, inv1 = 1.f / l_hi;
    size_t base_lo = ((size_t)(b * Lv + qrow_lo) * Hv + h) * HDv + 2 * tig;
    size_t base_hi = ((size_t)(b * Lv + qrow_hi) * Hv + h) * HDv + 2 * tig;
    #pragma unroll
    for (int nt = 0; nt < 8; nt++) {
        unsigned h01, l01, h23, l23;
        split2(O[nt][0] * inv0, O[nt][1] * inv0, h01, l01);
        split2(O[nt][2] * inv1, O[nt][3] * inv1, h23, l23);
        *(unsigned*)&obh[base_lo + nt * 8] = h01;
        *(unsigned*)&obl[base_lo + nt * 8] = l01;
        *(unsigned*)&obh[base_hi + nt * 8] = h23;
        *(unsigned*)&obl[base_hi + nt * 8] = l23;
    }
}

// ---------------- per-example adapter -----------------------------------------
// adapter_down: 4 l-rows per block; wd value reused across rows.
#define TLD 4
__global__ __launch_bounds__(256) void adapter_down(
    const float* __restrict__ lz, const float* __restrict__ wd,
    const float* __restrict__ bd, float* __restrict__ az)
{
    __shared__ float part[4][TLD][Av];
    int b = blockIdx.y, l0 = blockIdx.x * TLD;
    int a = threadIdx.x & 63, kg = threadIdx.x >> 6;
    const float* xr = lz + (size_t)(b * Lv + l0) * Dv + kg * 256;
    const float* wb = wd + (size_t)b * Dv * Av + (size_t)kg * 256 * Av + a;
    float s[TLD];
    #pragma unroll
    for (int r = 0; r < TLD; r++) s[r] = 0.f;
    #pragma unroll 4
    for (int dd = 0; dd < 256; dd++) {
        float w = wb[(size_t)dd * Av];
        #pragma unroll
        for (int r = 0; r < TLD; r++) s[r] += xr[(size_t)r * Dv + dd] * w;
    }
    #pragma unroll
    for (int r = 0; r < TLD; r++) part[kg][r][a] = s[r];
    __syncthreads();
    {
        int rr = threadIdx.x >> 6, aa = threadIdx.x & 63;   // 256 = TLD*Av outputs
        float t = part[0][rr][aa] + part[1][rr][aa]
                + part[2][rr][aa] + part[3][rr][aa]
                + bd[b * Av + aa];
        az[(size_t)(b * Lv + l0 + rr) * Av + aa] = gelu_f(t);
    }
}

// adapter_up: 8 l-rows per block; wu value reused across rows.
#define TLU 8
__global__ __launch_bounds__(256) void adapter_up(
    const float* __restrict__ az, const float* __restrict__ wu,
    const float* __restrict__ bu, float* __restrict__ out)
{
    int b = blockIdx.y, l0 = blockIdx.x * TLU;
    __shared__ float ash[TLU][Av];
    int tid = threadIdx.x;
    for (int i = tid; i < TLU * Av; i += 256)
        ash[i >> 6][i & 63] = az[(size_t)(b * Lv + l0 + (i >> 6)) * Av + (i & 63)];
    __syncthreads();
    const float* wb = wu + (size_t)b * Av * Dv;
    for (int dd = tid; dd < Dv; dd += 256) {
        float bb = bu[b * Dv + dd];
        float s[TLU];
        #pragma unroll
        for (int r = 0; r < TLU; r++) s[r] = bb;
        #pragma unroll 8
        for (int a = 0; a < Av; a++) {
            float w = wb[(size_t)a * Dv + dd];
            #pragma unroll
            for (int r = 0; r < TLU; r++) s[r] += ash[r][a] * w;
        }
        #pragma unroll
        for (int r = 0; r < TLU; r++)
            out[(size_t)(b * Lv + l0 + r) * Dv + dd] += s[r];
    }
}

// ---------------- driver -------------------------------------------------------
extern "C" void kernel_launch(void* const* d_in, const int* in_sizes, int n_in,
                              void* d_out, int out_size)
{
    const float* inputs  = (const float*)d_in[0];
    const float* encoded = (const float*)d_in[1];
    const float* awd     = (const float*)d_in[2];
    const float* awu     = (const float*)d_in[3];
    const float* abd     = (const float*)d_in[4];
    const float* abu     = (const float*)d_in[5];
    const float* pk      = (const float*)d_in[6];
    const float* pvv     = (const float*)d_in[7];
    const float* ln1     = (const float*)d_in[8];
    const float* ln2     = (const float*)d_in[9];
    const float* ln3     = (const float*)d_in[10];
    const float* sa_wq   = (const float*)d_in[11];
    const float* sa_wk   = (const float*)d_in[12];
    const float* sa_wv   = (const float*)d_in[13];
    const float* sa_wo   = (const float*)d_in[14];
    const float* ca_wq   = (const float*)d_in[15];
    const float* ca_wk   = (const float*)d_in[16];
    const float* ca_wv   = (const float*)d_in[17];
    const float* ca_wo   = (const float*)d_in[18];
    const float* relpos  = (const float*)d_in[19];
    const float* wi0     = (const float*)d_in[20];
    const float* wi1     = (const float*)d_in[21];
    const float* wo_mlp  = (const float*)d_in[22];
    float* out = (float*)d_out;

    float *xn, *x, *y, *h0, *az, *bias;
    __nv_bfloat16 *xnh, *xnl, *ench, *encl, *atth, *attl, *h1h, *h1l, *wth, *wtl;
    __nv_bfloat16 *qkvh, *qkvl, *ckvh, *ckvl, *cqh, *cql, *pkh, *pkl, *pvh, *pvl;
    cudaGetSymbolAddress((void**)&xn,   g_xn);
    cudaGetSymbolAddress((void**)&xnh,  g_xnh);
    cudaGetSymbolAddress((void**)&xnl,  g_xnl);
    cudaGetSymbolAddress((void**)&ench, g_ench);
    cudaGetSymbolAddress((void**)&encl, g_encl);
    cudaGetSymbolAddress((void**)&atth, g_atth);
    cudaGetSymbolAddress((void**)&attl, g_attl);
    cudaGetSymbolAddress((void**)&qkvh, g_qkvh);
    cudaGetSymbolAddress((void**)&qkvl, g_qkvl);
    cudaGetSymbolAddress((void**)&ckvh, g_ckvh);
    cudaGetSymbolAddress((void**)&ckvl, g_ckvl);
    cudaGetSymbolAddress((void**)&cqh,  g_cqh);
    cudaGetSymbolAddress((void**)&cql,  g_cql);
    cudaGetSymbolAddress((void**)&pkh,  g_pkh);
    cudaGetSymbolAddress((void**)&pkl,  g_pkl);
    cudaGetSymbolAddress((void**)&pvh,  g_pvh);
    cudaGetSymbolAddress((void**)&pvl,  g_pvl);
    cudaGetSymbolAddress((void**)&bias, g_bias);
    cudaGetSymbolAddress((void**)&x,    g_x);
    cudaGetSymbolAddress((void**)&y,    g_y);
    cudaGetSymbolAddress((void**)&h0,   g_h0);
    cudaGetSymbolAddress((void**)&h1h,  g_h1h);
    cudaGetSymbolAddress((void**)&h1l,  g_h1l);
    cudaGetSymbolAddress((void**)&az,   g_az);
    cudaGetSymbolAddress((void**)&wth,  g_wth);
    cudaGetSymbolAddress((void**)&wtl,  g_wtl);

    cudaFuncSetAttribute(fattn_kernel, cudaFuncAttributeMaxDynamicSharedMemorySize, FA_SMEM);
    cudaFuncSetAttribute(tgemm_kernel, cudaFuncAttributeMaxDynamicSharedMemorySize, TG_SMEM);

    const int M = Bv * Lv;
    dim3 g8(8, 32), g16(16, 32), g22(22, 32), g24(24, 32);
    dim3 ga(Lv / BQ, Bv * Hv);
    dim3 tsq(32, 32), tswi(88, 32), tswo(32, 88);

    // ---- fork a side stream into the capture ----
    cudaStream_t s1;
    cudaStreamCreateWithFlags(&s1, cudaStreamNonBlocking);
    cudaEvent_t evFork, evA, evSo, evPfx, evCq, evCkv, evCo, evW, evRn3, evAd;
    cudaEventCreateWithFlags(&evFork, cudaEventDisableTiming);
    cudaEventCreateWithFlags(&evA,    cudaEventDisableTiming);
    cudaEventCreateWithFlags(&evSo,   cudaEventDisableTiming);
    cudaEventCreateWithFlags(&evPfx,  cudaEventDisableTiming);
    cudaEventCreateWithFlags(&evCq,   cudaEventDisableTiming);
    cudaEventCreateWithFlags(&evCkv,  cudaEventDisableTiming);
    cudaEventCreateWithFlags(&evCo,   cudaEventDisableTiming);
    cudaEventCreateWithFlags(&evW,    cudaEventDisableTiming);
    cudaEventCreateWithFlags(&evRn3,  cudaEventDisableTiming);
    cudaEventCreateWithFlags(&evAd,   cudaEventDisableTiming);

    cudaEventRecord(evFork, 0);
    cudaStreamWaitEvent(s1, evFork, 0);

    // ---- side stream: input-only work (conversions + cross-KV GEMM) ----
    tsplit_kernel<<<tsq, 256, 0, s1>>>(sa_wq, wth + O_SAWQ, wtl + O_SAWQ, 1024, 1024, 0.125f);
    tsplit_kernel<<<tsq, 256, 0, s1>>>(sa_wk, wth + O_SAWK, wtl + O_SAWK, 1024, 1024, 1.f);
    tsplit_kernel<<<tsq, 256, 0, s1>>>(sa_wv, wth + O_SAWV, wtl + O_SAWV, 1024, 1024, 1.f);
    cudaEventRecord(evA, s1);
    split_kernel<<<(PFXN / 4 + 255) / 256, 256, 0, s1>>>(pk,  pkh, pkl, PFXN / 4);
    split_kernel<<<(PFXN / 4 + 255) / 256, 256, 0, s1>>>(pvv, pvh, pvl, PFXN / 4);
    bias_build<<<dim3(Hv, 4), 256, 0, s1>>>(relpos, bias);
    cudaEventRecord(evPfx, s1);
    tsplit_kernel<<<tsq, 256, 0, s1>>>(sa_wo, wth + O_SAWO, wtl + O_SAWO, 1024, 1024, 1.f);
    cudaEventRecord(evSo, s1);
    tsplit_kernel<<<tsq, 256, 0, s1>>>(ca_wq, wth + O_CAWQ, wtl + O_CAWQ, 1024, 1024, 0.125f);
    cudaEventRecord(evCq, s1);
    split_kernel<<<(M * Dv / 4 + 255) / 256, 256, 0, s1>>>(encoded, ench, encl, M * Dv / 4);
    tsplit_kernel<<<tsq, 256, 0, s1>>>(ca_wk, wth + O_CAWK, wtl + O_CAWK, 1024, 1024, 1.f);
    tsplit_kernel<<<tsq, 256, 0, s1>>>(ca_wv, wth + O_CAWV, wtl + O_CAWV, 1024, 1024, 1.f);
    tgemm_kernel<<<g16, 256, TG_SMEM, s1>>>(ench, encl, wth + O_CAWK, wtl + O_CAWK,
                                            nullptr, ckvh, ckvl, M, 2048, 1024, nullptr, nullptr);
    cudaEventRecord(evCkv, s1);
    tsplit_kernel<<<tsq, 256, 0, s1>>>(ca_wo, wth + O_CAWO, wtl + O_CAWO, 1024, 1024, 1.f);
    cudaEventRecord(evCo, s1);
    tsplit_kernel<<<tswi, 256, 0, s1>>>(wi0, wth + O_WI0, wtl + O_WI0, 1024, 2816, 1.f);
    tsplit_kernel<<<tswi, 256, 0, s1>>>(wi1, wth + O_WI1, wtl + O_WI1, 1024, 2816, 1.f);
    tsplit_kernel<<<tswo, 256, 0, s1>>>(wo_mlp, wth + O_WO, wtl + O_WO, 2816, 1024, 1.f);
    cudaEventRecord(evW, s1);

    // ---- main stream: critical path (up to rmsnorm3) ----
    rmsnorm_kernel<<<M, 256>>>(inputs, ln1, nullptr, xnh, xnl);
    cudaStreamWaitEvent(0, evA, 0);
    tgemm_kernel<<<g24, 256, TG_SMEM>>>(xnh, xnl, wth + O_SAWQ, wtl + O_SAWQ,
                                        nullptr, qkvh, qkvl, M, 3072, 1024, nullptr, nullptr);
    cudaStreamWaitEvent(0, evPfx, 0);
    fattn_kernel<<<ga, 256, FA_SMEM>>>(qkvh, qkvl, qkvh + 1024, qkvl + 1024,
                                       qkvh + 2048, qkvl + 2048, 3072, 3072,
                                       pkh, pkl, pvh, pvl, bias, atth, attl, 0, 1);
    cudaStreamWaitEvent(0, evSo, 0);
    tgemm_kernel<<<g8, 256, TG_SMEM>>>(atth, attl, wth + O_SAWO, wtl + O_SAWO,
                                       x, nullptr, nullptr, M, 1024, 1024, inputs, nullptr);

    rmsnorm_kernel<<<M, 256>>>(x, ln2, nullptr, xnh, xnl);
    cudaStreamWaitEvent(0, evCq, 0);
    tgemm_kernel<<<g8, 256, TG_SMEM>>>(xnh, xnl, wth + O_CAWQ, wtl + O_CAWQ,
                                       nullptr, cqh, cql, M, 1024, 1024, nullptr, nullptr);
    cudaStreamWaitEvent(0, evCkv, 0);
    fattn_kernel<<<ga, 256, FA_SMEM>>>(cqh, cql, ckvh, ckvl,
                                       ckvh + 1024, ckvl + 1024, 1024, 2048,
                                       pkh, pkl, pvh, pvl, bias, atth, attl, 1, 0);
    cudaStreamWaitEvent(0, evCo, 0);
    tgemm_kernel<<<g8, 256, TG_SMEM>>>(atth, attl, wth + O_CAWO, wtl + O_CAWO,
                                       y, nullptr, nullptr, M, 1024, 1024, x, nullptr);

    rmsnorm_kernel<<<M, 256>>>(y, ln3, xn, xnh, xnl);
    cudaEventRecord(evRn3, 0);

    // ---- side stream: adapter_down (issued AFTER evRn3 is recorded on host) --
    cudaStreamWaitEvent(s1, evRn3, 0);
    adapter_down<<<dim3(Lv / TLD, Bv), 256, 0, s1>>>(xn, awd, abd, az);
    cudaEventRecord(evAd, s1);

    // ---- main stream: MLP + join ----
    cudaStreamWaitEvent(0, evW, 0);
    tgemm_kernel<<<g22, 256, TG_SMEM>>>(xnh, xnl, wth + O_WI0, wtl + O_WI0,
                                        h0, nullptr, nullptr, M, Fv, 1024, nullptr, nullptr);
    tgemm_kernel<<<g22, 256, TG_SMEM>>>(xnh, xnl, wth + O_WI1, wtl + O_WI1,
                                        nullptr, h1h, h1l, M, Fv, 1024, nullptr, h0);
    tgemm_kernel<<<g8, 256, TG_SMEM>>>(h1h, h1l, wth + O_WO, wtl + O_WO,
                                       out, nullptr, nullptr, M, 1024, Fv, y, nullptr);
    cudaStreamWaitEvent(0, evAd, 0);
    adapter_up<<<dim3(Lv / TLU, Bv), 256>>>(az, awu, abu, out);
}

// round 17
// speedup vs baseline: 2.2554x; 1.0098x over previous
#include <cuda_runtime.h>
#include <cuda_bf16.h>
#include <math.h>

#define Bv 4
#define Lv 1024
#define Dv 1024
#define Hv 16
#define HDv 64
#define Fv 2816
#define Av 64
#define Pv 30
#define KTOT (Pv + Lv)
#define NKT 17
#define BQ 128

#define NSQ (1024*1024)
#define NWI (1024*2816)
#define O_SAWQ ((size_t)0)
#define O_SAWK ((size_t)1*NSQ)
#define O_SAWV ((size_t)2*NSQ)
#define O_SAWO ((size_t)3*NSQ)
#define O_CAWQ ((size_t)4*NSQ)
#define O_CAWK ((size_t)5*NSQ)
#define O_CAWV ((size_t)6*NSQ)
#define O_CAWO ((size_t)7*NSQ)
#define O_WI0  ((size_t)8*NSQ)
#define O_WI1  (O_WI0 + NWI)
#define O_WO   (O_WI1 + NWI)
#define W_TOT  (O_WO + NWI)
#define PFXN   (Bv*2*Pv*Hv*HDv)

// ---------------- scratch ----------------------------------------------------
__device__ float g_xn[Bv*Lv*Dv];
__device__ __nv_bfloat16 g_xnh[Bv*Lv*Dv], g_xnl[Bv*Lv*Dv];
__device__ __nv_bfloat16 g_ench[Bv*Lv*Dv], g_encl[Bv*Lv*Dv];
__device__ __nv_bfloat16 g_atth[Bv*Lv*Dv], g_attl[Bv*Lv*Dv];
__device__ __nv_bfloat16 g_qkvh[Bv*Lv*3*Dv], g_qkvl[Bv*Lv*3*Dv];
__device__ __nv_bfloat16 g_ckvh[Bv*Lv*2*Dv], g_ckvl[Bv*Lv*2*Dv];
__device__ __nv_bfloat16 g_cqh[Bv*Lv*Dv], g_cql[Bv*Lv*Dv];
__device__ __nv_bfloat16 g_pkh[PFXN], g_pkl[PFXN], g_pvh[PFXN], g_pvl[PFXN];
__device__ float g_bias[Hv*1024];
__device__ float g_x [Bv*Lv*Dv];
__device__ float g_y [Bv*Lv*Dv];
__device__ float g_h0[Bv*Lv*Fv];
__device__ __nv_bfloat16 g_h1h[Bv*Lv*Fv], g_h1l[Bv*Lv*Fv];
__device__ float g_az[Bv*Lv*Av];
__device__ float g_adout[Bv*Lv*Dv];
__device__ __nv_bfloat16 g_wth[W_TOT], g_wtl[W_TOT];

__device__ __forceinline__ float gelu_f(float x) {
    float x3 = x * x * x;
    return 0.5f * x * (1.0f + tanhf(0.7978845608028654f * (x + 0.044715f * x3)));
}

__device__ __forceinline__ void split1(float f, __nv_bfloat16& h, __nv_bfloat16& l) {
    h = __float2bfloat16(f);
    l = __float2bfloat16(f - __bfloat162float(h));
}

__device__ __forceinline__ void split2(float f0, float f1, unsigned &hi, unsigned &lo) {
    __nv_bfloat162 h = __floats2bfloat162_rn(f0, f1);
    float r0 = f0 - __bfloat162float(h.x);
    float r1 = f1 - __bfloat162float(h.y);
    __nv_bfloat162 l = __floats2bfloat162_rn(r0, r1);
    hi = *reinterpret_cast<unsigned*>(&h);
    lo = *reinterpret_cast<unsigned*>(&l);
}

__device__ __forceinline__ void mma16816(float* c, const unsigned* a, const unsigned* b) {
    asm volatile(
        "mma.sync.aligned.m16n8k16.row.col.f32.bf16.bf16.f32 "
        "{%0,%1,%2,%3}, {%4,%5,%6,%7}, {%8,%9}, {%0,%1,%2,%3};\n"
        : "+f"(c[0]), "+f"(c[1]), "+f"(c[2]), "+f"(c[3])
        : "r"(a[0]), "r"(a[1]), "r"(a[2]), "r"(a[3]), "r"(b[0]), "r"(b[1]));
}

#define LDSM4(r0,r1,r2,r3,a) \
    asm volatile("ldmatrix.sync.aligned.m8n8.x4.shared.b16 {%0,%1,%2,%3}, [%4];" \
        : "=r"(r0),"=r"(r1),"=r"(r2),"=r"(r3) : "r"(a))
#define LDSM4T(r0,r1,r2,r3,a) \
    asm volatile("ldmatrix.sync.aligned.m8n8.x4.trans.shared.b16 {%0,%1,%2,%3}, [%4];" \
        : "=r"(r0),"=r"(r1),"=r"(r2),"=r"(r3) : "r"(a))
#define CPA16(dst, src) \
    asm volatile("cp.async.cg.shared.global [%0], [%1], 16;" :: "r"(dst), "l"(src))
#define CPA16Z(dst, src) \
    asm volatile("cp.async.cg.shared.global [%0], [%1], 16, 0;" :: "r"(dst), "l"(src))

// ---------------- conversions -------------------------------------------------
__global__ __launch_bounds__(256) void split_kernel(
    const float* __restrict__ in, __nv_bfloat16* __restrict__ hi,
    __nv_bfloat16* __restrict__ lo, int n4)
{
    int i = blockIdx.x * 256 + threadIdx.x;
    if (i >= n4) return;
    float4 v = *(const float4*)&in[(size_t)i * 4];
    __nv_bfloat16 h[4], l[4];
    split1(v.x, h[0], l[0]); split1(v.y, h[1], l[1]);
    split1(v.z, h[2], l[2]); split1(v.w, h[3], l[3]);
    *(uint2*)&hi[(size_t)i * 4] = *(uint2*)h;
    *(uint2*)&lo[(size_t)i * 4] = *(uint2*)l;
}

__global__ __launch_bounds__(256) void tsplit_kernel(
    const float* __restrict__ W, __nv_bfloat16* __restrict__ th,
    __nv_bfloat16* __restrict__ tl, int K, int N, float scale)
{
    __shared__ float tile[32][33];
    int n0 = blockIdx.x * 32, k0 = blockIdx.y * 32;
    int tx = threadIdx.x & 31, ty = threadIdx.x >> 5;
    #pragma unroll
    for (int j = 0; j < 4; j++)
        tile[ty + 8*j][tx] = W[(size_t)(k0 + ty + 8*j) * N + n0 + tx];
    __syncthreads();
    #pragma unroll
    for (int j = 0; j < 4; j++) {
        float v = tile[tx][ty + 8*j] * scale;
        __nv_bfloat16 h, l;
        split1(v, h, l);
        size_t idx = (size_t)(n0 + ty + 8*j) * K + k0 + tx;
        th[idx] = h; tl[idx] = l;
    }
}

__global__ __launch_bounds__(256) void bias_build(
    const float* __restrict__ relpos, float* __restrict__ tab)
{
    int h = blockIdx.x;
    int r = blockIdx.y * 256 + threadIdx.x;
    int bkt;
    if (r < 16) bkt = r;
    else {
        bkt = 16 + (int)(logf((float)r * 0.0625f) * (16.0f / 2.0794415416798357f));
        if (bkt > 31) bkt = 31;
    }
    tab[h * 1024 + r] = relpos[h * 32 + bkt];
}

// ---------------- RMSNorm -----------------------------------------------------
__global__ __launch_bounds__(256) void rmsnorm_kernel(
    const float* __restrict__ x, const float* __restrict__ w,
    float* __restrict__ of32, __nv_bfloat16* __restrict__ ohi,
    __nv_bfloat16* __restrict__ olo)
{
    int row = blockIdx.x;
    const float* xr = x + (size_t)row * Dv;
    int tid = threadIdx.x;
    int d0 = tid * 4;
    float4 v = *(const float4*)&xr[d0];
    float s = v.x*v.x + v.y*v.y + v.z*v.z + v.w*v.w;
    #pragma unroll
    for (int off = 16; off; off >>= 1) s += __shfl_xor_sync(0xffffffffu, s, off);
    __shared__ float red[8];
    __shared__ float inv_s;
    if ((tid & 31) == 0) red[tid >> 5] = s;
    __syncthreads();
    if (tid == 0) {
        float t = 0.f;
        #pragma unroll
        for (int i = 0; i < 8; i++) t += red[i];
        inv_s = rsqrtf(t * (1.0f / Dv) + 1e-6f);
    }
    __syncthreads();
    float inv = inv_s;
    float4 wv = *(const float4*)&w[d0];
    float r[4];
    r[0] = v.x*inv*wv.x; r[1] = v.y*inv*wv.y; r[2] = v.z*inv*wv.z; r[3] = v.w*inv*wv.w;
    size_t o = (size_t)row * Dv + d0;
    if (of32) { float4 rr; rr.x=r[0]; rr.y=r[1]; rr.z=r[2]; rr.w=r[3]; *(float4*)&of32[o] = rr; }
    __nv_bfloat16 h[4], l[4];
    #pragma unroll
    for (int i = 0; i < 4; i++) split1(r[i], h[i], l[i]);
    *(uint2*)&ohi[o] = *(uint2*)h;
    *(uint2*)&olo[o] = *(uint2*)l;
}

// ---------------- tensor-core GEMM, 3-stage cp.async, 1 sync/tile ------------
#define TG_SEG 4096
#define TG_BUF (4*TG_SEG)
#define TG_SMEM (3*TG_BUF*2)      /* 96 KB */

__device__ __forceinline__ unsigned sw_elem(int row, int c) {
    return (unsigned)(row * 32 + ((c ^ ((row >> 1) & 3)) << 3));
}

__global__ __launch_bounds__(256, 2) void tgemm_kernel(
    const __nv_bfloat16* __restrict__ Ahi, const __nv_bfloat16* __restrict__ Alo,
    const __nv_bfloat16* __restrict__ Bh,  const __nv_bfloat16* __restrict__ Bl,
    float* __restrict__ Cf, __nv_bfloat16* __restrict__ Chi, __nv_bfloat16* __restrict__ Clo,
    int M, int N, int K,
    const float* __restrict__ res, const float* __restrict__ res2,
    const float* __restrict__ gate)
{
    extern __shared__ __align__(16) __nv_bfloat16 tgsm[];
    unsigned sbase = (unsigned)__cvta_generic_to_shared(tgsm);

    int tid  = threadIdx.x;
    int m0   = blockIdx.y * 128;
    int n0   = blockIdx.x * 128;
    int wid  = tid >> 5, lane = tid & 31;
    int g    = lane >> 2, tig = lane & 3;
    int l7   = lane & 7, sub = lane >> 3;
    int wm   = (wid & 1) * 64;
    int wn   = (wid >> 1) * 32;

    float acc[4][4][4];
    #pragma unroll
    for (int i = 0; i < 4; i++)
        #pragma unroll
        for (int j = 0; j < 4; j++)
            #pragma unroll
            for (int r = 0; r < 4; r++) acc[i][j][r] = 0.f;

#define TG_ISSUE(tt, bufb) do {                                                  \
    size_t k0i = (size_t)(tt) * 32;                                              \
    unsigned base = sbase + (unsigned)(bufb) * (TG_BUF * 2);                     \
    _Pragma("unroll")                                                            \
    for (int i_ = 0; i_ < 2; i_++) {                                             \
        int cc = tid + i_ * 256; int row = cc >> 2; int c4 = cc & 3;             \
        unsigned so = sw_elem(row, c4) * 2;                                      \
        size_t ga = (size_t)(m0 + row) * K + k0i + c4 * 8;                       \
        size_t gb = (size_t)(n0 + row) * K + k0i + c4 * 8;                       \
        CPA16(base + so,                 Ahi + ga);                              \
        CPA16(base + TG_SEG*2 + so,      Alo + ga);                              \
        CPA16(base + 2*TG_SEG*2 + so,    Bh + gb);                               \
        CPA16(base + 3*TG_SEG*2 + so,    Bl + gb);                               \
    }                                                                            \
    asm volatile("cp.async.commit_group;");                                      \
} while (0)

    int nk = K >> 5;
    TG_ISSUE(0, 0);
    if (nk > 1) TG_ISSUE(1, 1);

    int buf = 0;
    for (int t = 0; t < nk; t++) {
        if (t + 1 < nk) asm volatile("cp.async.wait_group 1;");
        else            asm volatile("cp.async.wait_group 0;");
        __syncthreads();

        if (t + 2 < nk) {
            int nb = buf + 2; if (nb >= 3) nb -= 3;
            TG_ISSUE(t + 2, nb);
        }

        unsigned bufo = sbase + (unsigned)buf * (TG_BUF * 2);
        #pragma unroll
        for (int ks = 0; ks < 2; ks++) {
            unsigned bh_[8], bl_[8];
            #pragma unroll
            for (int p = 0; p < 2; p++) {
                int nrow = wn + p * 16 + ((sub >> 1) << 3) + l7;
                int cB = ks * 2 + (sub & 1);
                unsigned ab = bufo + 2 * TG_SEG * 2 + sw_elem(nrow, cB) * 2;
                LDSM4(bh_[4*p+0], bh_[4*p+1], bh_[4*p+2], bh_[4*p+3], ab);
                LDSM4(bl_[4*p+0], bl_[4*p+1], bl_[4*p+2], bl_[4*p+3], ab + TG_SEG * 2);
            }
            #pragma unroll
            for (int mt = 0; mt < 4; mt++) {
                int arow = wm + mt * 16 + ((sub & 1) << 3) + l7;
                int cA = ks * 2 + (sub >> 1);
                unsigned aa = bufo + sw_elem(arow, cA) * 2;
                unsigned ah[4], al[4];
                LDSM4(ah[0], ah[1], ah[2], ah[3], aa);
                LDSM4(al[0], al[1], al[2], al[3], aa + TG_SEG * 2);
                #pragma unroll
                for (int nt = 0; nt < 4; nt++)
                    mma16816(acc[mt][nt], ah, &bh_[nt * 2]);
                #pragma unroll
                for (int nt = 0; nt < 4; nt++)
                    mma16816(acc[mt][nt], ah, &bl_[nt * 2]);
                #pragma unroll
                for (int nt = 0; nt < 4; nt++)
                    mma16816(acc[mt][nt], al, &bh_[nt * 2]);
            }
        }
        if (++buf == 3) buf = 0;
    }
#undef TG_ISSUE

    #pragma unroll
    for (int mt = 0; mt < 4; mt++) {
        #pragma unroll
        for (int half = 0; half < 2; half++) {
            int m = m0 + wm + mt * 16 + g + half * 8;
            #pragma unroll
            for (int nt = 0; nt < 4; nt++) {
                int n = n0 + wn + nt * 8 + 2 * tig;
                size_t idx = (size_t)m * N + n;
                float v0 = acc[mt][nt][half * 2 + 0];
                float v1 = acc[mt][nt][half * 2 + 1];
                if (res) {
                    float2 rv = *(const float2*)&res[idx];
                    v0 += rv.x; v1 += rv.y;
                }
                if (res2) {
                    float2 rv = *(const float2*)&res2[idx];
                    v0 += rv.x; v1 += rv.y;
                }
                if (gate) {
                    float2 gv = *(const float2*)&gate[idx];
                    v0 *= gelu_f(gv.x); v1 *= gelu_f(gv.y);
                }
                if (Cf) {
                    float2 o; o.x = v0; o.y = v1;
                    *(float2*)&Cf[idx] = o;
                } else {
                    unsigned hh, ll;
                    split2(v0, v1, hh, ll);
                    *(unsigned*)&Chi[idx] = hh;
                    *(unsigned*)&Clo[idx] = ll;
                }
            }
        }
    }
}

// ---------------- MMA flash attention (strided q/kv for fused layouts) --------
#define FA_QLO 16384
#define FA_KV  32768
#define FA_BIAS 98304
#define FA_SMEM 102400

__global__ __launch_bounds__(256) void fattn_kernel(
    const __nv_bfloat16* __restrict__ qh, const __nv_bfloat16* __restrict__ qlo_,
    const __nv_bfloat16* __restrict__ kh, const __nv_bfloat16* __restrict__ kl,
    const __nv_bfloat16* __restrict__ vh, const __nv_bfloat16* __restrict__ vl,
    int qstride, int kvstride,
    const __nv_bfloat16* __restrict__ pkh, const __nv_bfloat16* __restrict__ pkl,
    const __nv_bfloat16* __restrict__ pvh, const __nv_bfloat16* __restrict__ pvl,
    const float* __restrict__ biasTab,
    __nv_bfloat16* __restrict__ obh, __nv_bfloat16* __restrict__ obl,
    int sel, int causal)
{
    extern __shared__ __align__(16) char fsm[];
    unsigned sb = (unsigned)__cvta_generic_to_shared(fsm);
    const float* sbias = (const float*)(fsm + FA_BIAS);
    int tid = threadIdx.x, wid = tid >> 5, lane = tid & 31;
    int g = lane >> 2, tig = lane & 3;
    int bhid = blockIdx.y; int b = bhid >> 4, h = bhid & 15;
    // heaviest causal blocks (largest q0) launch first for wave balance
    int q0 = (gridDim.x - 1 - blockIdx.x) * BQ;
    int row0 = wid * 16;

    int ntile = causal ? ((Pv + q0 + BQ + 63) >> 6) : NKT;
    int lastk = Pv + q0 + row0 + 15;

    const __nv_bfloat16* msrc[4] = {kh, kl, vh, vl};
    const __nv_bfloat16* psrc[4] = {pkh, pkl, pvh, pvl};
    int rk = tid >> 3, ck = tid & 7;

    #pragma unroll
    for (int i = 0; i < 8; i++) {
        int arr = i >> 2;
        int r = rk + (i & 3) * 32;
        unsigned dst = sb + (arr ? FA_QLO : 0) + r * 128 + (((ck ^ (r & 7))) << 4);
        const __nv_bfloat16* src = (arr ? qlo_ : qh) +
            ((size_t)(b * Lv + q0 + r) * qstride + h * HDv + ck * 8);
        CPA16(dst, src);
    }
    if (causal) CPA16(sb + FA_BIAS + tid * 16, biasTab + h * 1024 + tid * 4);

#define FA_STAGE(t, bufb) do {                                                   \
    int tb_ = (t) * 64;                                                          \
    _Pragma("unroll")                                                            \
    for (int a_ = 0; a_ < 4; a_++) {                                             \
        _Pragma("unroll")                                                        \
        for (int i2 = 0; i2 < 2; i2++) {                                         \
            int r = rk + i2 * 32;                                                \
            unsigned dst = sb + FA_KV + (unsigned)(bufb) * 32768 + a_ * 8192     \
                           + r * 128 + ((ck ^ (r & 7)) << 4);                    \
            int gk = tb_ + r;                                                    \
            const __nv_bfloat16* src;                                            \
            if (gk < Pv)                                                         \
                src = psrc[a_] + ((((size_t)(b * 2 + sel) * Pv + gk) * Hv + h) * HDv + ck * 8); \
            else                                                                 \
                src = msrc[a_] + ((size_t)(b * Lv + (gk < KTOT ? gk - Pv : 0)) * kvstride + h * HDv + ck * 8); \
            if (gk < KTOT) { CPA16(dst, src); } else { CPA16Z(dst, src); }       \
        }                                                                        \
    }                                                                            \
    asm volatile("cp.async.commit_group;");                                      \
} while (0)

    FA_STAGE(0, 0);
    if (ntile > 1) FA_STAGE(1, 1);

    unsigned qhF[4][4], qlF[4][4];
    float S[8][4], O[8][4];
    #pragma unroll
    for (int i = 0; i < 8; i++) { O[i][0]=0.f; O[i][1]=0.f; O[i][2]=0.f; O[i][3]=0.f; }
    float m_lo = -1e30f, m_hi = -1e30f, l_lo = 0.f, l_hi = 0.f;
    int qrow_lo = q0 + row0 + g, qrow_hi = qrow_lo + 8;

    for (int t = 0; t < ntile; t++) {
        if (t + 1 < ntile) asm volatile("cp.async.wait_group 1;");
        else               asm volatile("cp.async.wait_group 0;");
        __syncthreads();

        if (t == 0) {
            int lrow = row0 + (lane & 15);
            int cb = lane >> 4;
            #pragma unroll
            for (int ks = 0; ks < 4; ks++) {
                int ch = (ks * 2 + cb) ^ (lrow & 7);
                unsigned a = sb + lrow * 128 + (ch << 4);
                LDSM4(qhF[ks][0], qhF[ks][1], qhF[ks][2], qhF[ks][3], a);
                LDSM4(qlF[ks][0], qlF[ks][1], qlF[ks][2], qlF[ks][3], a + FA_QLO);
            }
        }

        bool act = causal ? (t * 64 <= lastk) : true;
        if (act) {
            unsigned kvb = sb + FA_KV + (unsigned)(t & 1) * 32768;
            #pragma unroll
            for (int i = 0; i < 8; i++) { S[i][0]=0.f; S[i][1]=0.f; S[i][2]=0.f; S[i][3]=0.f; }

            int krow = ((lane >> 4) << 3) + (lane & 7);
            int kcb = (lane >> 3) & 1;
            #pragma unroll
            for (int ks = 0; ks < 4; ks++) {
                #pragma unroll
                for (int j = 0; j < 4; j++) {
                    int kr = j * 16 + krow;
                    int ch = (ks * 2 + kcb) ^ (kr & 7);
                    unsigned ka = kvb + kr * 128 + (ch << 4);
                    unsigned bh_[4], bl_[4];
                    LDSM4(bh_[0], bh_[1], bh_[2], bh_[3], ka);
                    LDSM4(bl_[0], bl_[1], bl_[2], bl_[3], ka + 8192);
                    mma16816(S[2*j],   qhF[ks], bh_);
                    mma16816(S[2*j+1], qhF[ks], bh_ + 2);
                    mma16816(S[2*j],   qhF[ks], bl_);
                    mma16816(S[2*j+1], qhF[ks], bl_ + 2);
                    mma16816(S[2*j],   qlF[ks], bh_);
                    mma16816(S[2*j+1], qlF[ks], bh_ + 2);
                }
            }

            int tb = t * 64;
            #pragma unroll
            for (int nt = 0; nt < 8; nt++) {
                #pragma unroll
                for (int u = 0; u < 2; u++) {
                    int key = tb + nt * 8 + 2 * tig + u;
                    if (key >= KTOT) { S[nt][u] = -1e10f; S[nt][2+u] = -1e10f; }
                    else if (causal) {
                        int kp = key - Pv;
                        if (kp >= 0) {
                            if (kp > qrow_lo) S[nt][u]   = -1e10f; else S[nt][u]   += sbias[qrow_lo - kp];
                            if (kp > qrow_hi) S[nt][2+u] = -1e10f; else S[nt][2+u] += sbias[qrow_hi - kp];
                        }
                    }
                }
            }

            float tm0 = -1e30f, tm1 = -1e30f;
            #pragma unroll
            for (int nt = 0; nt < 8; nt++) {
                tm0 = fmaxf(tm0, fmaxf(S[nt][0], S[nt][1]));
                tm1 = fmaxf(tm1, fmaxf(S[nt][2], S[nt][3]));
            }
            tm0 = fmaxf(tm0, __shfl_xor_sync(0xffffffffu, tm0, 1));
            tm0 = fmaxf(tm0, __shfl_xor_sync(0xffffffffu, tm0, 2));
            tm1 = fmaxf(tm1, __shfl_xor_sync(0xffffffffu, tm1, 1));
            tm1 = fmaxf(tm1, __shfl_xor_sync(0xffffffffu, tm1, 2));
            float mn0 = fmaxf(m_lo, tm0), mn1 = fmaxf(m_hi, tm1);
            float c0 = __expf(m_lo - mn0), c1 = __expf(m_hi - mn1);
            m_lo = mn0; m_hi = mn1;
            float s0 = 0.f, s1 = 0.f;
            #pragma unroll
            for (int nt = 0; nt < 8; nt++) {
                S[nt][0] = __expf(S[nt][0] - mn0); s0 += S[nt][0];
                S[nt][1] = __expf(S[nt][1] - mn0); s0 += S[nt][1];
                S[nt][2] = __expf(S[nt][2] - mn1); s1 += S[nt][2];
                S[nt][3] = __expf(S[nt][3] - mn1); s1 += S[nt][3];
            }
            s0 += __shfl_xor_sync(0xffffffffu, s0, 1);
            s0 += __shfl_xor_sync(0xffffffffu, s0, 2);
            s1 += __shfl_xor_sync(0xffffffffu, s1, 1);
            s1 += __shfl_xor_sync(0xffffffffu, s1, 2);
            l_lo = l_lo * c0 + s0; l_hi = l_hi * c1 + s1;
            #pragma unroll
            for (int nt = 0; nt < 8; nt++) {
                O[nt][0] *= c0; O[nt][1] *= c0; O[nt][2] *= c1; O[nt][3] *= c1;
            }

            int vrow = ((lane >> 3) & 1) * 8 + (lane & 7);
            int vcb = lane >> 4;
            #pragma unroll
            for (int ks = 0; ks < 4; ks++) {
                unsigned pah[4], pal[4];
                split2(S[2*ks][0],   S[2*ks][1],   pah[0], pal[0]);
                split2(S[2*ks][2],   S[2*ks][3],   pah[1], pal[1]);
                split2(S[2*ks+1][0], S[2*ks+1][1], pah[2], pal[2]);
                split2(S[2*ks+1][2], S[2*ks+1][3], pah[3], pal[3]);
                int vr = ks * 16 + vrow;
                #pragma unroll
                for (int j = 0; j < 4; j++) {
                    int ch = (2*j + vcb) ^ (vr & 7);
                    unsigned va = kvb + 16384 + vr * 128 + (ch << 4);
                    unsigned bh_[4], bl_[4];
                    LDSM4T(bh_[0], bh_[1], bh_[2], bh_[3], va);
                    LDSM4T(bl_[0], bl_[1], bl_[2], bl_[3], va + 8192);
                    mma16816(O[2*j],   pah, bh_);
                    mma16816(O[2*j+1], pah, bh_ + 2);
                    mma16816(O[2*j],   pah, bl_);
                    mma16816(O[2*j+1], pah, bl_ + 2);
                    mma16816(O[2*j],   pal, bh_);
                    mma16816(O[2*j+1], pal, bh_ + 2);
                }
            }
        }
        __syncthreads();
        if (t + 2 < ntile) FA_STAGE(t + 2, t & 1);
    }
#undef FA_STAGE

    float inv0 = 1.f / l_lo, inv1 = 1.f / l_hi;
    size_t base_lo = ((size_t)(b * Lv + qrow_lo) * Hv + h) * HDv + 2 * tig;
    size_t base_hi = ((size_t)(b * Lv + qrow_hi) * Hv + h) * HDv + 2 * tig;
    #pragma unroll
    for (int nt = 0; nt < 8; nt++) {
        unsigned h01, l01, h23, l23;
        split2(O[nt][0] * inv0, O[nt][1] * inv0, h01, l01);
        split2(O[nt][2] * inv1, O[nt][3] * inv1, h23, l23);
        *(unsigned*)&obh[base_lo + nt * 8] = h01;
        *(unsigned*)&obl[base_lo + nt * 8] = l01;
        *(unsigned*)&obh[base_hi + nt * 8] = h23;
        *(unsigned*)&obl[base_hi + nt * 8] = l23;
    }
}

// ---------------- per-example adapter -----------------------------------------
#define TLD 4
__global__ __launch_bounds__(256) void adapter_down(
    const float* __restrict__ lz, const float* __restrict__ wd,
    const float* __restrict__ bd, float* __restrict__ az)
{
    __shared__ float part[4][TLD][Av];
    int b = blockIdx.y, l0 = blockIdx.x * TLD;
    int a = threadIdx.x & 63, kg = threadIdx.x >> 6;
    const float* xr = lz + (size_t)(b * Lv + l0) * Dv + kg * 256;
    const float* wb = wd + (size_t)b * Dv * Av + (size_t)kg * 256 * Av + a;
    float s[TLD];
    #pragma unroll
    for (int r = 0; r < TLD; r++) s[r] = 0.f;
    #pragma unroll 4
    for (int dd = 0; dd < 256; dd++) {
        float w = wb[(size_t)dd * Av];
        #pragma unroll
        for (int r = 0; r < TLD; r++) s[r] += xr[(size_t)r * Dv + dd] * w;
    }
    #pragma unroll
    for (int r = 0; r < TLD; r++) part[kg][r][a] = s[r];
    __syncthreads();
    {
        int rr = threadIdx.x >> 6, aa = threadIdx.x & 63;
        float t = part[0][rr][aa] + part[1][rr][aa]
                + part[2][rr][aa] + part[3][rr][aa]
                + bd[b * Av + aa];
        az[(size_t)(b * Lv + l0 + rr) * Av + aa] = gelu_f(t);
    }
}

// adapter_up: writes adout = az@wu + bu (no read-modify-write of out)
#define TLU 8
__global__ __launch_bounds__(256) void adapter_up(
    const float* __restrict__ az, const float* __restrict__ wu,
    const float* __restrict__ bu, float* __restrict__ adout)
{
    int b = blockIdx.y, l0 = blockIdx.x * TLU;
    __shared__ float ash[TLU][Av];
    int tid = threadIdx.x;
    for (int i = tid; i < TLU * Av; i += 256)
        ash[i >> 6][i & 63] = az[(size_t)(b * Lv + l0 + (i >> 6)) * Av + (i & 63)];
    __syncthreads();
    const float* wb = wu + (size_t)b * Av * Dv;
    for (int dd = tid; dd < Dv; dd += 256) {
        float bb = bu[b * Dv + dd];
        float s[TLU];
        #pragma unroll
        for (int r = 0; r < TLU; r++) s[r] = bb;
        #pragma unroll 8
        for (int a = 0; a < Av; a++) {
            float w = wb[(size_t)a * Dv + dd];
            #pragma unroll
            for (int r = 0; r < TLU; r++) s[r] += ash[r][a] * w;
        }
        #pragma unroll
        for (int r = 0; r < TLU; r++)
            adout[(size_t)(b * Lv + l0 + r) * Dv + dd] = s[r];
    }
}

// ---------------- driver -------------------------------------------------------
extern "C" void kernel_launch(void* const* d_in, const int* in_sizes, int n_in,
                              void* d_out, int out_size)
{
    const float* inputs  = (const float*)d_in[0];
    const float* encoded = (const float*)d_in[1];
    const float* awd     = (const float*)d_in[2];
    const float* awu     = (const float*)d_in[3];
    const float* abd     = (const float*)d_in[4];
    const float* abu     = (const float*)d_in[5];
    const float* pk      = (const float*)d_in[6];
    const float* pvv     = (const float*)d_in[7];
    const float* ln1     = (const float*)d_in[8];
    const float* ln2     = (const float*)d_in[9];
    const float* ln3     = (const float*)d_in[10];
    const float* sa_wq   = (const float*)d_in[11];
    const float* sa_wk   = (const float*)d_in[12];
    const float* sa_wv   = (const float*)d_in[13];
    const float* sa_wo   = (const float*)d_in[14];
    const float* ca_wq   = (const float*)d_in[15];
    const float* ca_wk   = (const float*)d_in[16];
    const float* ca_wv   = (const float*)d_in[17];
    const float* ca_wo   = (const float*)d_in[18];
    const float* relpos  = (const float*)d_in[19];
    const float* wi0     = (const float*)d_in[20];
    const float* wi1     = (const float*)d_in[21];
    const float* wo_mlp  = (const float*)d_in[22];
    float* out = (float*)d_out;

    float *xn, *x, *y, *h0, *az, *adout, *bias;
    __nv_bfloat16 *xnh, *xnl, *ench, *encl, *atth, *attl, *h1h, *h1l, *wth, *wtl;
    __nv_bfloat16 *qkvh, *qkvl, *ckvh, *ckvl, *cqh, *cql, *pkh, *pkl, *pvh, *pvl;
    cudaGetSymbolAddress((void**)&xn,   g_xn);
    cudaGetSymbolAddress((void**)&xnh,  g_xnh);
    cudaGetSymbolAddress((void**)&xnl,  g_xnl);
    cudaGetSymbolAddress((void**)&ench, g_ench);
    cudaGetSymbolAddress((void**)&encl, g_encl);
    cudaGetSymbolAddress((void**)&atth, g_atth);
    cudaGetSymbolAddress((void**)&attl, g_attl);
    cudaGetSymbolAddress((void**)&qkvh, g_qkvh);
    cudaGetSymbolAddress((void**)&qkvl, g_qkvl);
    cudaGetSymbolAddress((void**)&ckvh, g_ckvh);
    cudaGetSymbolAddress((void**)&ckvl, g_ckvl);
    cudaGetSymbolAddress((void**)&cqh,  g_cqh);
    cudaGetSymbolAddress((void**)&cql,  g_cql);
    cudaGetSymbolAddress((void**)&pkh,  g_pkh);
    cudaGetSymbolAddress((void**)&pkl,  g_pkl);
    cudaGetSymbolAddress((void**)&pvh,  g_pvh);
    cudaGetSymbolAddress((void**)&pvl,  g_pvl);
    cudaGetSymbolAddress((void**)&bias, g_bias);
    cudaGetSymbolAddress((void**)&x,    g_x);
    cudaGetSymbolAddress((void**)&y,    g_y);
    cudaGetSymbolAddress((void**)&h0,   g_h0);
    cudaGetSymbolAddress((void**)&h1h,  g_h1h);
    cudaGetSymbolAddress((void**)&h1l,  g_h1l);
    cudaGetSymbolAddress((void**)&az,   g_az);
    cudaGetSymbolAddress((void**)&adout,g_adout);
    cudaGetSymbolAddress((void**)&wth,  g_wth);
    cudaGetSymbolAddress((void**)&wtl,  g_wtl);

    cudaFuncSetAttribute(fattn_kernel, cudaFuncAttributeMaxDynamicSharedMemorySize, FA_SMEM);
    cudaFuncSetAttribute(tgemm_kernel, cudaFuncAttributeMaxDynamicSharedMemorySize, TG_SMEM);

    const int M = Bv * Lv;
    dim3 g8(8, 32), g16(16, 32), g22(22, 32), g24(24, 32);
    dim3 ga(Lv / BQ, Bv * Hv);
    dim3 tsq(32, 32), tswi(88, 32), tswo(32, 88);

    // ---- fork a side stream into the capture ----
    cudaStream_t s1;
    cudaStreamCreateWithFlags(&s1, cudaStreamNonBlocking);
    cudaEvent_t evFork, evA, evSo, evPfx, evCq, evCkv, evCo, evW, evRn3, evAd;
    cudaEventCreateWithFlags(&evFork, cudaEventDisableTiming);
    cudaEventCreateWithFlags(&evA,    cudaEventDisableTiming);
    cudaEventCreateWithFlags(&evSo,   cudaEventDisableTiming);
    cudaEventCreateWithFlags(&evPfx,  cudaEventDisableTiming);
    cudaEventCreateWithFlags(&evCq,   cudaEventDisableTiming);
    cudaEventCreateWithFlags(&evCkv,  cudaEventDisableTiming);
    cudaEventCreateWithFlags(&evCo,   cudaEventDisableTiming);
    cudaEventCreateWithFlags(&evW,    cudaEventDisableTiming);
    cudaEventCreateWithFlags(&evRn3,  cudaEventDisableTiming);
    cudaEventCreateWithFlags(&evAd,   cudaEventDisableTiming);

    cudaEventRecord(evFork, 0);
    cudaStreamWaitEvent(s1, evFork, 0);

    // ---- side stream: input-only work (conversions + cross-KV GEMM) ----
    tsplit_kernel<<<tsq, 256, 0, s1>>>(sa_wq, wth + O_SAWQ, wtl + O_SAWQ, 1024, 1024, 0.125f);
    tsplit_kernel<<<tsq, 256, 0, s1>>>(sa_wk, wth + O_SAWK, wtl + O_SAWK, 1024, 1024, 1.f);
    tsplit_kernel<<<tsq, 256, 0, s1>>>(sa_wv, wth + O_SAWV, wtl + O_SAWV, 1024, 1024, 1.f);
    cudaEventRecord(evA, s1);
    split_kernel<<<(PFXN / 4 + 255) / 256, 256, 0, s1>>>(pk,  pkh, pkl, PFXN / 4);
    split_kernel<<<(PFXN / 4 + 255) / 256, 256, 0, s1>>>(pvv, pvh, pvl, PFXN / 4);
    bias_build<<<dim3(Hv, 4), 256, 0, s1>>>(relpos, bias);
    cudaEventRecord(evPfx, s1);
    tsplit_kernel<<<tsq, 256, 0, s1>>>(sa_wo, wth + O_SAWO, wtl + O_SAWO, 1024, 1024, 1.f);
    cudaEventRecord(evSo, s1);
    tsplit_kernel<<<tsq, 256, 0, s1>>>(ca_wq, wth + O_CAWQ, wtl + O_CAWQ, 1024, 1024, 0.125f);
    cudaEventRecord(evCq, s1);
    split_kernel<<<(M * Dv / 4 + 255) / 256, 256, 0, s1>>>(encoded, ench, encl, M * Dv / 4);
    tsplit_kernel<<<tsq, 256, 0, s1>>>(ca_wk, wth + O_CAWK, wtl + O_CAWK, 1024, 1024, 1.f);
    tsplit_kernel<<<tsq, 256, 0, s1>>>(ca_wv, wth + O_CAWV, wtl + O_CAWV, 1024, 1024, 1.f);
    tgemm_kernel<<<g16, 256, TG_SMEM, s1>>>(ench, encl, wth + O_CAWK, wtl + O_CAWK,
                                            nullptr, ckvh, ckvl, M, 2048, 1024,
                                            nullptr, nullptr, nullptr);
    cudaEventRecord(evCkv, s1);
    tsplit_kernel<<<tsq, 256, 0, s1>>>(ca_wo, wth + O_CAWO, wtl + O_CAWO, 1024, 1024, 1.f);
    cudaEventRecord(evCo, s1);
    tsplit_kernel<<<tswi, 256, 0, s1>>>(wi0, wth + O_WI0, wtl + O_WI0, 1024, 2816, 1.f);
    tsplit_kernel<<<tswi, 256, 0, s1>>>(wi1, wth + O_WI1, wtl + O_WI1, 1024, 2816, 1.f);
    tsplit_kernel<<<tswo, 256, 0, s1>>>(wo_mlp, wth + O_WO, wtl + O_WO, 2816, 1024, 1.f);
    cudaEventRecord(evW, s1);

    // ---- main stream: critical path (up to rmsnorm3) ----
    rmsnorm_kernel<<<M, 256>>>(inputs, ln1, nullptr, xnh, xnl);
    cudaStreamWaitEvent(0, evA, 0);
    tgemm_kernel<<<g24, 256, TG_SMEM>>>(xnh, xnl, wth + O_SAWQ, wtl + O_SAWQ,
                                        nullptr, qkvh, qkvl, M, 3072, 1024,
                                        nullptr, nullptr, nullptr);
    cudaStreamWaitEvent(0, evPfx, 0);
    fattn_kernel<<<ga, 256, FA_SMEM>>>(qkvh, qkvl, qkvh + 1024, qkvl + 1024,
                                       qkvh + 2048, qkvl + 2048, 3072, 3072,
                                       pkh, pkl, pvh, pvl, bias, atth, attl, 0, 1);
    cudaStreamWaitEvent(0, evSo, 0);
    tgemm_kernel<<<g8, 256, TG_SMEM>>>(atth, attl, wth + O_SAWO, wtl + O_SAWO,
                                       x, nullptr, nullptr, M, 1024, 1024,
                                       inputs, nullptr, nullptr);

    rmsnorm_kernel<<<M, 256>>>(x, ln2, nullptr, xnh, xnl);
    cudaStreamWaitEvent(0, evCq, 0);
    tgemm_kernel<<<g8, 256, TG_SMEM>>>(xnh, xnl, wth + O_CAWQ, wtl + O_CAWQ,
                                       nullptr, cqh, cql, M, 1024, 1024,
                                       nullptr, nullptr, nullptr);
    cudaStreamWaitEvent(0, evCkv, 0);
    fattn_kernel<<<ga, 256, FA_SMEM>>>(cqh, cql, ckvh, ckvl,
                                       ckvh + 1024, ckvl + 1024, 1024, 2048,
                                       pkh, pkl, pvh, pvl, bias, atth, attl, 1, 0);
    cudaStreamWaitEvent(0, evCo, 0);
    tgemm_kernel<<<g8, 256, TG_SMEM>>>(atth, attl, wth + O_CAWO, wtl + O_CAWO,
                                       y, nullptr, nullptr, M, 1024, 1024,
                                       x, nullptr, nullptr);

    rmsnorm_kernel<<<M, 256>>>(y, ln3, xn, xnh, xnl);
    cudaEventRecord(evRn3, 0);

    // ---- side stream: adapter chain (issued AFTER evRn3 recorded on host) ----
    cudaStreamWaitEvent(s1, evRn3, 0);
    adapter_down<<<dim3(Lv / TLD, Bv), 256, 0, s1>>>(xn, awd, abd, az);
    adapter_up<<<dim3(Lv / TLU, Bv), 256, 0, s1>>>(az, awu, abu, adout);
    cudaEventRecord(evAd, s1);

    // ---- main stream: MLP; wo-GEMM folds in y + adapter output ----
    cudaStreamWaitEvent(0, evW, 0);
    tgemm_kernel<<<g22, 256, TG_SMEM>>>(xnh, xnl, wth + O_WI0, wtl + O_WI0,
                                        h0, nullptr, nullptr, M, Fv, 1024,
                                        nullptr, nullptr, nullptr);
    tgemm_kernel<<<g22, 256, TG_SMEM>>>(xnh, xnl, wth + O_WI1, wtl + O_WI1,
                                        nullptr, h1h, h1l, M, Fv, 1024,
                                        nullptr, nullptr, h0);
    cudaStreamWaitEvent(0, evAd, 0);
    tgemm_kernel<<<g8, 256, TG_SMEM>>>(h1h, h1l, wth + O_WO, wtl + O_WO,
                                       out, nullptr, nullptr, M, 1024, Fv,
                                       y, adout, nullptr);
}